// round 1
// baseline (speedup 1.0000x reference)
#include <cuda_runtime.h>
#include <math.h>

#define B_   16
#define L_   8192
#define DM   128
#define DI   256
#define NH   8
#define HD   32
#define DST  64
#define CDIM 384
#define DPRJ 648
#define BL   (B_*L_)   /* 131072 */

// ---------------- scratch (static device globals; no allocation) ----------
__device__ float g_gate[BL*DM];                 // 67MB
__device__ float g_u[2][(size_t)BL*DM];         // 134MB
__device__ float g_zx[2][(size_t)BL*DPRJ];      // 680MB
__device__ float g_xBC[2][(size_t)BL*CDIM];     // 403MB
__device__ float g_dt[2][(size_t)BL*NH];        // 8MB
__device__ float g_y[2][(size_t)BL*DI];         // 268MB
__device__ float g_ydir[2][(size_t)BL*DM];      // 134MB
__device__ float g_Wf[2][DM*3*DM];              // fused front weights
__device__ float g_bf[2][DM];                   // fused front bias

__device__ __forceinline__ float sigm(float v) { return 1.f / (1.f + __expf(-v)); }

// ---------------- weight prep: E[dir][o, s*128+i] = lin@convw (+lin at s==1)
__global__ void prep_w_k(const float* __restrict__ flw, const float* __restrict__ fcw,
                         const float* __restrict__ blw, const float* __restrict__ bcw,
                         float* __restrict__ w0, float* __restrict__ w1)
{
    int idx = blockIdx.x * blockDim.x + threadIdx.x;
    if (idx >= 2 * 128 * 384) return;
    int dir = idx / (128 * 384);
    int rem = idx % (128 * 384);
    int o = rem / 384, kk = rem % 384;
    int s = kk >> 7, i = kk & 127;
    const float* lw = dir ? blw : flw;
    const float* cw = dir ? bcw : fcw;
    float acc = (s == 1) ? lw[o * 128 + i] : 0.f;
    #pragma unroll 4
    for (int j = 0; j < 128; j++)
        acc = fmaf(lw[o * 128 + j], cw[j * 384 + i * 3 + s], acc);
    (dir ? w1 : w0)[o * 384 + kk] = acc;
}

__global__ void prep_b_k(const float* __restrict__ flb, const float* __restrict__ fcb,
                         const float* __restrict__ blb, const float* __restrict__ bcb,
                         const float* __restrict__ flw, const float* __restrict__ blw,
                         float* __restrict__ b0, float* __restrict__ b1)
{
    int t = threadIdx.x;              // 256 threads
    int dir = t >> 7, o = t & 127;
    const float* lb = dir ? blb : flb;
    const float* cb = dir ? bcb : fcb;
    const float* lw = dir ? blw : flw;
    float acc = lb[o];
    for (int j = 0; j < 128; j++) acc = fmaf(lw[o * 128 + j], cb[j], acc);
    (dir ? b1 : b0)[o] = acc;
}

// ---------------- generic fp32 GEMM: C[M,N] = act(A @ W^T + bias) ----------
// A: (M,K) row-major (or virtual conv3 view of x when mode!=0), W: (N,K) row-major.
// mode 0: plain.  mode 1: A[m, s*128+i] = x[b, l+s-1, i] (0-pad).  mode 2: reversed x.
// BM=BN=128, BK=16, 256 threads, 8x8 per thread.
__global__ __launch_bounds__(256) void gemm_k(
    const float* __restrict__ A, const float* __restrict__ W,
    const float* __restrict__ bias, float* __restrict__ C,
    int N, int K, int mode, int act)
{
    __shared__ float As[16][128];
    __shared__ float Bs[16][128];
    int tid = threadIdx.x;
    int tx = tid & 15, ty = tid >> 4;
    int bm = blockIdx.x << 7;
    int bn = blockIdx.y << 7;
    int lrow = tid >> 2;            // 0..63
    int lc4  = (tid & 3) << 2;      // 0,4,8,12

    float acc[8][8] = {};

    for (int k0 = 0; k0 < K; k0 += 16) {
        #pragma unroll
        for (int r = 0; r < 2; r++) {
            int m = bm + lrow + (r << 6);
            int kk = k0 + lc4;
            float4 v = make_float4(0.f, 0.f, 0.f, 0.f);
            if (mode == 0) {
                v = *reinterpret_cast<const float4*>(A + (size_t)m * K + kk);
            } else {
                int b = m >> 13, l = m & (L_ - 1);
                int s = kk >> 7, i = kk & 127;
                int ls = l + s - 1;
                if (ls >= 0 && ls < L_) {
                    int lsrc = (mode == 2) ? (L_ - 1 - ls) : ls;
                    v = *reinterpret_cast<const float4*>(A + ((size_t)b * L_ + lsrc) * DM + i);
                }
            }
            int mm = lrow + (r << 6);
            As[lc4 + 0][mm] = v.x; As[lc4 + 1][mm] = v.y;
            As[lc4 + 2][mm] = v.z; As[lc4 + 3][mm] = v.w;
        }
        #pragma unroll
        for (int r = 0; r < 2; r++) {
            int n = bn + lrow + (r << 6);
            int kk = k0 + lc4;
            float4 v = make_float4(0.f, 0.f, 0.f, 0.f);
            if (n < N) v = *reinterpret_cast<const float4*>(W + (size_t)n * K + kk);
            int nn = lrow + (r << 6);
            Bs[lc4 + 0][nn] = v.x; Bs[lc4 + 1][nn] = v.y;
            Bs[lc4 + 2][nn] = v.z; Bs[lc4 + 3][nn] = v.w;
        }
        __syncthreads();
        #pragma unroll
        for (int k = 0; k < 16; k++) {
            float a[8], bb[8];
            *reinterpret_cast<float4*>(a)      = *reinterpret_cast<const float4*>(&As[k][ty << 2]);
            *reinterpret_cast<float4*>(a + 4)  = *reinterpret_cast<const float4*>(&As[k][(ty << 2) + 64]);
            *reinterpret_cast<float4*>(bb)     = *reinterpret_cast<const float4*>(&Bs[k][tx << 2]);
            *reinterpret_cast<float4*>(bb + 4) = *reinterpret_cast<const float4*>(&Bs[k][(tx << 2) + 64]);
            #pragma unroll
            for (int i = 0; i < 8; i++)
                #pragma unroll
                for (int j = 0; j < 8; j++)
                    acc[i][j] = fmaf(a[i], bb[j], acc[i][j]);
        }
        __syncthreads();
    }

    #pragma unroll
    for (int i = 0; i < 8; i++) {
        int m = bm + (ty << 2) + (i & 3) + ((i >> 2) << 6);
        #pragma unroll
        for (int j = 0; j < 8; j++) {
            int n = bn + (tx << 2) + (j & 3) + ((j >> 2) << 6);
            if (n < N) {
                float c = acc[i][j];
                if (bias) c += bias[n];
                if (act == 1) c *= sigm(c);   // silu
                C[(size_t)m * N + n] = c;
            }
        }
    }
}

// ---------------- depthwise causal conv4 + silu on xBC, and softplus dt ----
__global__ void dconv_k(const float* __restrict__ zx, const float* __restrict__ cw,
                        const float* __restrict__ cb, const float* __restrict__ dtb,
                        float* __restrict__ xBC, float* __restrict__ dto)
{
    int b = blockIdx.y;
    int l0 = blockIdx.x << 7;       // 128 l per block
    int c = threadIdx.x;            // 0..383
    const float* src = zx + (size_t)b * L_ * DPRJ + 256 + c;
    float k0 = cw[c * 4 + 0], k1 = cw[c * 4 + 1], k2 = cw[c * 4 + 2], k3 = cw[c * 4 + 3];
    float bias = cb[c];
    float xm3, xm2, xm1;
    if (l0 == 0) { xm3 = 0.f; xm2 = 0.f; xm1 = 0.f; }
    else {
        xm3 = src[(size_t)(l0 - 3) * DPRJ];
        xm2 = src[(size_t)(l0 - 2) * DPRJ];
        xm1 = src[(size_t)(l0 - 1) * DPRJ];
    }
    float dbias = (c < NH) ? dtb[c] : 0.f;
    for (int t = 0; t < 128; t++) {
        int l = l0 + t;
        size_t ro = (size_t)b * L_ + l;
        float xc = src[(size_t)l * DPRJ];
        float a = fmaf(k0, xm3, fmaf(k1, xm2, fmaf(k2, xm1, fmaf(k3, xc, bias))));
        xBC[ro * CDIM + c] = a * sigm(a);
        xm3 = xm2; xm2 = xm1; xm1 = xc;
        if (c < NH) {
            float v = zx[ro * DPRJ + 640 + c] + dbias;
            dto[ro * NH + c] = (v > 15.f) ? v : log1pf(__expf(v));
        }
    }
}

// ---------------- sequential SSM scan, one block per (dir,b,h) -------------
__global__ __launch_bounds__(256) void scan_k(
    const float* __restrict__ xBC0, const float* __restrict__ dt0,
    const float* __restrict__ xBC1, const float* __restrict__ dt1,
    const float* __restrict__ Al0, const float* __restrict__ D0,
    const float* __restrict__ Al1, const float* __restrict__ D1,
    float* __restrict__ y0, float* __restrict__ y1)
{
    int dir = blockIdx.x >> 7;
    int bh = blockIdx.x & 127;
    int b = bh >> 3, h = bh & 7;
    const float* xBC = dir ? xBC1 : xBC0;
    const float* dtb = dir ? dt1 : dt0;
    float A  = -__expf((dir ? Al1 : Al0)[h]);
    float Dv = (dir ? D1 : D0)[h];
    float* yo = dir ? y1 : y0;

    int p = threadIdx.x >> 3;       // 0..31 headdim index
    int ng = threadIdx.x & 7;       // 0..7  state-group
    float s[8];
    #pragma unroll
    for (int j = 0; j < 8; j++) s[j] = 0.f;

    const float* base = xBC + (size_t)b * L_ * CDIM;
    const float* dtp  = dtb + (size_t)b * L_ * NH + h;
    float* yrow = yo + (size_t)b * L_ * DI + h * HD + p;

    #pragma unroll 2
    for (int l = 0; l < L_; l++) {
        const float* row = base + (size_t)l * CDIM;
        float dt = __ldg(dtp + (size_t)l * NH);
        float dA = __expf(dt * A);
        float xv = __ldg(row + h * HD + p);
        float coef = dt * xv;
        float4 Bv0 = __ldg(reinterpret_cast<const float4*>(row + 256 + ng * 8));
        float4 Bv1 = __ldg(reinterpret_cast<const float4*>(row + 260 + ng * 8));
        float4 Cv0 = __ldg(reinterpret_cast<const float4*>(row + 320 + ng * 8));
        float4 Cv1 = __ldg(reinterpret_cast<const float4*>(row + 324 + ng * 8));
        float acc;
        s[0] = fmaf(s[0], dA, coef * Bv0.x); acc  = s[0] * Cv0.x;
        s[1] = fmaf(s[1], dA, coef * Bv0.y); acc = fmaf(s[1], Cv0.y, acc);
        s[2] = fmaf(s[2], dA, coef * Bv0.z); acc = fmaf(s[2], Cv0.z, acc);
        s[3] = fmaf(s[3], dA, coef * Bv0.w); acc = fmaf(s[3], Cv0.w, acc);
        s[4] = fmaf(s[4], dA, coef * Bv1.x); acc = fmaf(s[4], Cv1.x, acc);
        s[5] = fmaf(s[5], dA, coef * Bv1.y); acc = fmaf(s[5], Cv1.y, acc);
        s[6] = fmaf(s[6], dA, coef * Bv1.z); acc = fmaf(s[6], Cv1.z, acc);
        s[7] = fmaf(s[7], dA, coef * Bv1.w); acc = fmaf(s[7], Cv1.w, acc);
        acc += __shfl_xor_sync(0xffffffffu, acc, 1);
        acc += __shfl_xor_sync(0xffffffffu, acc, 2);
        acc += __shfl_xor_sync(0xffffffffu, acc, 4);
        if (ng == 0) yrow[(size_t)l * DI] = acc + Dv * xv;
    }
}

// ---------------- y <- rmsnorm(y * silu(z)) * norm_w  (in place, 256 wide) -
__global__ void rmsy_k(float* __restrict__ y, const float* __restrict__ zx,
                       const float* __restrict__ nw)
{
    int warp = threadIdx.x >> 5, lane = threadIdx.x & 31;
    size_t row = (size_t)blockIdx.x * 8 + warp;
    float* yr = y + row * DI;
    const float* zr = zx + row * DPRJ;
    float4 y0v = *reinterpret_cast<const float4*>(yr + lane * 8);
    float4 y1v = *reinterpret_cast<const float4*>(yr + lane * 8 + 4);
    float4 z0v = *reinterpret_cast<const float4*>(zr + lane * 8);
    float4 z1v = *reinterpret_cast<const float4*>(zr + lane * 8 + 4);
    float v[8];
    v[0] = y0v.x * (z0v.x * sigm(z0v.x));
    v[1] = y0v.y * (z0v.y * sigm(z0v.y));
    v[2] = y0v.z * (z0v.z * sigm(z0v.z));
    v[3] = y0v.w * (z0v.w * sigm(z0v.w));
    v[4] = y1v.x * (z1v.x * sigm(z1v.x));
    v[5] = y1v.y * (z1v.y * sigm(z1v.y));
    v[6] = y1v.z * (z1v.z * sigm(z1v.z));
    v[7] = y1v.w * (z1v.w * sigm(z1v.w));
    float ss = 0.f;
    #pragma unroll
    for (int j = 0; j < 8; j++) ss = fmaf(v[j], v[j], ss);
    #pragma unroll
    for (int o = 16; o; o >>= 1) ss += __shfl_xor_sync(0xffffffffu, ss, o);
    float r = rsqrtf(ss * (1.f / 256.f) + 1e-5f);
    float4 w0 = *reinterpret_cast<const float4*>(nw + lane * 8);
    float4 w1 = *reinterpret_cast<const float4*>(nw + lane * 8 + 4);
    float4 o0, o1;
    o0.x = v[0] * r * w0.x; o0.y = v[1] * r * w0.y; o0.z = v[2] * r * w0.z; o0.w = v[3] * r * w0.w;
    o1.x = v[4] * r * w1.x; o1.y = v[5] * r * w1.y; o1.z = v[6] * r * w1.z; o1.w = v[7] * r * w1.w;
    *reinterpret_cast<float4*>(yr + lane * 8)     = o0;
    *reinterpret_cast<float4*>(yr + lane * 8 + 4) = o1;
}

// ---------------- e = (yf + reverse(yb)) * gate ----------------------------
__global__ void combine_k(const float* __restrict__ yf, const float* __restrict__ yb,
                          const float* __restrict__ gate, float* __restrict__ e)
{
    size_t i = (size_t)blockIdx.x * blockDim.x + threadIdx.x;  // float4 index
    if (i >= (size_t)BL * 32) return;
    size_t row = i >> 5; int c4 = (int)(i & 31);
    size_t b = row >> 13; int l = (int)(row & (L_ - 1));
    size_t rowb = (b << 13) + (size_t)(L_ - 1 - l);
    float4 a  = reinterpret_cast<const float4*>(yf)[row * 32 + c4];
    float4 bb = reinterpret_cast<const float4*>(yb)[rowb * 32 + c4];
    float4 g  = reinterpret_cast<const float4*>(gate)[row * 32 + c4];
    float4 o;
    o.x = (a.x + bb.x) * g.x; o.y = (a.y + bb.y) * g.y;
    o.z = (a.z + bb.z) * g.z; o.w = (a.w + bb.w) * g.w;
    reinterpret_cast<float4*>(e)[row * 32 + c4] = o;
}

// ---------------- out = x + rmsnorm(o, norm_w)  (128 wide) -----------------
__global__ void final_k(const float* __restrict__ x, const float* __restrict__ o,
                        const float* __restrict__ nw, float* __restrict__ outp)
{
    int warp = threadIdx.x >> 5, lane = threadIdx.x & 31;
    size_t row = (size_t)blockIdx.x * 8 + warp;
    float4 v = *reinterpret_cast<const float4*>(o + row * DM + lane * 4);
    float ss = v.x * v.x + v.y * v.y + v.z * v.z + v.w * v.w;
    #pragma unroll
    for (int s = 16; s; s >>= 1) ss += __shfl_xor_sync(0xffffffffu, ss, s);
    float r = rsqrtf(ss * (1.f / 128.f) + 1e-5f);
    float4 xv = *reinterpret_cast<const float4*>(x + row * DM + lane * 4);
    float4 w  = *reinterpret_cast<const float4*>(nw + lane * 4);
    float4 res;
    res.x = xv.x + v.x * r * w.x; res.y = xv.y + v.y * r * w.y;
    res.z = xv.z + v.z * r * w.z; res.w = xv.w + v.w * r * w.w;
    *reinterpret_cast<float4*>(outp + row * DM + lane * 4) = res;
}

// ---------------- launch ----------------------------------------------------
extern "C" void kernel_launch(void* const* d_in, const int* in_sizes, int n_in,
                              void* d_out, int out_size)
{
    const float* x       = (const float*)d_in[0];
    const float* gate_w  = (const float*)d_in[1];
    const float* gate_b  = (const float*)d_in[2];
    const float* fconv_w = (const float*)d_in[3];
    const float* fconv_b = (const float*)d_in[4];
    const float* flin_w  = (const float*)d_in[5];
    const float* flin_b  = (const float*)d_in[6];
    const float* f_in_w  = (const float*)d_in[7];
    const float* f_cw    = (const float*)d_in[8];
    const float* f_cb    = (const float*)d_in[9];
    const float* f_dtb   = (const float*)d_in[10];
    const float* f_Alog  = (const float*)d_in[11];
    const float* f_D     = (const float*)d_in[12];
    const float* f_nw    = (const float*)d_in[13];
    const float* f_ow    = (const float*)d_in[14];
    const float* bconv_w = (const float*)d_in[15];
    const float* bconv_b = (const float*)d_in[16];
    const float* blin_w  = (const float*)d_in[17];
    const float* blin_b  = (const float*)d_in[18];
    const float* b_in_w  = (const float*)d_in[19];
    const float* b_cw    = (const float*)d_in[20];
    const float* b_cb    = (const float*)d_in[21];
    const float* b_dtb   = (const float*)d_in[22];
    const float* b_Alog  = (const float*)d_in[23];
    const float* b_D     = (const float*)d_in[24];
    const float* b_nw    = (const float*)d_in[25];
    const float* b_ow    = (const float*)d_in[26];
    const float* out_w   = (const float*)d_in[27];
    const float* out_b   = (const float*)d_in[28];
    const float* norm_w  = (const float*)d_in[29];

    float *p_gate, *p_u, *p_zx, *p_xBC, *p_dt, *p_y, *p_ydir, *p_Wf, *p_bf;
    cudaGetSymbolAddress((void**)&p_gate, g_gate);
    cudaGetSymbolAddress((void**)&p_u,    g_u);
    cudaGetSymbolAddress((void**)&p_zx,   g_zx);
    cudaGetSymbolAddress((void**)&p_xBC,  g_xBC);
    cudaGetSymbolAddress((void**)&p_dt,   g_dt);
    cudaGetSymbolAddress((void**)&p_y,    g_y);
    cudaGetSymbolAddress((void**)&p_ydir, g_ydir);
    cudaGetSymbolAddress((void**)&p_Wf,   g_Wf);
    cudaGetSymbolAddress((void**)&p_bf,   g_bf);

    float* u0   = p_u;                 float* u1   = p_u   + (size_t)BL * DM;
    float* zx0  = p_zx;                float* zx1  = p_zx  + (size_t)BL * DPRJ;
    float* xb0  = p_xBC;               float* xb1  = p_xBC + (size_t)BL * CDIM;
    float* dt0  = p_dt;                float* dt1  = p_dt  + (size_t)BL * NH;
    float* y0   = p_y;                 float* y1   = p_y   + (size_t)BL * DI;
    float* yd0  = p_ydir;              float* yd1  = p_ydir + (size_t)BL * DM;
    float* Wf0  = p_Wf;                float* Wf1  = p_Wf  + DM * 3 * DM;
    float* bf0  = p_bf;                float* bf1  = p_bf  + DM;

    const int MT = BL / 128;           // 1024 M-tiles

    // weight prep
    prep_w_k<<<384, 256>>>(flin_w, fconv_w, blin_w, bconv_w, Wf0, Wf1);
    prep_b_k<<<1, 256>>>(flin_b, fconv_b, blin_b, bconv_b, flin_w, blin_w, bf0, bf1);

    // gate = silu(x @ gate_w.T + gate_b)
    gemm_k<<<dim3(MT, 1), 256>>>(x, gate_w, gate_b, p_gate, 128, 128, 0, 1);

    // front: u = (x + conv3(x)) @ lin.T + bias  (fused, fwd and reversed)
    gemm_k<<<dim3(MT, 1), 256>>>(x, Wf0, bf0, u0, 128, 384, 1, 0);
    gemm_k<<<dim3(MT, 1), 256>>>(x, Wf1, bf1, u1, 128, 384, 2, 0);

    // in_proj: zxbcdt = u @ in_w.T
    gemm_k<<<dim3(MT, 6), 256>>>(u0, f_in_w, nullptr, zx0, 648, 128, 0, 0);
    gemm_k<<<dim3(MT, 6), 256>>>(u1, b_in_w, nullptr, zx1, 648, 128, 0, 0);

    // depthwise causal conv4 + silu, dt softplus
    dconv_k<<<dim3(L_ / 128, B_), 384>>>(zx0, f_cw, f_cb, f_dtb, xb0, dt0);
    dconv_k<<<dim3(L_ / 128, B_), 384>>>(zx1, b_cw, b_cb, b_dtb, xb1, dt1);

    // SSM scan (both directions in one grid)
    scan_k<<<256, 256>>>(xb0, dt0, xb1, dt1, f_Alog, f_D, b_Alog, b_D, y0, y1);

    // y <- rmsnorm(y * silu(z)) * norm_w
    rmsy_k<<<BL / 8, 256>>>(y0, zx0, f_nw);
    rmsy_k<<<BL / 8, 256>>>(y1, zx1, b_nw);

    // out proj (256 -> 128)
    gemm_k<<<dim3(MT, 1), 256>>>(y0, f_ow, nullptr, yd0, 128, 256, 0, 0);
    gemm_k<<<dim3(MT, 1), 256>>>(y1, b_ow, nullptr, yd1, 128, 256, 0, 0);

    // e = (yf + reverse(yb)) * gate   (into u0, no longer needed)
    combine_k<<<(BL * 32) / 256, 256>>>(yd0, yd1, p_gate, u0);

    // out = e @ out_w.T + out_b  (into u1)
    gemm_k<<<dim3(MT, 1), 256>>>(u0, out_w, out_b, u1, 128, 128, 0, 0);

    // result = x + rmsnorm(out, norm_w)
    final_k<<<BL / 8, 256>>>(x, u1, norm_w, (float*)d_out);
}

// round 2
// speedup vs baseline: 1.5887x; 1.5887x over previous
#include <cuda_runtime.h>
#include <math.h>

#define B_   16
#define L_   8192
#define DM   128
#define DI   256
#define NH   8
#define HD   32
#define DST  64
#define CDIM 384
#define DPRJ 648
#define BL   (B_*L_)   /* 131072 */
#define QC   256       /* scan chunk length */
#define NC   (L_/QC)   /* 32 chunks */

// ---------------- scratch (static device globals; no allocation) ----------
__device__ float g_gate[BL*DM];
__device__ float g_u[2][(size_t)BL*DM];
__device__ float g_zx[2][(size_t)BL*DPRJ];
__device__ float g_xBC[2][(size_t)BL*CDIM];
__device__ float g_dt[2][(size_t)BL*NH];
__device__ float g_y[2][(size_t)BL*DI];
__device__ float g_ydir[2][(size_t)BL*DM];
__device__ float g_Wf[2][DM*3*DM];
__device__ float g_bf[2][DM];
__device__ float g_S[(size_t)2*16*8*NC*2048];   // chunk states (local, then s0)
__device__ float g_cum[(size_t)2*16*8*L_];      // per-step cumulative decay

__device__ __forceinline__ float sigm(float v) { return 1.f / (1.f + __expf(-v)); }

__device__ __forceinline__ unsigned long long splat2(float v) {
    unsigned long long r;
    asm("mov.b64 %0, {%1, %1};" : "=l"(r) : "f"(v));
    return r;
}
__device__ __forceinline__ void fma2(unsigned long long& d, unsigned long long a, unsigned long long b) {
    asm("fma.rn.f32x2 %0, %1, %2, %0;" : "+l"(d) : "l"(a), "l"(b));
}
__device__ __forceinline__ void unpack2(unsigned long long v, float& lo, float& hi) {
    asm("mov.b64 {%0, %1}, %2;" : "=f"(lo), "=f"(hi) : "l"(v));
}

// ---------------- weight prep: E[dir][o, s*128+i] = lin@convw (+lin at s==1)
__global__ void prep_w_k(const float* __restrict__ flw, const float* __restrict__ fcw,
                         const float* __restrict__ blw, const float* __restrict__ bcw,
                         float* __restrict__ w0, float* __restrict__ w1)
{
    int idx = blockIdx.x * blockDim.x + threadIdx.x;
    if (idx >= 2 * 128 * 384) return;
    int dir = idx / (128 * 384);
    int rem = idx % (128 * 384);
    int o = rem / 384, kk = rem % 384;
    int s = kk >> 7, i = kk & 127;
    const float* lw = dir ? blw : flw;
    const float* cw = dir ? bcw : fcw;
    float acc = (s == 1) ? lw[o * 128 + i] : 0.f;
    #pragma unroll 4
    for (int j = 0; j < 128; j++)
        acc = fmaf(lw[o * 128 + j], cw[j * 384 + i * 3 + s], acc);
    (dir ? w1 : w0)[o * 384 + kk] = acc;
}

__global__ void prep_b_k(const float* __restrict__ flb, const float* __restrict__ fcb,
                         const float* __restrict__ blb, const float* __restrict__ bcb,
                         const float* __restrict__ flw, const float* __restrict__ blw,
                         float* __restrict__ b0, float* __restrict__ b1)
{
    int t = threadIdx.x;
    int dir = t >> 7, o = t & 127;
    const float* lb = dir ? blb : flb;
    const float* cb = dir ? bcb : fcb;
    const float* lw = dir ? blw : flw;
    float acc = lb[o];
    for (int j = 0; j < 128; j++) acc = fmaf(lw[o * 128 + j], cb[j], acc);
    (dir ? b1 : b0)[o] = acc;
}

// ---------------- generic fp32 GEMM (f32x2 inner), C = act(A @ W^T + bias) -
__global__ __launch_bounds__(256) void gemm_k(
    const float* __restrict__ A, const float* __restrict__ W,
    const float* __restrict__ bias, float* __restrict__ C,
    int N, int K, int mode, int act)
{
    __shared__ float As[16][128];
    __shared__ float Bs[16][128];
    int tid = threadIdx.x;
    int tx = tid & 15, ty = tid >> 4;
    int bm = blockIdx.x << 7;
    int bn = blockIdx.y << 7;
    int lrow = tid >> 2;
    int lc4  = (tid & 3) << 2;

    // acc2[ip][j]: packed pair over m-rows (2*ip, 2*ip+1 within the 8-row slab)
    unsigned long long acc2[4][8];
    #pragma unroll
    for (int i = 0; i < 4; i++)
        #pragma unroll
        for (int j = 0; j < 8; j++) acc2[i][j] = 0ull;

    for (int k0 = 0; k0 < K; k0 += 16) {
        #pragma unroll
        for (int r = 0; r < 2; r++) {
            int m = bm + lrow + (r << 6);
            int kk = k0 + lc4;
            float4 v = make_float4(0.f, 0.f, 0.f, 0.f);
            if (mode == 0) {
                v = *reinterpret_cast<const float4*>(A + (size_t)m * K + kk);
            } else {
                int b = m >> 13, l = m & (L_ - 1);
                int s = kk >> 7, i = kk & 127;
                int ls = l + s - 1;
                if (ls >= 0 && ls < L_) {
                    int lsrc = (mode == 2) ? (L_ - 1 - ls) : ls;
                    v = *reinterpret_cast<const float4*>(A + ((size_t)b * L_ + lsrc) * DM + i);
                }
            }
            int mm = lrow + (r << 6);
            As[lc4 + 0][mm] = v.x; As[lc4 + 1][mm] = v.y;
            As[lc4 + 2][mm] = v.z; As[lc4 + 3][mm] = v.w;
        }
        #pragma unroll
        for (int r = 0; r < 2; r++) {
            int n = bn + lrow + (r << 6);
            int kk = k0 + lc4;
            float4 v = make_float4(0.f, 0.f, 0.f, 0.f);
            if (n < N) v = *reinterpret_cast<const float4*>(W + (size_t)n * K + kk);
            int nn = lrow + (r << 6);
            Bs[lc4 + 0][nn] = v.x; Bs[lc4 + 1][nn] = v.y;
            Bs[lc4 + 2][nn] = v.z; Bs[lc4 + 3][nn] = v.w;
        }
        __syncthreads();
        #pragma unroll
        for (int k = 0; k < 16; k++) {
            // a pairs: ip -> rows (ty*4 + 2*(ip&1) [+64 if ip>=2]) .. +1
            unsigned long long a2[4];
            a2[0] = *reinterpret_cast<const unsigned long long*>(&As[k][(ty << 2)]);
            a2[1] = *reinterpret_cast<const unsigned long long*>(&As[k][(ty << 2) + 2]);
            a2[2] = *reinterpret_cast<const unsigned long long*>(&As[k][(ty << 2) + 64]);
            a2[3] = *reinterpret_cast<const unsigned long long*>(&As[k][(ty << 2) + 66]);
            float bb[8];
            *reinterpret_cast<float4*>(bb)     = *reinterpret_cast<const float4*>(&Bs[k][tx << 2]);
            *reinterpret_cast<float4*>(bb + 4) = *reinterpret_cast<const float4*>(&Bs[k][(tx << 2) + 64]);
            unsigned long long b2[8];
            #pragma unroll
            for (int j = 0; j < 8; j++) b2[j] = splat2(bb[j]);
            #pragma unroll
            for (int i = 0; i < 4; i++)
                #pragma unroll
                for (int j = 0; j < 8; j++)
                    fma2(acc2[i][j], a2[i], b2[j]);
        }
        __syncthreads();
    }

    #pragma unroll
    for (int ip = 0; ip < 4; ip++) {
        #pragma unroll
        for (int half = 0; half < 2; half++) {
            int q = 2 * (ip & 1) + half;
            int m = bm + (ty << 2) + q + ((ip >> 1) << 6);
            #pragma unroll
            for (int j = 0; j < 8; j++) {
                int n = bn + (tx << 2) + (j & 3) + ((j >> 2) << 6);
                if (n < N) {
                    float lo, hi;
                    unpack2(acc2[ip][j], lo, hi);
                    float c = half ? hi : lo;
                    if (bias) c += bias[n];
                    if (act == 1) c *= sigm(c);
                    C[(size_t)m * N + n] = c;
                }
            }
        }
    }
}

// ---------------- depthwise causal conv4 + silu on xBC, and softplus dt ----
__global__ void dconv_k(const float* __restrict__ zx, const float* __restrict__ cw,
                        const float* __restrict__ cb, const float* __restrict__ dtb,
                        float* __restrict__ xBC, float* __restrict__ dto)
{
    int b = blockIdx.y;
    int l0 = blockIdx.x << 7;
    int c = threadIdx.x;
    const float* src = zx + (size_t)b * L_ * DPRJ + 256 + c;
    float k0 = cw[c * 4 + 0], k1 = cw[c * 4 + 1], k2 = cw[c * 4 + 2], k3 = cw[c * 4 + 3];
    float bias = cb[c];
    float xm3, xm2, xm1;
    if (l0 == 0) { xm3 = 0.f; xm2 = 0.f; xm1 = 0.f; }
    else {
        xm3 = src[(size_t)(l0 - 3) * DPRJ];
        xm2 = src[(size_t)(l0 - 2) * DPRJ];
        xm1 = src[(size_t)(l0 - 1) * DPRJ];
    }
    float dbias = (c < NH) ? dtb[c] : 0.f;
    #pragma unroll 4
    for (int t = 0; t < 128; t++) {
        int l = l0 + t;
        size_t ro = (size_t)b * L_ + l;
        float xc = src[(size_t)l * DPRJ];
        float a = fmaf(k0, xm3, fmaf(k1, xm2, fmaf(k2, xm1, fmaf(k3, xc, bias))));
        xBC[ro * CDIM + c] = a * sigm(a);
        xm3 = xm2; xm2 = xm1; xm1 = xc;
        if (c < NH) {
            float v = zx[ro * DPRJ + 640 + c] + dbias;
            dto[ro * NH + c] = (v > 15.f) ? v : log1pf(__expf(v));
        }
    }
}

// ======================= chunked SSM scan =================================
// pass 1: per-(dir,b,h,chunk) local scan from zero state.
//   writes local y, per-step cumD, chunk-final local state S.
__global__ __launch_bounds__(256) void scan1_k(
    const float* __restrict__ xBC0, const float* __restrict__ dt0,
    const float* __restrict__ xBC1, const float* __restrict__ dt1,
    const float* __restrict__ Al0, const float* __restrict__ D0,
    const float* __restrict__ Al1, const float* __restrict__ D1,
    float* __restrict__ y0, float* __restrict__ y1,
    float* __restrict__ S, float* __restrict__ cum)
{
    int bid = blockIdx.x;
    int c  = bid & (NC - 1);
    int h  = (bid >> 5) & 7;
    int b  = (bid >> 8) & 15;
    int dir = bid >> 12;

    const float* xBC = dir ? xBC1 : xBC0;
    const float* dtb = dir ? dt1 : dt0;
    float A  = -__expf((dir ? Al1 : Al0)[h]);
    float Dv = (dir ? D1 : D0)[h];
    float* yo = dir ? y1 : y0;

    int p  = threadIdx.x >> 3;
    int ng = threadIdx.x & 7;
    float s[8];
    #pragma unroll
    for (int j = 0; j < 8; j++) s[j] = 0.f;

    const float* base = xBC + (size_t)b * L_ * CDIM;
    const float* dtp  = dtb + (size_t)b * L_ * NH + h;
    float* yrow = yo + (size_t)b * L_ * DI + h * HD + p;
    float* cumh = cum + (((size_t)dir * 16 + b) * 8 + h) * L_;

    float cd = 1.f;
    int l0 = c * QC;
    #pragma unroll 2
    for (int t = 0; t < QC; t++) {
        int l = l0 + t;
        const float* row = base + (size_t)l * CDIM;
        float dt = __ldg(dtp + (size_t)l * NH);
        float dA = __expf(dt * A);
        cd *= dA;
        float xv = __ldg(row + h * HD + p);
        float coef = dt * xv;
        float4 Bv0 = __ldg(reinterpret_cast<const float4*>(row + 256 + ng * 8));
        float4 Bv1 = __ldg(reinterpret_cast<const float4*>(row + 260 + ng * 8));
        float4 Cv0 = __ldg(reinterpret_cast<const float4*>(row + 320 + ng * 8));
        float4 Cv1 = __ldg(reinterpret_cast<const float4*>(row + 324 + ng * 8));
        float acc;
        s[0] = fmaf(s[0], dA, coef * Bv0.x); acc  = s[0] * Cv0.x;
        s[1] = fmaf(s[1], dA, coef * Bv0.y); acc = fmaf(s[1], Cv0.y, acc);
        s[2] = fmaf(s[2], dA, coef * Bv0.z); acc = fmaf(s[2], Cv0.z, acc);
        s[3] = fmaf(s[3], dA, coef * Bv0.w); acc = fmaf(s[3], Cv0.w, acc);
        s[4] = fmaf(s[4], dA, coef * Bv1.x); acc = fmaf(s[4], Cv1.x, acc);
        s[5] = fmaf(s[5], dA, coef * Bv1.y); acc = fmaf(s[5], Cv1.y, acc);
        s[6] = fmaf(s[6], dA, coef * Bv1.z); acc = fmaf(s[6], Cv1.z, acc);
        s[7] = fmaf(s[7], dA, coef * Bv1.w); acc = fmaf(s[7], Cv1.w, acc);
        acc += __shfl_xor_sync(0xffffffffu, acc, 1);
        acc += __shfl_xor_sync(0xffffffffu, acc, 2);
        acc += __shfl_xor_sync(0xffffffffu, acc, 4);
        if (ng == 0) yrow[(size_t)l * DI] = acc + Dv * xv;
        if (threadIdx.x == 0) cumh[l] = cd;
    }
    // chunk-final local state -> S
    float* Sp = S + ((((size_t)dir * 16 + b) * 8 + h) * NC + c) * 2048 + p * 64 + ng * 8;
    *reinterpret_cast<float4*>(Sp)     = make_float4(s[0], s[1], s[2], s[3]);
    *reinterpret_cast<float4*>(Sp + 4) = make_float4(s[4], s[5], s[6], s[7]);
}

// pass 2: per-(dir,b,h) inter-chunk recurrence; overwrite S[c] with s0 of chunk c.
__global__ __launch_bounds__(256) void scan2_k(float* __restrict__ S, const float* __restrict__ cum)
{
    int bid = blockIdx.x;
    int h = bid & 7, b = (bid >> 3) & 15, dir = bid >> 7;
    float* Sb = S + (((size_t)dir * 16 + b) * 8 + h) * NC * 2048 + threadIdx.x * 8;
    const float* cumh = cum + (((size_t)dir * 16 + b) * 8 + h) * L_;
    float s[8];
    #pragma unroll
    for (int j = 0; j < 8; j++) s[j] = 0.f;
    for (int c = 0; c < NC; c++) {
        float* Sp = Sb + (size_t)c * 2048;
        float4 a0 = *reinterpret_cast<const float4*>(Sp);
        float4 a1 = *reinterpret_cast<const float4*>(Sp + 4);
        float Tc = cumh[(c + 1) * QC - 1];
        *reinterpret_cast<float4*>(Sp)     = make_float4(s[0], s[1], s[2], s[3]);
        *reinterpret_cast<float4*>(Sp + 4) = make_float4(s[4], s[5], s[6], s[7]);
        s[0] = fmaf(s[0], Tc, a0.x); s[1] = fmaf(s[1], Tc, a0.y);
        s[2] = fmaf(s[2], Tc, a0.z); s[3] = fmaf(s[3], Tc, a0.w);
        s[4] = fmaf(s[4], Tc, a1.x); s[5] = fmaf(s[5], Tc, a1.y);
        s[6] = fmaf(s[6], Tc, a1.z); s[7] = fmaf(s[7], Tc, a1.w);
    }
}

// pass 3: add y_t += cumD_t * (C_t . s0_chunk) for chunks 1..NC-1.
__global__ __launch_bounds__(256) void scan3_k(
    const float* __restrict__ xBC0, const float* __restrict__ xBC1,
    float* __restrict__ y0, float* __restrict__ y1,
    const float* __restrict__ S, const float* __restrict__ cum)
{
    int idx = blockIdx.x;
    int c = idx % (NC - 1) + 1;
    int rest = idx / (NC - 1);
    int h = rest & 7, b = (rest >> 3) & 15, dir = rest >> 7;

    const float* xBC = dir ? xBC1 : xBC0;
    float* yo = dir ? y1 : y0;

    int p  = threadIdx.x >> 3;
    int ng = threadIdx.x & 7;

    const float* Sp = S + ((((size_t)dir * 16 + b) * 8 + h) * NC + c) * 2048 + p * 64 + ng * 8;
    float4 s0a = *reinterpret_cast<const float4*>(Sp);
    float4 s0b = *reinterpret_cast<const float4*>(Sp + 4);

    const float* base = xBC + (size_t)b * L_ * CDIM;
    const float* cumh = cum + (((size_t)dir * 16 + b) * 8 + h) * L_;
    float* yrow = yo + (size_t)b * L_ * DI + h * HD + p;

    int l0 = c * QC;
    #pragma unroll 2
    for (int t = 0; t < QC; t++) {
        int l = l0 + t;
        const float* row = base + (size_t)l * CDIM;
        float4 Cv0 = __ldg(reinterpret_cast<const float4*>(row + 320 + ng * 8));
        float4 Cv1 = __ldg(reinterpret_cast<const float4*>(row + 324 + ng * 8));
        float acc = s0a.x * Cv0.x;
        acc = fmaf(s0a.y, Cv0.y, acc);
        acc = fmaf(s0a.z, Cv0.z, acc);
        acc = fmaf(s0a.w, Cv0.w, acc);
        acc = fmaf(s0b.x, Cv1.x, acc);
        acc = fmaf(s0b.y, Cv1.y, acc);
        acc = fmaf(s0b.z, Cv1.z, acc);
        acc = fmaf(s0b.w, Cv1.w, acc);
        acc += __shfl_xor_sync(0xffffffffu, acc, 1);
        acc += __shfl_xor_sync(0xffffffffu, acc, 2);
        acc += __shfl_xor_sync(0xffffffffu, acc, 4);
        if (ng == 0) {
            float cd = cumh[l];
            yrow[(size_t)l * DI] += cd * acc;
        }
    }
}

// ---------------- y <- rmsnorm(y * silu(z)) * norm_w  (in place) ----------
__global__ void rmsy_k(float* __restrict__ y, const float* __restrict__ zx,
                       const float* __restrict__ nw)
{
    int warp = threadIdx.x >> 5, lane = threadIdx.x & 31;
    size_t row = (size_t)blockIdx.x * 8 + warp;
    float* yr = y + row * DI;
    const float* zr = zx + row * DPRJ;
    float4 y0v = *reinterpret_cast<const float4*>(yr + lane * 8);
    float4 y1v = *reinterpret_cast<const float4*>(yr + lane * 8 + 4);
    float4 z0v = *reinterpret_cast<const float4*>(zr + lane * 8);
    float4 z1v = *reinterpret_cast<const float4*>(zr + lane * 8 + 4);
    float v[8];
    v[0] = y0v.x * (z0v.x * sigm(z0v.x));
    v[1] = y0v.y * (z0v.y * sigm(z0v.y));
    v[2] = y0v.z * (z0v.z * sigm(z0v.z));
    v[3] = y0v.w * (z0v.w * sigm(z0v.w));
    v[4] = y1v.x * (z1v.x * sigm(z1v.x));
    v[5] = y1v.y * (z1v.y * sigm(z1v.y));
    v[6] = y1v.z * (z1v.z * sigm(z1v.z));
    v[7] = y1v.w * (z1v.w * sigm(z1v.w));
    float ss = 0.f;
    #pragma unroll
    for (int j = 0; j < 8; j++) ss = fmaf(v[j], v[j], ss);
    #pragma unroll
    for (int o = 16; o; o >>= 1) ss += __shfl_xor_sync(0xffffffffu, ss, o);
    float r = rsqrtf(ss * (1.f / 256.f) + 1e-5f);
    float4 w0 = *reinterpret_cast<const float4*>(nw + lane * 8);
    float4 w1 = *reinterpret_cast<const float4*>(nw + lane * 8 + 4);
    float4 o0, o1;
    o0.x = v[0] * r * w0.x; o0.y = v[1] * r * w0.y; o0.z = v[2] * r * w0.z; o0.w = v[3] * r * w0.w;
    o1.x = v[4] * r * w1.x; o1.y = v[5] * r * w1.y; o1.z = v[6] * r * w1.z; o1.w = v[7] * r * w1.w;
    *reinterpret_cast<float4*>(yr + lane * 8)     = o0;
    *reinterpret_cast<float4*>(yr + lane * 8 + 4) = o1;
}

// ---------------- e = (yf + reverse(yb)) * gate ----------------------------
__global__ void combine_k(const float* __restrict__ yf, const float* __restrict__ yb,
                          const float* __restrict__ gate, float* __restrict__ e)
{
    size_t i = (size_t)blockIdx.x * blockDim.x + threadIdx.x;
    if (i >= (size_t)BL * 32) return;
    size_t row = i >> 5; int c4 = (int)(i & 31);
    size_t b = row >> 13; int l = (int)(row & (L_ - 1));
    size_t rowb = (b << 13) + (size_t)(L_ - 1 - l);
    float4 a  = reinterpret_cast<const float4*>(yf)[row * 32 + c4];
    float4 bb = reinterpret_cast<const float4*>(yb)[rowb * 32 + c4];
    float4 g  = reinterpret_cast<const float4*>(gate)[row * 32 + c4];
    float4 o;
    o.x = (a.x + bb.x) * g.x; o.y = (a.y + bb.y) * g.y;
    o.z = (a.z + bb.z) * g.z; o.w = (a.w + bb.w) * g.w;
    reinterpret_cast<float4*>(e)[row * 32 + c4] = o;
}

// ---------------- out = x + rmsnorm(o, norm_w) ------------------------------
__global__ void final_k(const float* __restrict__ x, const float* __restrict__ o,
                        const float* __restrict__ nw, float* __restrict__ outp)
{
    int warp = threadIdx.x >> 5, lane = threadIdx.x & 31;
    size_t row = (size_t)blockIdx.x * 8 + warp;
    float4 v = *reinterpret_cast<const float4*>(o + row * DM + lane * 4);
    float ss = v.x * v.x + v.y * v.y + v.z * v.z + v.w * v.w;
    #pragma unroll
    for (int s = 16; s; s >>= 1) ss += __shfl_xor_sync(0xffffffffu, ss, s);
    float r = rsqrtf(ss * (1.f / 128.f) + 1e-5f);
    float4 xv = *reinterpret_cast<const float4*>(x + row * DM + lane * 4);
    float4 w  = *reinterpret_cast<const float4*>(nw + lane * 4);
    float4 res;
    res.x = xv.x + v.x * r * w.x; res.y = xv.y + v.y * r * w.y;
    res.z = xv.z + v.z * r * w.z; res.w = xv.w + v.w * r * w.w;
    *reinterpret_cast<float4*>(outp + row * DM + lane * 4) = res;
}

// ---------------- launch ----------------------------------------------------
extern "C" void kernel_launch(void* const* d_in, const int* in_sizes, int n_in,
                              void* d_out, int out_size)
{
    const float* x       = (const float*)d_in[0];
    const float* gate_w  = (const float*)d_in[1];
    const float* gate_b  = (const float*)d_in[2];
    const float* fconv_w = (const float*)d_in[3];
    const float* fconv_b = (const float*)d_in[4];
    const float* flin_w  = (const float*)d_in[5];
    const float* flin_b  = (const float*)d_in[6];
    const float* f_in_w  = (const float*)d_in[7];
    const float* f_cw    = (const float*)d_in[8];
    const float* f_cb    = (const float*)d_in[9];
    const float* f_dtb   = (const float*)d_in[10];
    const float* f_Alog  = (const float*)d_in[11];
    const float* f_D     = (const float*)d_in[12];
    const float* f_nw    = (const float*)d_in[13];
    const float* f_ow    = (const float*)d_in[14];
    const float* bconv_w = (const float*)d_in[15];
    const float* bconv_b = (const float*)d_in[16];
    const float* blin_w  = (const float*)d_in[17];
    const float* blin_b  = (const float*)d_in[18];
    const float* b_in_w  = (const float*)d_in[19];
    const float* b_cw    = (const float*)d_in[20];
    const float* b_cb    = (const float*)d_in[21];
    const float* b_dtb   = (const float*)d_in[22];
    const float* b_Alog  = (const float*)d_in[23];
    const float* b_D     = (const float*)d_in[24];
    const float* b_nw    = (const float*)d_in[25];
    const float* b_ow    = (const float*)d_in[26];
    const float* out_w   = (const float*)d_in[27];
    const float* out_b   = (const float*)d_in[28];
    const float* norm_w  = (const float*)d_in[29];

    float *p_gate, *p_u, *p_zx, *p_xBC, *p_dt, *p_y, *p_ydir, *p_Wf, *p_bf, *p_S, *p_cum;
    cudaGetSymbolAddress((void**)&p_gate, g_gate);
    cudaGetSymbolAddress((void**)&p_u,    g_u);
    cudaGetSymbolAddress((void**)&p_zx,   g_zx);
    cudaGetSymbolAddress((void**)&p_xBC,  g_xBC);
    cudaGetSymbolAddress((void**)&p_dt,   g_dt);
    cudaGetSymbolAddress((void**)&p_y,    g_y);
    cudaGetSymbolAddress((void**)&p_ydir, g_ydir);
    cudaGetSymbolAddress((void**)&p_Wf,   g_Wf);
    cudaGetSymbolAddress((void**)&p_bf,   g_bf);
    cudaGetSymbolAddress((void**)&p_S,    g_S);
    cudaGetSymbolAddress((void**)&p_cum,  g_cum);

    float* u0   = p_u;                 float* u1   = p_u   + (size_t)BL * DM;
    float* zx0  = p_zx;                float* zx1  = p_zx  + (size_t)BL * DPRJ;
    float* xb0  = p_xBC;               float* xb1  = p_xBC + (size_t)BL * CDIM;
    float* dt0  = p_dt;                float* dt1  = p_dt  + (size_t)BL * NH;
    float* y0   = p_y;                 float* y1   = p_y   + (size_t)BL * DI;
    float* yd0  = p_ydir;              float* yd1  = p_ydir + (size_t)BL * DM;
    float* Wf0  = p_Wf;                float* Wf1  = p_Wf  + DM * 3 * DM;
    float* bf0  = p_bf;                float* bf1  = p_bf  + DM;

    const int MT = BL / 128;

    prep_w_k<<<384, 256>>>(flin_w, fconv_w, blin_w, bconv_w, Wf0, Wf1);
    prep_b_k<<<1, 256>>>(flin_b, fconv_b, blin_b, bconv_b, flin_w, blin_w, bf0, bf1);

    gemm_k<<<dim3(MT, 1), 256>>>(x, gate_w, gate_b, p_gate, 128, 128, 0, 1);

    gemm_k<<<dim3(MT, 1), 256>>>(x, Wf0, bf0, u0, 128, 384, 1, 0);
    gemm_k<<<dim3(MT, 1), 256>>>(x, Wf1, bf1, u1, 128, 384, 2, 0);

    gemm_k<<<dim3(MT, 6), 256>>>(u0, f_in_w, nullptr, zx0, 648, 128, 0, 0);
    gemm_k<<<dim3(MT, 6), 256>>>(u1, b_in_w, nullptr, zx1, 648, 128, 0, 0);

    dconv_k<<<dim3(L_ / 128, B_), 384>>>(zx0, f_cw, f_cb, f_dtb, xb0, dt0);
    dconv_k<<<dim3(L_ / 128, B_), 384>>>(zx1, b_cw, b_cb, b_dtb, xb1, dt1);

    // chunked scan
    scan1_k<<<2 * 16 * 8 * NC, 256>>>(xb0, dt0, xb1, dt1, f_Alog, f_D, b_Alog, b_D,
                                      y0, y1, p_S, p_cum);
    scan2_k<<<256, 256>>>(p_S, p_cum);
    scan3_k<<<2 * 16 * 8 * (NC - 1), 256>>>(xb0, xb1, y0, y1, p_S, p_cum);

    rmsy_k<<<BL / 8, 256>>>(y0, zx0, f_nw);
    rmsy_k<<<BL / 8, 256>>>(y1, zx1, b_nw);

    gemm_k<<<dim3(MT, 1), 256>>>(y0, f_ow, nullptr, yd0, 128, 256, 0, 0);
    gemm_k<<<dim3(MT, 1), 256>>>(y1, b_ow, nullptr, yd1, 128, 256, 0, 0);

    combine_k<<<(BL * 32) / 256, 256>>>(yd0, yd1, p_gate, u0);

    gemm_k<<<dim3(MT, 1), 256>>>(u0, out_w, out_b, u1, 128, 128, 0, 0);

    final_k<<<BL / 8, 256>>>(x, u1, norm_w, (float*)d_out);
}

// round 3
// speedup vs baseline: 1.9120x; 1.2035x over previous
#include <cuda_runtime.h>
#include <math.h>

#define B_   16
#define L_   8192
#define DM   128
#define DI   256
#define NH   8
#define HD   32
#define DST  64
#define CDIM 384
#define DPRJ 648
#define BL   (B_*L_)   /* 131072 */
#define QC   256       /* scan chunk length */
#define NC   (L_/QC)   /* 32 chunks */

// ---------------- scratch (static device globals; no allocation) ----------
__device__ float g_gate[BL*DM];
__device__ float g_u[2][(size_t)BL*DM];
__device__ float g_zx[2][(size_t)BL*DPRJ];
__device__ float g_xBC[2][(size_t)BL*CDIM];
__device__ float g_dt[2][(size_t)BL*NH];
__device__ float g_y[2][(size_t)BL*DI];
__device__ float g_ydir[2][(size_t)BL*DM];
__device__ float g_Wf[2][DM*3*DM];
__device__ float g_bf[2][DM];
__device__ float g_S[(size_t)2*16*8*NC*2048];
__device__ float g_cum[(size_t)2*16*8*L_];

__device__ __forceinline__ float sigm(float v) { return 1.f / (1.f + __expf(-v)); }

__device__ __forceinline__ unsigned tf32r(float v) {
    unsigned r;
    asm("cvt.rna.tf32.f32 %0, %1;" : "=r"(r) : "f"(v));
    return r;
}

// ---------------- weight prep: E[dir][o, s*128+i] = lin@convw (+lin at s==1)
__global__ void prep_w_k(const float* __restrict__ flw, const float* __restrict__ fcw,
                         const float* __restrict__ blw, const float* __restrict__ bcw,
                         float* __restrict__ w0, float* __restrict__ w1)
{
    int idx = blockIdx.x * blockDim.x + threadIdx.x;
    if (idx >= 2 * 128 * 384) return;
    int dir = idx / (128 * 384);
    int rem = idx % (128 * 384);
    int o = rem / 384, kk = rem % 384;
    int s = kk >> 7, i = kk & 127;
    const float* lw = dir ? blw : flw;
    const float* cw = dir ? bcw : fcw;
    float acc = (s == 1) ? lw[o * 128 + i] : 0.f;
    #pragma unroll 4
    for (int j = 0; j < 128; j++)
        acc = fmaf(lw[o * 128 + j], cw[j * 384 + i * 3 + s], acc);
    (dir ? w1 : w0)[o * 384 + kk] = acc;
}

__global__ void prep_b_k(const float* __restrict__ flb, const float* __restrict__ fcb,
                         const float* __restrict__ blb, const float* __restrict__ bcb,
                         const float* __restrict__ flw, const float* __restrict__ blw,
                         float* __restrict__ b0, float* __restrict__ b1)
{
    int t = threadIdx.x;
    int dir = t >> 7, o = t & 127;
    const float* lb = dir ? blb : flb;
    const float* cb = dir ? bcb : fcb;
    const float* lw = dir ? blw : flw;
    float acc = lb[o];
    for (int j = 0; j < 128; j++) acc = fmaf(lw[o * 128 + j], cb[j], acc);
    (dir ? b1 : b0)[o] = acc;
}

// ---------------- tf32 tensor-core GEMM: C[M,N] = act(A @ W^T + bias) ------
// A: (M,K) fp32 row-major (or virtual conv3 view of x when mode!=0), W: (N,K).
// BM=128 BN=128 BK=16, 256 threads, warp tile 64x32 via m16n8k8 tf32 mma.
#define SPAD 136   /* smem row stride; 136 % 32 == 8 -> conflict-free frags */
__global__ __launch_bounds__(256, 2) void gemm_k(
    const float* __restrict__ A, const float* __restrict__ W,
    const float* __restrict__ bias, float* __restrict__ C,
    int N, int K, int mode, int act)
{
    __shared__ float As[16][SPAD];
    __shared__ float Bs[16][SPAD];
    int tid = threadIdx.x;
    int lane = tid & 31, warp = tid >> 5;
    int wm = warp & 1, wn = warp >> 1;            // warp tile: rows wm*64, cols wn*32
    int bm = blockIdx.x << 7, bn = blockIdx.y << 7;
    int lrow = tid >> 2;                           // 0..63
    int lc4  = (tid & 3) << 2;                     // 0,4,8,12
    int rl = lane >> 2, cl = lane & 3;

    float acc[4][4][4];
    #pragma unroll
    for (int a = 0; a < 4; a++)
        #pragma unroll
        for (int b = 0; b < 4; b++)
            #pragma unroll
            for (int e = 0; e < 4; e++) acc[a][b][e] = 0.f;

    float4 ar[2], br[2];

    auto fetch = [&](int k0) {
        #pragma unroll
        for (int rr = 0; rr < 2; rr++) {
            int m = bm + lrow + (rr << 6);
            int kk = k0 + lc4;
            float4 v = make_float4(0.f, 0.f, 0.f, 0.f);
            if (mode == 0) {
                v = *reinterpret_cast<const float4*>(A + (size_t)m * K + kk);
            } else {
                int b = m >> 13, l = m & (L_ - 1);
                int s = kk >> 7, i = kk & 127;
                int ls = l + s - 1;
                if (ls >= 0 && ls < L_) {
                    int lsrc = (mode == 2) ? (L_ - 1 - ls) : ls;
                    v = *reinterpret_cast<const float4*>(A + ((size_t)b * L_ + lsrc) * DM + i);
                }
            }
            ar[rr] = v;
        }
        #pragma unroll
        for (int rr = 0; rr < 2; rr++) {
            int n = bn + lrow + (rr << 6);
            int kk = k0 + lc4;
            float4 v = make_float4(0.f, 0.f, 0.f, 0.f);
            if (n < N) v = *reinterpret_cast<const float4*>(W + (size_t)n * K + kk);
            br[rr] = v;
        }
    };

    fetch(0);
    for (int k0 = 0; k0 < K; k0 += 16) {
        // store prefetched tile (converted to tf32)
        #pragma unroll
        for (int rr = 0; rr < 2; rr++) {
            int mm = lrow + (rr << 6);
            As[lc4 + 0][mm] = __uint_as_float(tf32r(ar[rr].x));
            As[lc4 + 1][mm] = __uint_as_float(tf32r(ar[rr].y));
            As[lc4 + 2][mm] = __uint_as_float(tf32r(ar[rr].z));
            As[lc4 + 3][mm] = __uint_as_float(tf32r(ar[rr].w));
            Bs[lc4 + 0][mm] = __uint_as_float(tf32r(br[rr].x));
            Bs[lc4 + 1][mm] = __uint_as_float(tf32r(br[rr].y));
            Bs[lc4 + 2][mm] = __uint_as_float(tf32r(br[rr].z));
            Bs[lc4 + 3][mm] = __uint_as_float(tf32r(br[rr].w));
        }
        __syncthreads();
        if (k0 + 16 < K) fetch(k0 + 16);
        // compute two k8 sub-steps
        #pragma unroll
        for (int ks = 0; ks < 2; ks++) {
            int kb = ks << 3;
            unsigned bf[4][2];
            #pragma unroll
            for (int tn = 0; tn < 4; tn++) {
                int n = wn * 32 + tn * 8 + rl;
                bf[tn][0] = __float_as_uint(Bs[kb + cl][n]);
                bf[tn][1] = __float_as_uint(Bs[kb + cl + 4][n]);
            }
            unsigned af[4][4];
            #pragma unroll
            for (int tm = 0; tm < 4; tm++) {
                int m = wm * 64 + tm * 16 + rl;
                af[tm][0] = __float_as_uint(As[kb + cl][m]);
                af[tm][1] = __float_as_uint(As[kb + cl][m + 8]);
                af[tm][2] = __float_as_uint(As[kb + cl + 4][m]);
                af[tm][3] = __float_as_uint(As[kb + cl + 4][m + 8]);
            }
            #pragma unroll
            for (int tm = 0; tm < 4; tm++)
                #pragma unroll
                for (int tn = 0; tn < 4; tn++)
                    asm volatile(
                        "mma.sync.aligned.m16n8k8.row.col.f32.tf32.tf32.f32 "
                        "{%0,%1,%2,%3}, {%4,%5,%6,%7}, {%8,%9}, {%0,%1,%2,%3};"
                        : "+f"(acc[tm][tn][0]), "+f"(acc[tm][tn][1]),
                          "+f"(acc[tm][tn][2]), "+f"(acc[tm][tn][3])
                        : "r"(af[tm][0]), "r"(af[tm][1]), "r"(af[tm][2]), "r"(af[tm][3]),
                          "r"(bf[tn][0]), "r"(bf[tn][1]));
        }
        __syncthreads();
    }

    // epilogue
    #pragma unroll
    for (int tm = 0; tm < 4; tm++) {
        int m0 = bm + wm * 64 + tm * 16 + rl;
        #pragma unroll
        for (int tn = 0; tn < 4; tn++) {
            int n0 = bn + wn * 32 + tn * 8 + cl * 2;
            #pragma unroll
            for (int e = 0; e < 4; e++) {
                int m = m0 + ((e >> 1) << 3);
                int n = n0 + (e & 1);
                if (n < N) {
                    float v = acc[tm][tn][e];
                    if (bias) v += bias[n];
                    if (act == 1) v *= sigm(v);
                    C[(size_t)m * N + n] = v;
                }
            }
        }
    }
}

// ---------------- depthwise causal conv4 + silu on xBC, and softplus dt ----
__global__ void dconv_k(const float* __restrict__ zx, const float* __restrict__ cw,
                        const float* __restrict__ cb, const float* __restrict__ dtb,
                        float* __restrict__ xBC, float* __restrict__ dto)
{
    int b = blockIdx.y;
    int l0 = blockIdx.x << 7;
    int c = threadIdx.x;
    const float* src = zx + (size_t)b * L_ * DPRJ + 256 + c;
    float k0 = cw[c * 4 + 0], k1 = cw[c * 4 + 1], k2 = cw[c * 4 + 2], k3 = cw[c * 4 + 3];
    float bias = cb[c];
    float xm3, xm2, xm1;
    if (l0 == 0) { xm3 = 0.f; xm2 = 0.f; xm1 = 0.f; }
    else {
        xm3 = src[(size_t)(l0 - 3) * DPRJ];
        xm2 = src[(size_t)(l0 - 2) * DPRJ];
        xm1 = src[(size_t)(l0 - 1) * DPRJ];
    }
    float dbias = (c < NH) ? dtb[c] : 0.f;
    #pragma unroll 4
    for (int t = 0; t < 128; t++) {
        int l = l0 + t;
        size_t ro = (size_t)b * L_ + l;
        float xc = src[(size_t)l * DPRJ];
        float a = fmaf(k0, xm3, fmaf(k1, xm2, fmaf(k2, xm1, fmaf(k3, xc, bias))));
        xBC[ro * CDIM + c] = a * sigm(a);
        xm3 = xm2; xm2 = xm1; xm1 = xc;
        if (c < NH) {
            float v = zx[ro * DPRJ + 640 + c] + dbias;
            dto[ro * NH + c] = (v > 15.f) ? v : log1pf(__expf(v));
        }
    }
}

// ======================= chunked SSM scan =================================
__global__ __launch_bounds__(256) void scan1_k(
    const float* __restrict__ xBC0, const float* __restrict__ dt0,
    const float* __restrict__ xBC1, const float* __restrict__ dt1,
    const float* __restrict__ Al0, const float* __restrict__ D0,
    const float* __restrict__ Al1, const float* __restrict__ D1,
    float* __restrict__ y0, float* __restrict__ y1,
    float* __restrict__ S, float* __restrict__ cum)
{
    int bid = blockIdx.x;
    int c  = bid & (NC - 1);
    int h  = (bid >> 5) & 7;
    int b  = (bid >> 8) & 15;
    int dir = bid >> 12;

    const float* xBC = dir ? xBC1 : xBC0;
    const float* dtb = dir ? dt1 : dt0;
    float A  = -__expf((dir ? Al1 : Al0)[h]);
    float Dv = (dir ? D1 : D0)[h];
    float* yo = dir ? y1 : y0;

    int p  = threadIdx.x >> 3;
    int ng = threadIdx.x & 7;
    float s[8];
    #pragma unroll
    for (int j = 0; j < 8; j++) s[j] = 0.f;

    const float* base = xBC + (size_t)b * L_ * CDIM;
    const float* dtp  = dtb + (size_t)b * L_ * NH + h;
    float* yrow = yo + (size_t)b * L_ * DI + h * HD + p;
    float* cumh = cum + (((size_t)dir * 16 + b) * 8 + h) * L_;

    float cd = 1.f;
    int l0 = c * QC;
    #pragma unroll 2
    for (int t = 0; t < QC; t++) {
        int l = l0 + t;
        const float* row = base + (size_t)l * CDIM;
        float dt = __ldg(dtp + (size_t)l * NH);
        float dA = __expf(dt * A);
        cd *= dA;
        float xv = __ldg(row + h * HD + p);
        float coef = dt * xv;
        float4 Bv0 = __ldg(reinterpret_cast<const float4*>(row + 256 + ng * 8));
        float4 Bv1 = __ldg(reinterpret_cast<const float4*>(row + 260 + ng * 8));
        float4 Cv0 = __ldg(reinterpret_cast<const float4*>(row + 320 + ng * 8));
        float4 Cv1 = __ldg(reinterpret_cast<const float4*>(row + 324 + ng * 8));
        float acc;
        s[0] = fmaf(s[0], dA, coef * Bv0.x); acc  = s[0] * Cv0.x;
        s[1] = fmaf(s[1], dA, coef * Bv0.y); acc = fmaf(s[1], Cv0.y, acc);
        s[2] = fmaf(s[2], dA, coef * Bv0.z); acc = fmaf(s[2], Cv0.z, acc);
        s[3] = fmaf(s[3], dA, coef * Bv0.w); acc = fmaf(s[3], Cv0.w, acc);
        s[4] = fmaf(s[4], dA, coef * Bv1.x); acc = fmaf(s[4], Cv1.x, acc);
        s[5] = fmaf(s[5], dA, coef * Bv1.y); acc = fmaf(s[5], Cv1.y, acc);
        s[6] = fmaf(s[6], dA, coef * Bv1.z); acc = fmaf(s[6], Cv1.z, acc);
        s[7] = fmaf(s[7], dA, coef * Bv1.w); acc = fmaf(s[7], Cv1.w, acc);
        acc += __shfl_xor_sync(0xffffffffu, acc, 1);
        acc += __shfl_xor_sync(0xffffffffu, acc, 2);
        acc += __shfl_xor_sync(0xffffffffu, acc, 4);
        if (ng == 0) yrow[(size_t)l * DI] = acc + Dv * xv;
        if (threadIdx.x == 0) cumh[l] = cd;
    }
    float* Sp = S + ((((size_t)dir * 16 + b) * 8 + h) * NC + c) * 2048 + p * 64 + ng * 8;
    *reinterpret_cast<float4*>(Sp)     = make_float4(s[0], s[1], s[2], s[3]);
    *reinterpret_cast<float4*>(Sp + 4) = make_float4(s[4], s[5], s[6], s[7]);
}

__global__ __launch_bounds__(256) void scan2_k(float* __restrict__ S, const float* __restrict__ cum)
{
    int bid = blockIdx.x;
    int h = bid & 7, b = (bid >> 3) & 15, dir = bid >> 7;
    float* Sb = S + (((size_t)dir * 16 + b) * 8 + h) * NC * 2048 + threadIdx.x * 8;
    const float* cumh = cum + (((size_t)dir * 16 + b) * 8 + h) * L_;
    float s[8];
    #pragma unroll
    for (int j = 0; j < 8; j++) s[j] = 0.f;
    for (int c = 0; c < NC; c++) {
        float* Sp = Sb + (size_t)c * 2048;
        float4 a0 = *reinterpret_cast<const float4*>(Sp);
        float4 a1 = *reinterpret_cast<const float4*>(Sp + 4);
        float Tc = cumh[(c + 1) * QC - 1];
        *reinterpret_cast<float4*>(Sp)     = make_float4(s[0], s[1], s[2], s[3]);
        *reinterpret_cast<float4*>(Sp + 4) = make_float4(s[4], s[5], s[6], s[7]);
        s[0] = fmaf(s[0], Tc, a0.x); s[1] = fmaf(s[1], Tc, a0.y);
        s[2] = fmaf(s[2], Tc, a0.z); s[3] = fmaf(s[3], Tc, a0.w);
        s[4] = fmaf(s[4], Tc, a1.x); s[5] = fmaf(s[5], Tc, a1.y);
        s[6] = fmaf(s[6], Tc, a1.z); s[7] = fmaf(s[7], Tc, a1.w);
    }
}

__global__ __launch_bounds__(256) void scan3_k(
    const float* __restrict__ xBC0, const float* __restrict__ xBC1,
    float* __restrict__ y0, float* __restrict__ y1,
    const float* __restrict__ S, const float* __restrict__ cum)
{
    int idx = blockIdx.x;
    int c = idx % (NC - 1) + 1;
    int rest = idx / (NC - 1);
    int h = rest & 7, b = (rest >> 3) & 15, dir = rest >> 7;

    const float* xBC = dir ? xBC1 : xBC0;
    float* yo = dir ? y1 : y0;

    int p  = threadIdx.x >> 3;
    int ng = threadIdx.x & 7;

    const float* Sp = S + ((((size_t)dir * 16 + b) * 8 + h) * NC + c) * 2048 + p * 64 + ng * 8;
    float4 s0a = *reinterpret_cast<const float4*>(Sp);
    float4 s0b = *reinterpret_cast<const float4*>(Sp + 4);

    const float* base = xBC + (size_t)b * L_ * CDIM;
    const float* cumh = cum + (((size_t)dir * 16 + b) * 8 + h) * L_;
    float* yrow = yo + (size_t)b * L_ * DI + h * HD + p;

    int l0 = c * QC;
    #pragma unroll 2
    for (int t = 0; t < QC; t++) {
        int l = l0 + t;
        const float* row = base + (size_t)l * CDIM;
        float4 Cv0 = __ldg(reinterpret_cast<const float4*>(row + 320 + ng * 8));
        float4 Cv1 = __ldg(reinterpret_cast<const float4*>(row + 324 + ng * 8));
        float acc = s0a.x * Cv0.x;
        acc = fmaf(s0a.y, Cv0.y, acc);
        acc = fmaf(s0a.z, Cv0.z, acc);
        acc = fmaf(s0a.w, Cv0.w, acc);
        acc = fmaf(s0b.x, Cv1.x, acc);
        acc = fmaf(s0b.y, Cv1.y, acc);
        acc = fmaf(s0b.z, Cv1.z, acc);
        acc = fmaf(s0b.w, Cv1.w, acc);
        acc += __shfl_xor_sync(0xffffffffu, acc, 1);
        acc += __shfl_xor_sync(0xffffffffu, acc, 2);
        acc += __shfl_xor_sync(0xffffffffu, acc, 4);
        if (ng == 0) {
            float cd = cumh[l];
            yrow[(size_t)l * DI] += cd * acc;
        }
    }
}

// ---------------- y <- rmsnorm(y * silu(z)) * norm_w  (in place) ----------
__global__ void rmsy_k(float* __restrict__ y, const float* __restrict__ zx,
                       const float* __restrict__ nw)
{
    int warp = threadIdx.x >> 5, lane = threadIdx.x & 31;
    size_t row = (size_t)blockIdx.x * 8 + warp;
    float* yr = y + row * DI;
    const float* zr = zx + row * DPRJ;
    float4 y0v = *reinterpret_cast<const float4*>(yr + lane * 8);
    float4 y1v = *reinterpret_cast<const float4*>(yr + lane * 8 + 4);
    float4 z0v = *reinterpret_cast<const float4*>(zr + lane * 8);
    float4 z1v = *reinterpret_cast<const float4*>(zr + lane * 8 + 4);
    float v[8];
    v[0] = y0v.x * (z0v.x * sigm(z0v.x));
    v[1] = y0v.y * (z0v.y * sigm(z0v.y));
    v[2] = y0v.z * (z0v.z * sigm(z0v.z));
    v[3] = y0v.w * (z0v.w * sigm(z0v.w));
    v[4] = y1v.x * (z1v.x * sigm(z1v.x));
    v[5] = y1v.y * (z1v.y * sigm(z1v.y));
    v[6] = y1v.z * (z1v.z * sigm(z1v.z));
    v[7] = y1v.w * (z1v.w * sigm(z1v.w));
    float ss = 0.f;
    #pragma unroll
    for (int j = 0; j < 8; j++) ss = fmaf(v[j], v[j], ss);
    #pragma unroll
    for (int o = 16; o; o >>= 1) ss += __shfl_xor_sync(0xffffffffu, ss, o);
    float r = rsqrtf(ss * (1.f / 256.f) + 1e-5f);
    float4 w0 = *reinterpret_cast<const float4*>(nw + lane * 8);
    float4 w1 = *reinterpret_cast<const float4*>(nw + lane * 8 + 4);
    float4 o0, o1;
    o0.x = v[0] * r * w0.x; o0.y = v[1] * r * w0.y; o0.z = v[2] * r * w0.z; o0.w = v[3] * r * w0.w;
    o1.x = v[4] * r * w1.x; o1.y = v[5] * r * w1.y; o1.z = v[6] * r * w1.z; o1.w = v[7] * r * w1.w;
    *reinterpret_cast<float4*>(yr + lane * 8)     = o0;
    *reinterpret_cast<float4*>(yr + lane * 8 + 4) = o1;
}

// ---------------- e = (yf + reverse(yb)) * gate ----------------------------
__global__ void combine_k(const float* __restrict__ yf, const float* __restrict__ yb,
                          const float* __restrict__ gate, float* __restrict__ e)
{
    size_t i = (size_t)blockIdx.x * blockDim.x + threadIdx.x;
    if (i >= (size_t)BL * 32) return;
    size_t row = i >> 5; int c4 = (int)(i & 31);
    size_t b = row >> 13; int l = (int)(row & (L_ - 1));
    size_t rowb = (b << 13) + (size_t)(L_ - 1 - l);
    float4 a  = reinterpret_cast<const float4*>(yf)[row * 32 + c4];
    float4 bb = reinterpret_cast<const float4*>(yb)[rowb * 32 + c4];
    float4 g  = reinterpret_cast<const float4*>(gate)[row * 32 + c4];
    float4 o;
    o.x = (a.x + bb.x) * g.x; o.y = (a.y + bb.y) * g.y;
    o.z = (a.z + bb.z) * g.z; o.w = (a.w + bb.w) * g.w;
    reinterpret_cast<float4*>(e)[row * 32 + c4] = o;
}

// ---------------- out = x + rmsnorm(o, norm_w) ------------------------------
__global__ void final_k(const float* __restrict__ x, const float* __restrict__ o,
                        const float* __restrict__ nw, float* __restrict__ outp)
{
    int warp = threadIdx.x >> 5, lane = threadIdx.x & 31;
    size_t row = (size_t)blockIdx.x * 8 + warp;
    float4 v = *reinterpret_cast<const float4*>(o + row * DM + lane * 4);
    float ss = v.x * v.x + v.y * v.y + v.z * v.z + v.w * v.w;
    #pragma unroll
    for (int s = 16; s; s >>= 1) ss += __shfl_xor_sync(0xffffffffu, ss, s);
    float r = rsqrtf(ss * (1.f / 128.f) + 1e-5f);
    float4 xv = *reinterpret_cast<const float4*>(x + row * DM + lane * 4);
    float4 w  = *reinterpret_cast<const float4*>(nw + lane * 4);
    float4 res;
    res.x = xv.x + v.x * r * w.x; res.y = xv.y + v.y * r * w.y;
    res.z = xv.z + v.z * r * w.z; res.w = xv.w + v.w * r * w.w;
    *reinterpret_cast<float4*>(outp + row * DM + lane * 4) = res;
}

// ---------------- launch ----------------------------------------------------
extern "C" void kernel_launch(void* const* d_in, const int* in_sizes, int n_in,
                              void* d_out, int out_size)
{
    const float* x       = (const float*)d_in[0];
    const float* gate_w  = (const float*)d_in[1];
    const float* gate_b  = (const float*)d_in[2];
    const float* fconv_w = (const float*)d_in[3];
    const float* fconv_b = (const float*)d_in[4];
    const float* flin_w  = (const float*)d_in[5];
    const float* flin_b  = (const float*)d_in[6];
    const float* f_in_w  = (const float*)d_in[7];
    const float* f_cw    = (const float*)d_in[8];
    const float* f_cb    = (const float*)d_in[9];
    const float* f_dtb   = (const float*)d_in[10];
    const float* f_Alog  = (const float*)d_in[11];
    const float* f_D     = (const float*)d_in[12];
    const float* f_nw    = (const float*)d_in[13];
    const float* f_ow    = (const float*)d_in[14];
    const float* bconv_w = (const float*)d_in[15];
    const float* bconv_b = (const float*)d_in[16];
    const float* blin_w  = (const float*)d_in[17];
    const float* blin_b  = (const float*)d_in[18];
    const float* b_in_w  = (const float*)d_in[19];
    const float* b_cw    = (const float*)d_in[20];
    const float* b_cb    = (const float*)d_in[21];
    const float* b_dtb   = (const float*)d_in[22];
    const float* b_Alog  = (const float*)d_in[23];
    const float* b_D     = (const float*)d_in[24];
    const float* b_nw    = (const float*)d_in[25];
    const float* b_ow    = (const float*)d_in[26];
    const float* out_w   = (const float*)d_in[27];
    const float* out_b   = (const float*)d_in[28];
    const float* norm_w  = (const float*)d_in[29];

    float *p_gate, *p_u, *p_zx, *p_xBC, *p_dt, *p_y, *p_ydir, *p_Wf, *p_bf, *p_S, *p_cum;
    cudaGetSymbolAddress((void**)&p_gate, g_gate);
    cudaGetSymbolAddress((void**)&p_u,    g_u);
    cudaGetSymbolAddress((void**)&p_zx,   g_zx);
    cudaGetSymbolAddress((void**)&p_xBC,  g_xBC);
    cudaGetSymbolAddress((void**)&p_dt,   g_dt);
    cudaGetSymbolAddress((void**)&p_y,    g_y);
    cudaGetSymbolAddress((void**)&p_ydir, g_ydir);
    cudaGetSymbolAddress((void**)&p_Wf,   g_Wf);
    cudaGetSymbolAddress((void**)&p_bf,   g_bf);
    cudaGetSymbolAddress((void**)&p_S,    g_S);
    cudaGetSymbolAddress((void**)&p_cum,  g_cum);

    float* u0   = p_u;                 float* u1   = p_u   + (size_t)BL * DM;
    float* zx0  = p_zx;                float* zx1  = p_zx  + (size_t)BL * DPRJ;
    float* xb0  = p_xBC;               float* xb1  = p_xBC + (size_t)BL * CDIM;
    float* dt0  = p_dt;                float* dt1  = p_dt  + (size_t)BL * NH;
    float* y0   = p_y;                 float* y1   = p_y   + (size_t)BL * DI;
    float* yd0  = p_ydir;              float* yd1  = p_ydir + (size_t)BL * DM;
    float* Wf0  = p_Wf;                float* Wf1  = p_Wf  + DM * 3 * DM;
    float* bf0  = p_bf;                float* bf1  = p_bf  + DM;

    const int MT = BL / 128;

    prep_w_k<<<384, 256>>>(flin_w, fconv_w, blin_w, bconv_w, Wf0, Wf1);
    prep_b_k<<<1, 256>>>(flin_b, fconv_b, blin_b, bconv_b, flin_w, blin_w, bf0, bf1);

    gemm_k<<<dim3(MT, 1), 256>>>(x, gate_w, gate_b, p_gate, 128, 128, 0, 1);

    gemm_k<<<dim3(MT, 1), 256>>>(x, Wf0, bf0, u0, 128, 384, 1, 0);
    gemm_k<<<dim3(MT, 1), 256>>>(x, Wf1, bf1, u1, 128, 384, 2, 0);

    gemm_k<<<dim3(MT, 6), 256>>>(u0, f_in_w, nullptr, zx0, 648, 128, 0, 0);
    gemm_k<<<dim3(MT, 6), 256>>>(u1, b_in_w, nullptr, zx1, 648, 128, 0, 0);

    dconv_k<<<dim3(L_ / 128, B_), 384>>>(zx0, f_cw, f_cb, f_dtb, xb0, dt0);
    dconv_k<<<dim3(L_ / 128, B_), 384>>>(zx1, b_cw, b_cb, b_dtb, xb1, dt1);

    scan1_k<<<2 * 16 * 8 * NC, 256>>>(xb0, dt0, xb1, dt1, f_Alog, f_D, b_Alog, b_D,
                                      y0, y1, p_S, p_cum);
    scan2_k<<<256, 256>>>(p_S, p_cum);
    scan3_k<<<2 * 16 * 8 * (NC - 1), 256>>>(xb0, xb1, y0, y1, p_S, p_cum);

    rmsy_k<<<BL / 8, 256>>>(y0, zx0, f_nw);
    rmsy_k<<<BL / 8, 256>>>(y1, zx1, b_nw);

    gemm_k<<<dim3(MT, 1), 256>>>(y0, f_ow, nullptr, yd0, 128, 256, 0, 0);
    gemm_k<<<dim3(MT, 1), 256>>>(y1, b_ow, nullptr, yd1, 128, 256, 0, 0);

    combine_k<<<(BL * 32) / 256, 256>>>(yd0, yd1, p_gate, u0);

    gemm_k<<<dim3(MT, 1), 256>>>(u0, out_w, out_b, u1, 128, 128, 0, 0);

    final_k<<<BL / 8, 256>>>(x, u1, norm_w, (float*)d_out);
}

// round 4
// speedup vs baseline: 3.4497x; 1.8042x over previous
#include <cuda_runtime.h>
#include <math.h>

#define B_   16
#define L_   8192
#define DM   128
#define DI   256
#define NH   8
#define HD   32
#define DST  64
#define CDIM 384
#define DPRJ 648
#define BL   (B_*L_)   /* 131072 */
#define QC   128       /* scan chunk length */
#define NC   (L_/QC)   /* 64 chunks */
#define TS   8         /* scan1 smem tile steps */
#define NT   (QC/TS)
#define TS3  16        /* scan3 smem tile steps */
#define NT3  (QC/TS3)

// ---------------- scratch (static device globals; no allocation) ----------
__device__ float g_gate[BL*DM];
__device__ float g_u[2][(size_t)BL*DM];
__device__ float g_zx[2][(size_t)BL*DPRJ];
__device__ float g_xBC[2][(size_t)BL*CDIM];
__device__ float g_dt[2][(size_t)BL*NH];
__device__ float g_y[2][(size_t)BL*DI];
__device__ float g_ydir[2][(size_t)BL*DM];
__device__ float g_Wf[2][DM*3*DM];
__device__ float g_bf[2][DM];
__device__ float g_S[(size_t)2*16*8*NC*2048];
__device__ float g_cum[(size_t)2*16*8*L_];

__device__ __forceinline__ float sigm(float v) { return 1.f / (1.f + __expf(-v)); }

__device__ __forceinline__ unsigned tf32r(float v) {
    unsigned r;
    asm("cvt.rna.tf32.f32 %0, %1;" : "=r"(r) : "f"(v));
    return r;
}

typedef unsigned long long u64;
__device__ __forceinline__ u64 splat2(float v) {
    u64 r; asm("mov.b64 %0, {%1, %1};" : "=l"(r) : "f"(v)); return r;
}
__device__ __forceinline__ u64 mul2(u64 a, u64 b) {
    u64 d; asm("mul.rn.f32x2 %0, %1, %2;" : "=l"(d) : "l"(a), "l"(b)); return d;
}
__device__ __forceinline__ void fma2acc(u64& d, u64 a, u64 b) {
    asm("fma.rn.f32x2 %0, %1, %2, %0;" : "+l"(d) : "l"(a), "l"(b));
}
__device__ __forceinline__ u64 add2(u64 a, u64 b) {
    u64 d; asm("add.rn.f32x2 %0, %1, %2;" : "=l"(d) : "l"(a), "l"(b)); return d;
}
__device__ __forceinline__ float sum2(u64 v) {
    float lo, hi; asm("mov.b64 {%0, %1}, %2;" : "=f"(lo), "=f"(hi) : "l"(v)); return lo + hi;
}

// ---------------- weight prep: E[dir][o, s*128+i] = lin@convw (+lin at s==1)
__global__ void prep_w_k(const float* __restrict__ flw, const float* __restrict__ fcw,
                         const float* __restrict__ blw, const float* __restrict__ bcw,
                         float* __restrict__ w0, float* __restrict__ w1)
{
    int idx = blockIdx.x * blockDim.x + threadIdx.x;
    if (idx >= 2 * 128 * 384) return;
    int dir = idx / (128 * 384);
    int rem = idx % (128 * 384);
    int o = rem / 384, kk = rem % 384;
    int s = kk >> 7, i = kk & 127;
    const float* lw = dir ? blw : flw;
    const float* cw = dir ? bcw : fcw;
    float acc = (s == 1) ? lw[o * 128 + i] : 0.f;
    #pragma unroll 4
    for (int j = 0; j < 128; j++)
        acc = fmaf(lw[o * 128 + j], cw[j * 384 + i * 3 + s], acc);
    (dir ? w1 : w0)[o * 384 + kk] = acc;
}

__global__ void prep_b_k(const float* __restrict__ flb, const float* __restrict__ fcb,
                         const float* __restrict__ blb, const float* __restrict__ bcb,
                         const float* __restrict__ flw, const float* __restrict__ blw,
                         float* __restrict__ b0, float* __restrict__ b1)
{
    int t = threadIdx.x;
    int dir = t >> 7, o = t & 127;
    const float* lb = dir ? blb : flb;
    const float* cb = dir ? bcb : fcb;
    const float* lw = dir ? blw : flw;
    float acc = lb[o];
    for (int j = 0; j < 128; j++) acc = fmaf(lw[o * 128 + j], cb[j], acc);
    (dir ? b1 : b0)[o] = acc;
}

// ---------------- tf32 tensor-core GEMM: C[M,N] = act(A @ W^T + bias) ------
#define SPAD 136
__global__ __launch_bounds__(256, 2) void gemm_k(
    const float* __restrict__ A, const float* __restrict__ W,
    const float* __restrict__ bias, float* __restrict__ C,
    int N, int K, int mode, int act)
{
    __shared__ float As[16][SPAD];
    __shared__ float Bs[16][SPAD];
    int tid = threadIdx.x;
    int lane = tid & 31, warp = tid >> 5;
    int wm = warp & 1, wn = warp >> 1;
    int bm = blockIdx.x << 7, bn = blockIdx.y << 7;
    int lrow = tid >> 2;
    int lc4  = (tid & 3) << 2;
    int rl = lane >> 2, cl = lane & 3;

    float acc[4][4][4];
    #pragma unroll
    for (int a = 0; a < 4; a++)
        #pragma unroll
        for (int b = 0; b < 4; b++)
            #pragma unroll
            for (int e = 0; e < 4; e++) acc[a][b][e] = 0.f;

    float4 ar[2], br[2];

    auto fetch = [&](int k0) {
        #pragma unroll
        for (int rr = 0; rr < 2; rr++) {
            int m = bm + lrow + (rr << 6);
            int kk = k0 + lc4;
            float4 v = make_float4(0.f, 0.f, 0.f, 0.f);
            if (mode == 0) {
                v = *reinterpret_cast<const float4*>(A + (size_t)m * K + kk);
            } else {
                int b = m >> 13, l = m & (L_ - 1);
                int s = kk >> 7, i = kk & 127;
                int ls = l + s - 1;
                if (ls >= 0 && ls < L_) {
                    int lsrc = (mode == 2) ? (L_ - 1 - ls) : ls;
                    v = *reinterpret_cast<const float4*>(A + ((size_t)b * L_ + lsrc) * DM + i);
                }
            }
            ar[rr] = v;
        }
        #pragma unroll
        for (int rr = 0; rr < 2; rr++) {
            int n = bn + lrow + (rr << 6);
            int kk = k0 + lc4;
            float4 v = make_float4(0.f, 0.f, 0.f, 0.f);
            if (n < N) v = *reinterpret_cast<const float4*>(W + (size_t)n * K + kk);
            br[rr] = v;
        }
    };

    fetch(0);
    for (int k0 = 0; k0 < K; k0 += 16) {
        #pragma unroll
        for (int rr = 0; rr < 2; rr++) {
            int mm = lrow + (rr << 6);
            As[lc4 + 0][mm] = __uint_as_float(tf32r(ar[rr].x));
            As[lc4 + 1][mm] = __uint_as_float(tf32r(ar[rr].y));
            As[lc4 + 2][mm] = __uint_as_float(tf32r(ar[rr].z));
            As[lc4 + 3][mm] = __uint_as_float(tf32r(ar[rr].w));
            Bs[lc4 + 0][mm] = __uint_as_float(tf32r(br[rr].x));
            Bs[lc4 + 1][mm] = __uint_as_float(tf32r(br[rr].y));
            Bs[lc4 + 2][mm] = __uint_as_float(tf32r(br[rr].z));
            Bs[lc4 + 3][mm] = __uint_as_float(tf32r(br[rr].w));
        }
        __syncthreads();
        if (k0 + 16 < K) fetch(k0 + 16);
        #pragma unroll
        for (int ks = 0; ks < 2; ks++) {
            int kb = ks << 3;
            unsigned bf[4][2];
            #pragma unroll
            for (int tn = 0; tn < 4; tn++) {
                int n = wn * 32 + tn * 8 + rl;
                bf[tn][0] = __float_as_uint(Bs[kb + cl][n]);
                bf[tn][1] = __float_as_uint(Bs[kb + cl + 4][n]);
            }
            unsigned af[4][4];
            #pragma unroll
            for (int tm = 0; tm < 4; tm++) {
                int m = wm * 64 + tm * 16 + rl;
                af[tm][0] = __float_as_uint(As[kb + cl][m]);
                af[tm][1] = __float_as_uint(As[kb + cl][m + 8]);
                af[tm][2] = __float_as_uint(As[kb + cl + 4][m]);
                af[tm][3] = __float_as_uint(As[kb + cl + 4][m + 8]);
            }
            #pragma unroll
            for (int tm = 0; tm < 4; tm++)
                #pragma unroll
                for (int tn = 0; tn < 4; tn++)
                    asm volatile(
                        "mma.sync.aligned.m16n8k8.row.col.f32.tf32.tf32.f32 "
                        "{%0,%1,%2,%3}, {%4,%5,%6,%7}, {%8,%9}, {%0,%1,%2,%3};"
                        : "+f"(acc[tm][tn][0]), "+f"(acc[tm][tn][1]),
                          "+f"(acc[tm][tn][2]), "+f"(acc[tm][tn][3])
                        : "r"(af[tm][0]), "r"(af[tm][1]), "r"(af[tm][2]), "r"(af[tm][3]),
                          "r"(bf[tn][0]), "r"(bf[tn][1]));
        }
        __syncthreads();
    }

    #pragma unroll
    for (int tm = 0; tm < 4; tm++) {
        int m0 = bm + wm * 64 + tm * 16 + rl;
        #pragma unroll
        for (int tn = 0; tn < 4; tn++) {
            int n0 = bn + wn * 32 + tn * 8 + cl * 2;
            #pragma unroll
            for (int e = 0; e < 4; e++) {
                int m = m0 + ((e >> 1) << 3);
                int n = n0 + (e & 1);
                if (n < N) {
                    float v = acc[tm][tn][e];
                    if (bias) v += bias[n];
                    if (act == 1) v *= sigm(v);
                    C[(size_t)m * N + n] = v;
                }
            }
        }
    }
}

// ---------------- depthwise causal conv4 + silu on xBC, and softplus dt ----
__global__ void dconv_k(const float* __restrict__ zx, const float* __restrict__ cw,
                        const float* __restrict__ cb, const float* __restrict__ dtb,
                        float* __restrict__ xBC, float* __restrict__ dto)
{
    int b = blockIdx.y;
    int l0 = blockIdx.x << 7;
    int c = threadIdx.x;
    const float* src = zx + (size_t)b * L_ * DPRJ + 256 + c;
    float k0 = cw[c * 4 + 0], k1 = cw[c * 4 + 1], k2 = cw[c * 4 + 2], k3 = cw[c * 4 + 3];
    float bias = cb[c];
    float xm3, xm2, xm1;
    if (l0 == 0) { xm3 = 0.f; xm2 = 0.f; xm1 = 0.f; }
    else {
        xm3 = src[(size_t)(l0 - 3) * DPRJ];
        xm2 = src[(size_t)(l0 - 2) * DPRJ];
        xm1 = src[(size_t)(l0 - 1) * DPRJ];
    }
    float dbias = (c < NH) ? dtb[c] : 0.f;
    #pragma unroll 4
    for (int t = 0; t < 128; t++) {
        int l = l0 + t;
        size_t ro = (size_t)b * L_ + l;
        float xc = src[(size_t)l * DPRJ];
        float a = fmaf(k0, xm3, fmaf(k1, xm2, fmaf(k2, xm1, fmaf(k3, xc, bias))));
        xBC[ro * CDIM + c] = a * sigm(a);
        xm3 = xm2; xm2 = xm1; xm1 = xc;
        if (c < NH) {
            float v = zx[ro * DPRJ + 640 + c] + dbias;
            dto[ro * NH + c] = (v > 15.f) ? v : log1pf(__expf(v));
        }
    }
}

// ======================= chunked SSM scan (one CTA per dir,b,chunk) =======
// scan1: local scan from zero state; warp = head, lane = headdim p;
// each lane holds the full 64-wide state as 32 packed f32x2 regs.
__global__ __launch_bounds__(256, 2) void scan1_k(
    const float* __restrict__ xBC0, const float* __restrict__ dt0,
    const float* __restrict__ xBC1, const float* __restrict__ dt1,
    const float* __restrict__ Al0, const float* __restrict__ D0,
    const float* __restrict__ Al1, const float* __restrict__ D1,
    float* __restrict__ y0, float* __restrict__ y1,
    float* __restrict__ S, float* __restrict__ cum)
{
    __shared__ float sx[2][TS][CDIM];
    __shared__ float sdt[2][TS * NH];

    int bid = blockIdx.x;
    int c   = bid & (NC - 1);
    int b   = (bid >> 6) & 15;
    int dir = bid >> 10;

    const float* xBC = dir ? xBC1 : xBC0;
    const float* dtb = dir ? dt1 : dt0;
    float* yo = dir ? y1 : y0;

    int h = threadIdx.x >> 5;
    int p = threadIdx.x & 31;

    float A  = -__expf((dir ? Al1 : Al0)[h]);
    float Dv = (dir ? D1 : D0)[h];

    const float* xbase  = xBC + ((size_t)b * L_ + (size_t)c * QC) * CDIM;
    const float* dtbase = dtb + ((size_t)b * L_ + (size_t)c * QC) * NH;
    float* ybase = yo + ((size_t)b * L_ + (size_t)c * QC) * DI + h * HD + p;
    float* cumh  = cum + (((size_t)dir * 16 + b) * 8 + h) * L_ + (size_t)c * QC;

    u64 s2[32];
    #pragma unroll
    for (int j = 0; j < 32; j++) s2[j] = 0ull;
    float cd = 1.f;

    auto load_tile = [&](int buf, int tile) {
        int l = tile * TS;
        const float4* g = reinterpret_cast<const float4*>(xbase + (size_t)(l + h) * CDIM);
        float4* sdst = reinterpret_cast<float4*>(&sx[buf][h][0]);
        #pragma unroll
        for (int k = 0; k < 3; k++) sdst[p + 32 * k] = g[p + 32 * k];
        if (threadIdx.x < (TS * NH) / 4) {
            reinterpret_cast<float4*>(&sdt[buf][0])[threadIdx.x] =
                reinterpret_cast<const float4*>(dtbase + (size_t)l * NH)[threadIdx.x];
        }
    };

    load_tile(0, 0);
    __syncthreads();

    for (int tile = 0; tile < NT; tile++) {
        int cur = tile & 1;
        if (tile + 1 < NT) load_tile(cur ^ 1, tile + 1);
        #pragma unroll
        for (int t = 0; t < TS; t++) {
            float dt = sdt[cur][t * NH + h];
            float dA = __expf(dt * A);
            cd *= dA;
            float xv = sx[cur][t][h * HD + p];
            float coef = dt * xv;
            u64 dA2 = splat2(dA), coef2 = splat2(coef);
            u64 yacc[4] = {0ull, 0ull, 0ull, 0ull};
            const float4* B4 = reinterpret_cast<const float4*>(&sx[cur][t][256]);
            const float4* C4 = reinterpret_cast<const float4*>(&sx[cur][t][320]);
            #pragma unroll
            for (int j = 0; j < 16; j++) {
                union { float4 f; u64 u[2]; } Bu, Cu;
                Bu.f = B4[j]; Cu.f = C4[j];
                u64 t0 = mul2(coef2, Bu.u[0]);
                fma2acc(t0, s2[2 * j], dA2);
                s2[2 * j] = t0;
                u64 t1 = mul2(coef2, Bu.u[1]);
                fma2acc(t1, s2[2 * j + 1], dA2);
                s2[2 * j + 1] = t1;
                fma2acc(yacc[j & 3], t0, Cu.u[0]);
                fma2acc(yacc[j & 3], t1, Cu.u[1]);
            }
            float yv = sum2(add2(add2(yacc[0], yacc[1]), add2(yacc[2], yacc[3])));
            ybase[(size_t)(tile * TS + t) * DI] = yv + Dv * xv;
            if (p == 0) cumh[tile * TS + t] = cd;
        }
        __syncthreads();
    }

    float* Sp = S + ((((size_t)dir * 16 + b) * 8 + h) * NC + c) * 2048 + p * 64;
    #pragma unroll
    for (int j = 0; j < 16; j++) {
        union { float4 f; u64 u[2]; } su;
        su.u[0] = s2[2 * j]; su.u[1] = s2[2 * j + 1];
        reinterpret_cast<float4*>(Sp)[j] = su.f;
    }
}

// scan2: per-(dir,b,h) inter-chunk recurrence; overwrite S[c] with s0 of chunk c.
__global__ __launch_bounds__(256) void scan2_k(float* __restrict__ S, const float* __restrict__ cum)
{
    int bid = blockIdx.x;
    int h = bid & 7, b = (bid >> 3) & 15, dir = bid >> 7;
    float* Sb = S + (((size_t)dir * 16 + b) * 8 + h) * NC * 2048 + threadIdx.x * 8;
    const float* cumh = cum + (((size_t)dir * 16 + b) * 8 + h) * L_;
    float s[8];
    #pragma unroll
    for (int j = 0; j < 8; j++) s[j] = 0.f;
    for (int c = 0; c < NC; c++) {
        float* Sp = Sb + (size_t)c * 2048;
        float4 a0 = *reinterpret_cast<const float4*>(Sp);
        float4 a1 = *reinterpret_cast<const float4*>(Sp + 4);
        float Tc = cumh[(c + 1) * QC - 1];
        *reinterpret_cast<float4*>(Sp)     = make_float4(s[0], s[1], s[2], s[3]);
        *reinterpret_cast<float4*>(Sp + 4) = make_float4(s[4], s[5], s[6], s[7]);
        s[0] = fmaf(s[0], Tc, a0.x); s[1] = fmaf(s[1], Tc, a0.y);
        s[2] = fmaf(s[2], Tc, a0.z); s[3] = fmaf(s[3], Tc, a0.w);
        s[4] = fmaf(s[4], Tc, a1.x); s[5] = fmaf(s[5], Tc, a1.y);
        s[6] = fmaf(s[6], Tc, a1.z); s[7] = fmaf(s[7], Tc, a1.w);
    }
}

// scan3: y_t += cum_t * (C_t . s0_chunk), one CTA per (dir,b,chunk>=1).
__global__ __launch_bounds__(256, 2) void scan3_k(
    const float* __restrict__ xBC0, const float* __restrict__ xBC1,
    float* __restrict__ y0, float* __restrict__ y1,
    const float* __restrict__ S, const float* __restrict__ cum)
{
    __shared__ float sc[2][TS3][64];

    int bid = blockIdx.x;
    int c    = bid % (NC - 1) + 1;
    int rest = bid / (NC - 1);
    int b = rest & 15, dir = rest >> 4;

    const float* xBC = dir ? xBC1 : xBC0;
    float* yo = dir ? y1 : y0;

    int h = threadIdx.x >> 5;
    int p = threadIdx.x & 31;

    // load s0 (64 floats per lane) as packed pairs
    const float* Sp = S + ((((size_t)dir * 16 + b) * 8 + h) * NC + c) * 2048 + p * 64;
    u64 s02[32];
    #pragma unroll
    for (int j = 0; j < 16; j++) {
        union { float4 f; u64 u[2]; } su;
        su.f = reinterpret_cast<const float4*>(Sp)[j];
        s02[2 * j] = su.u[0]; s02[2 * j + 1] = su.u[1];
    }

    const float* cbase = xBC + ((size_t)b * L_ + (size_t)c * QC) * CDIM + 320;
    const float* cumh  = cum + (((size_t)dir * 16 + b) * 8 + h) * L_ + (size_t)c * QC;
    float* ybase = yo + ((size_t)b * L_ + (size_t)c * QC) * DI + h * HD + p;

    auto load_tile = [&](int buf, int tile) {
        int l = tile * TS3;
        int row = threadIdx.x >> 4, f4 = threadIdx.x & 15;
        reinterpret_cast<float4*>(&sc[buf][row][0])[f4] =
            *reinterpret_cast<const float4*>(cbase + (size_t)(l + row) * CDIM + f4 * 4);
    };

    load_tile(0, 0);
    __syncthreads();

    for (int tile = 0; tile < NT3; tile++) {
        int cur = tile & 1;
        if (tile + 1 < NT3) load_tile(cur ^ 1, tile + 1);
        #pragma unroll
        for (int t = 0; t < TS3; t++) {
            u64 yacc[4] = {0ull, 0ull, 0ull, 0ull};
            const float4* C4 = reinterpret_cast<const float4*>(&sc[cur][t][0]);
            #pragma unroll
            for (int j = 0; j < 16; j++) {
                union { float4 f; u64 u[2]; } Cu;
                Cu.f = C4[j];
                fma2acc(yacc[j & 3], s02[2 * j], Cu.u[0]);
                fma2acc(yacc[j & 3], s02[2 * j + 1], Cu.u[1]);
            }
            float dot = sum2(add2(add2(yacc[0], yacc[1]), add2(yacc[2], yacc[3])));
            int l = tile * TS3 + t;
            float cd = __ldg(cumh + l);
            ybase[(size_t)l * DI] += cd * dot;
        }
        __syncthreads();
    }
}

// ---------------- y <- rmsnorm(y * silu(z)) * norm_w  (in place) ----------
__global__ void rmsy_k(float* __restrict__ y, const float* __restrict__ zx,
                       const float* __restrict__ nw)
{
    int warp = threadIdx.x >> 5, lane = threadIdx.x & 31;
    size_t row = (size_t)blockIdx.x * 8 + warp;
    float* yr = y + row * DI;
    const float* zr = zx + row * DPRJ;
    float4 y0v = *reinterpret_cast<const float4*>(yr + lane * 8);
    float4 y1v = *reinterpret_cast<const float4*>(yr + lane * 8 + 4);
    float4 z0v = *reinterpret_cast<const float4*>(zr + lane * 8);
    float4 z1v = *reinterpret_cast<const float4*>(zr + lane * 8 + 4);
    float v[8];
    v[0] = y0v.x * (z0v.x * sigm(z0v.x));
    v[1] = y0v.y * (z0v.y * sigm(z0v.y));
    v[2] = y0v.z * (z0v.z * sigm(z0v.z));
    v[3] = y0v.w * (z0v.w * sigm(z0v.w));
    v[4] = y1v.x * (z1v.x * sigm(z1v.x));
    v[5] = y1v.y * (z1v.y * sigm(z1v.y));
    v[6] = y1v.z * (z1v.z * sigm(z1v.z));
    v[7] = y1v.w * (z1v.w * sigm(z1v.w));
    float ss = 0.f;
    #pragma unroll
    for (int j = 0; j < 8; j++) ss = fmaf(v[j], v[j], ss);
    #pragma unroll
    for (int o = 16; o; o >>= 1) ss += __shfl_xor_sync(0xffffffffu, ss, o);
    float r = rsqrtf(ss * (1.f / 256.f) + 1e-5f);
    float4 w0 = *reinterpret_cast<const float4*>(nw + lane * 8);
    float4 w1 = *reinterpret_cast<const float4*>(nw + lane * 8 + 4);
    float4 o0, o1;
    o0.x = v[0] * r * w0.x; o0.y = v[1] * r * w0.y; o0.z = v[2] * r * w0.z; o0.w = v[3] * r * w0.w;
    o1.x = v[4] * r * w1.x; o1.y = v[5] * r * w1.y; o1.z = v[6] * r * w1.z; o1.w = v[7] * r * w1.w;
    *reinterpret_cast<float4*>(yr + lane * 8)     = o0;
    *reinterpret_cast<float4*>(yr + lane * 8 + 4) = o1;
}

// ---------------- e = (yf + reverse(yb)) * gate ----------------------------
__global__ void combine_k(const float* __restrict__ yf, const float* __restrict__ yb,
                          const float* __restrict__ gate, float* __restrict__ e)
{
    size_t i = (size_t)blockIdx.x * blockDim.x + threadIdx.x;
    if (i >= (size_t)BL * 32) return;
    size_t row = i >> 5; int c4 = (int)(i & 31);
    size_t b = row >> 13; int l = (int)(row & (L_ - 1));
    size_t rowb = (b << 13) + (size_t)(L_ - 1 - l);
    float4 a  = reinterpret_cast<const float4*>(yf)[row * 32 + c4];
    float4 bb = reinterpret_cast<const float4*>(yb)[rowb * 32 + c4];
    float4 g  = reinterpret_cast<const float4*>(gate)[row * 32 + c4];
    float4 o;
    o.x = (a.x + bb.x) * g.x; o.y = (a.y + bb.y) * g.y;
    o.z = (a.z + bb.z) * g.z; o.w = (a.w + bb.w) * g.w;
    reinterpret_cast<float4*>(e)[row * 32 + c4] = o;
}

// ---------------- out = x + rmsnorm(o, norm_w) ------------------------------
__global__ void final_k(const float* __restrict__ x, const float* __restrict__ o,
                        const float* __restrict__ nw, float* __restrict__ outp)
{
    int warp = threadIdx.x >> 5, lane = threadIdx.x & 31;
    size_t row = (size_t)blockIdx.x * 8 + warp;
    float4 v = *reinterpret_cast<const float4*>(o + row * DM + lane * 4);
    float ss = v.x * v.x + v.y * v.y + v.z * v.z + v.w * v.w;
    #pragma unroll
    for (int s = 16; s; s >>= 1) ss += __shfl_xor_sync(0xffffffffu, ss, s);
    float r = rsqrtf(ss * (1.f / 128.f) + 1e-5f);
    float4 xv = *reinterpret_cast<const float4*>(x + row * DM + lane * 4);
    float4 w  = *reinterpret_cast<const float4*>(nw + lane * 4);
    float4 res;
    res.x = xv.x + v.x * r * w.x; res.y = xv.y + v.y * r * w.y;
    res.z = xv.z + v.z * r * w.z; res.w = xv.w + v.w * r * w.w;
    *reinterpret_cast<float4*>(outp + row * DM + lane * 4) = res;
}

// ---------------- launch ----------------------------------------------------
extern "C" void kernel_launch(void* const* d_in, const int* in_sizes, int n_in,
                              void* d_out, int out_size)
{
    const float* x       = (const float*)d_in[0];
    const float* gate_w  = (const float*)d_in[1];
    const float* gate_b  = (const float*)d_in[2];
    const float* fconv_w = (const float*)d_in[3];
    const float* fconv_b = (const float*)d_in[4];
    const float* flin_w  = (const float*)d_in[5];
    const float* flin_b  = (const float*)d_in[6];
    const float* f_in_w  = (const float*)d_in[7];
    const float* f_cw    = (const float*)d_in[8];
    const float* f_cb    = (const float*)d_in[9];
    const float* f_dtb   = (const float*)d_in[10];
    const float* f_Alog  = (const float*)d_in[11];
    const float* f_D     = (const float*)d_in[12];
    const float* f_nw    = (const float*)d_in[13];
    const float* f_ow    = (const float*)d_in[14];
    const float* bconv_w = (const float*)d_in[15];
    const float* bconv_b = (const float*)d_in[16];
    const float* blin_w  = (const float*)d_in[17];
    const float* blin_b  = (const float*)d_in[18];
    const float* b_in_w  = (const float*)d_in[19];
    const float* b_cw    = (const float*)d_in[20];
    const float* b_cb    = (const float*)d_in[21];
    const float* b_dtb   = (const float*)d_in[22];
    const float* b_Alog  = (const float*)d_in[23];
    const float* b_D     = (const float*)d_in[24];
    const float* b_nw    = (const float*)d_in[25];
    const float* b_ow    = (const float*)d_in[26];
    const float* out_w   = (const float*)d_in[27];
    const float* out_b   = (const float*)d_in[28];
    const float* norm_w  = (const float*)d_in[29];

    float *p_gate, *p_u, *p_zx, *p_xBC, *p_dt, *p_y, *p_ydir, *p_Wf, *p_bf, *p_S, *p_cum;
    cudaGetSymbolAddress((void**)&p_gate, g_gate);
    cudaGetSymbolAddress((void**)&p_u,    g_u);
    cudaGetSymbolAddress((void**)&p_zx,   g_zx);
    cudaGetSymbolAddress((void**)&p_xBC,  g_xBC);
    cudaGetSymbolAddress((void**)&p_dt,   g_dt);
    cudaGetSymbolAddress((void**)&p_y,    g_y);
    cudaGetSymbolAddress((void**)&p_ydir, g_ydir);
    cudaGetSymbolAddress((void**)&p_Wf,   g_Wf);
    cudaGetSymbolAddress((void**)&p_bf,   g_bf);
    cudaGetSymbolAddress((void**)&p_S,    g_S);
    cudaGetSymbolAddress((void**)&p_cum,  g_cum);

    float* u0   = p_u;                 float* u1   = p_u   + (size_t)BL * DM;
    float* zx0  = p_zx;                float* zx1  = p_zx  + (size_t)BL * DPRJ;
    float* xb0  = p_xBC;               float* xb1  = p_xBC + (size_t)BL * CDIM;
    float* dt0  = p_dt;                float* dt1  = p_dt  + (size_t)BL * NH;
    float* y0   = p_y;                 float* y1   = p_y   + (size_t)BL * DI;
    float* yd0  = p_ydir;              float* yd1  = p_ydir + (size_t)BL * DM;
    float* Wf0  = p_Wf;                float* Wf1  = p_Wf  + DM * 3 * DM;
    float* bf0  = p_bf;                float* bf1  = p_bf  + DM;

    const int MT = BL / 128;

    prep_w_k<<<384, 256>>>(flin_w, fconv_w, blin_w, bconv_w, Wf0, Wf1);
    prep_b_k<<<1, 256>>>(flin_b, fconv_b, blin_b, bconv_b, flin_w, blin_w, bf0, bf1);

    gemm_k<<<dim3(MT, 1), 256>>>(x, gate_w, gate_b, p_gate, 128, 128, 0, 1);

    gemm_k<<<dim3(MT, 1), 256>>>(x, Wf0, bf0, u0, 128, 384, 1, 0);
    gemm_k<<<dim3(MT, 1), 256>>>(x, Wf1, bf1, u1, 128, 384, 2, 0);

    gemm_k<<<dim3(MT, 6), 256>>>(u0, f_in_w, nullptr, zx0, 648, 128, 0, 0);
    gemm_k<<<dim3(MT, 6), 256>>>(u1, b_in_w, nullptr, zx1, 648, 128, 0, 0);

    dconv_k<<<dim3(L_ / 128, B_), 384>>>(zx0, f_cw, f_cb, f_dtb, xb0, dt0);
    dconv_k<<<dim3(L_ / 128, B_), 384>>>(zx1, b_cw, b_cb, b_dtb, xb1, dt1);

    scan1_k<<<2 * 16 * NC, 256>>>(xb0, dt0, xb1, dt1, f_Alog, f_D, b_Alog, b_D,
                                  y0, y1, p_S, p_cum);
    scan2_k<<<256, 256>>>(p_S, p_cum);
    scan3_k<<<2 * 16 * (NC - 1), 256>>>(xb0, xb1, y0, y1, p_S, p_cum);

    rmsy_k<<<BL / 8, 256>>>(y0, zx0, f_nw);
    rmsy_k<<<BL / 8, 256>>>(y1, zx1, b_nw);

    gemm_k<<<dim3(MT, 1), 256>>>(y0, f_ow, nullptr, yd0, 128, 256, 0, 0);
    gemm_k<<<dim3(MT, 1), 256>>>(y1, b_ow, nullptr, yd1, 128, 256, 0, 0);

    combine_k<<<(BL * 32) / 256, 256>>>(yd0, yd1, p_gate, u0);

    gemm_k<<<dim3(MT, 1), 256>>>(u0, out_w, out_b, u1, 128, 128, 0, 0);

    final_k<<<BL / 8, 256>>>(x, u1, norm_w, (float*)d_out);
}

// round 5
// speedup vs baseline: 3.4693x; 1.0057x over previous
#include <cuda_runtime.h>
#include <math.h>

#define B_   16
#define L_   8192
#define DM   128
#define DI   256
#define NH   8
#define HD   32
#define DST  64
#define CDIM 384
#define DPRJ 648
#define BL   (B_*L_)   /* 131072 */
#define QC   128       /* scan chunk length */
#define NC   (L_/QC)   /* 64 chunks */
#define TS   8         /* scan1 smem tile steps */
#define NT   (QC/TS)
#define TS3  16        /* scan3 smem tile steps */
#define NT3  (QC/TS3)

// ---------------- scratch (static device globals; no allocation) ----------
__device__ float g_gate[BL*DM];
__device__ float g_u[2][(size_t)BL*DM];
__device__ float g_zx[2][(size_t)BL*DPRJ];
__device__ float g_xBC[2][(size_t)BL*CDIM];
__device__ float g_dt[2][(size_t)BL*NH];
__device__ float g_y[2][(size_t)BL*DI];
__device__ float g_ydir[2][(size_t)BL*DM];
__device__ float g_Wf[2][DM*3*DM];
__device__ float g_bf[2][DM];
__device__ float g_S[(size_t)2*16*8*NC*2048];
__device__ float g_cum[(size_t)2*16*8*L_];

__device__ __forceinline__ float sigm(float v) { return 1.f / (1.f + __expf(-v)); }

__device__ __forceinline__ float tf32f(float v) {
    unsigned r;
    asm("cvt.rna.tf32.f32 %0, %1;" : "=r"(r) : "f"(v));
    return __uint_as_float(r);
}

typedef unsigned long long u64;
__device__ __forceinline__ u64 splat2(float v) {
    u64 r; asm("mov.b64 %0, {%1, %1};" : "=l"(r) : "f"(v)); return r;
}
__device__ __forceinline__ u64 mul2(u64 a, u64 b) {
    u64 d; asm("mul.rn.f32x2 %0, %1, %2;" : "=l"(d) : "l"(a), "l"(b)); return d;
}
__device__ __forceinline__ void fma2acc(u64& d, u64 a, u64 b) {
    asm("fma.rn.f32x2 %0, %1, %2, %0;" : "+l"(d) : "l"(a), "l"(b));
}
__device__ __forceinline__ u64 add2(u64 a, u64 b) {
    u64 d; asm("add.rn.f32x2 %0, %1, %2;" : "=l"(d) : "l"(a), "l"(b)); return d;
}
__device__ __forceinline__ float sum2(u64 v) {
    float lo, hi; asm("mov.b64 {%0, %1}, %2;" : "=f"(lo), "=f"(hi) : "l"(v)); return lo + hi;
}

// ---------------- weight prep: E[dir][o, s*128+i] = lin@convw (+lin at s==1)
__global__ void prep_w_k(const float* __restrict__ flw, const float* __restrict__ fcw,
                         const float* __restrict__ blw, const float* __restrict__ bcw,
                         float* __restrict__ w0, float* __restrict__ w1)
{
    int idx = blockIdx.x * blockDim.x + threadIdx.x;
    if (idx >= 2 * 128 * 384) return;
    int dir = idx / (128 * 384);
    int rem = idx % (128 * 384);
    int o = rem / 384, kk = rem % 384;
    int s = kk >> 7, i = kk & 127;
    const float* lw = dir ? blw : flw;
    const float* cw = dir ? bcw : fcw;
    float acc = (s == 1) ? lw[o * 128 + i] : 0.f;
    #pragma unroll 4
    for (int j = 0; j < 128; j++)
        acc = fmaf(lw[o * 128 + j], cw[j * 384 + i * 3 + s], acc);
    (dir ? w1 : w0)[o * 384 + kk] = acc;
}

__global__ void prep_b_k(const float* __restrict__ flb, const float* __restrict__ fcb,
                         const float* __restrict__ blb, const float* __restrict__ bcb,
                         const float* __restrict__ flw, const float* __restrict__ blw,
                         float* __restrict__ b0, float* __restrict__ b1)
{
    int t = threadIdx.x;
    int dir = t >> 7, o = t & 127;
    const float* lb = dir ? blb : flb;
    const float* cb = dir ? bcb : fcb;
    const float* lw = dir ? blw : flw;
    float acc = lb[o];
    for (int j = 0; j < 128; j++) acc = fmaf(lw[o * 128 + j], cb[j], acc);
    (dir ? b1 : b0)[o] = acc;
}

// ---------------- tf32 tensor-core GEMM, double-buffered smem --------------
// C[M,N] = act(A @ W^T + bias); A: (M,K) fp32 (or conv3 view when mode!=0).
#define SPAD 136
__global__ __launch_bounds__(256, 2) void gemm_k(
    const float* __restrict__ A, const float* __restrict__ W,
    const float* __restrict__ bias, float* __restrict__ C,
    int N, int K, int mode, int act)
{
    __shared__ float As[2][16][SPAD];
    __shared__ float Bs[2][16][SPAD];
    int tid = threadIdx.x;
    int lane = tid & 31, warp = tid >> 5;
    int wm = warp & 1, wn = warp >> 1;
    int bm = blockIdx.x << 7, bn = blockIdx.y << 7;
    int lrow = tid >> 2;
    int lc4  = (tid & 3) << 2;
    int rl = lane >> 2, cl = lane & 3;

    float acc[4][4][4];
    #pragma unroll
    for (int a = 0; a < 4; a++)
        #pragma unroll
        for (int b = 0; b < 4; b++)
            #pragma unroll
            for (int e = 0; e < 4; e++) acc[a][b][e] = 0.f;

    float4 ar[2], br[2];

    // hoisted row pointers (mode 0 A; W always)
    const float* arow[2];
    const float* wrow[2];
    bool wok[2];
    #pragma unroll
    for (int rr = 0; rr < 2; rr++) {
        arow[rr] = A + (size_t)(bm + lrow + (rr << 6)) * K + lc4;
        int n = bn + lrow + (rr << 6);
        wok[rr] = (n < N);
        wrow[rr] = W + (size_t)(wok[rr] ? n : 0) * K + lc4;
    }

    auto fetch = [&](int k0) {
        #pragma unroll
        for (int rr = 0; rr < 2; rr++) {
            if (mode == 0) {
                ar[rr] = *reinterpret_cast<const float4*>(arow[rr] + k0);
            } else {
                int m = bm + lrow + (rr << 6);
                int kk = k0 + lc4;
                int b = m >> 13, l = m & (L_ - 1);
                int s = kk >> 7, i = kk & 127;
                int ls = l + s - 1;
                float4 v = make_float4(0.f, 0.f, 0.f, 0.f);
                if (ls >= 0 && ls < L_) {
                    int lsrc = (mode == 2) ? (L_ - 1 - ls) : ls;
                    v = *reinterpret_cast<const float4*>(A + ((size_t)b * L_ + lsrc) * DM + i);
                }
                ar[rr] = v;
            }
            br[rr] = wok[rr] ? *reinterpret_cast<const float4*>(wrow[rr] + k0)
                             : make_float4(0.f, 0.f, 0.f, 0.f);
        }
    };

    auto stage = [&](int buf) {
        #pragma unroll
        for (int rr = 0; rr < 2; rr++) {
            int mm = lrow + (rr << 6);
            As[buf][lc4 + 0][mm] = tf32f(ar[rr].x);
            As[buf][lc4 + 1][mm] = tf32f(ar[rr].y);
            As[buf][lc4 + 2][mm] = tf32f(ar[rr].z);
            As[buf][lc4 + 3][mm] = tf32f(ar[rr].w);
            Bs[buf][lc4 + 0][mm] = tf32f(br[rr].x);
            Bs[buf][lc4 + 1][mm] = tf32f(br[rr].y);
            Bs[buf][lc4 + 2][mm] = tf32f(br[rr].z);
            Bs[buf][lc4 + 3][mm] = tf32f(br[rr].w);
        }
    };

    fetch(0);
    stage(0);

    int cur = 0;
    for (int k0 = 0; k0 < K; k0 += 16, cur ^= 1) {
        __syncthreads();
        bool more = (k0 + 16 < K);
        if (more) fetch(k0 + 16);

        #pragma unroll
        for (int ks = 0; ks < 2; ks++) {
            int kb = ks << 3;
            unsigned bf[4][2];
            #pragma unroll
            for (int tn = 0; tn < 4; tn++) {
                int n = wn * 32 + tn * 8 + rl;
                bf[tn][0] = __float_as_uint(Bs[cur][kb + cl][n]);
                bf[tn][1] = __float_as_uint(Bs[cur][kb + cl + 4][n]);
            }
            unsigned af[4][4];
            #pragma unroll
            for (int tm = 0; tm < 4; tm++) {
                int m = wm * 64 + tm * 16 + rl;
                af[tm][0] = __float_as_uint(As[cur][kb + cl][m]);
                af[tm][1] = __float_as_uint(As[cur][kb + cl][m + 8]);
                af[tm][2] = __float_as_uint(As[cur][kb + cl + 4][m]);
                af[tm][3] = __float_as_uint(As[cur][kb + cl + 4][m + 8]);
            }
            #pragma unroll
            for (int tm = 0; tm < 4; tm++)
                #pragma unroll
                for (int tn = 0; tn < 4; tn++)
                    asm volatile(
                        "mma.sync.aligned.m16n8k8.row.col.f32.tf32.tf32.f32 "
                        "{%0,%1,%2,%3}, {%4,%5,%6,%7}, {%8,%9}, {%0,%1,%2,%3};"
                        : "+f"(acc[tm][tn][0]), "+f"(acc[tm][tn][1]),
                          "+f"(acc[tm][tn][2]), "+f"(acc[tm][tn][3])
                        : "r"(af[tm][0]), "r"(af[tm][1]), "r"(af[tm][2]), "r"(af[tm][3]),
                          "r"(bf[tn][0]), "r"(bf[tn][1]));
        }

        if (more) stage(cur ^ 1);
    }

    #pragma unroll
    for (int tm = 0; tm < 4; tm++) {
        int m0 = bm + wm * 64 + tm * 16 + rl;
        #pragma unroll
        for (int tn = 0; tn < 4; tn++) {
            int n0 = bn + wn * 32 + tn * 8 + cl * 2;
            #pragma unroll
            for (int e = 0; e < 4; e++) {
                int m = m0 + ((e >> 1) << 3);
                int n = n0 + (e & 1);
                if (n < N) {
                    float v = acc[tm][tn][e];
                    if (bias) v += bias[n];
                    if (act == 1) v *= sigm(v);
                    C[(size_t)m * N + n] = v;
                }
            }
        }
    }
}

// ---------------- depthwise causal conv4 + silu on xBC, and softplus dt ----
__global__ void dconv_k(const float* __restrict__ zx, const float* __restrict__ cw,
                        const float* __restrict__ cb, const float* __restrict__ dtb,
                        float* __restrict__ xBC, float* __restrict__ dto)
{
    int b = blockIdx.y;
    int l0 = blockIdx.x << 7;
    int c = threadIdx.x;
    const float* src = zx + (size_t)b * L_ * DPRJ + 256 + c;
    float k0 = cw[c * 4 + 0], k1 = cw[c * 4 + 1], k2 = cw[c * 4 + 2], k3 = cw[c * 4 + 3];
    float bias = cb[c];
    float xm3, xm2, xm1;
    if (l0 == 0) { xm3 = 0.f; xm2 = 0.f; xm1 = 0.f; }
    else {
        xm3 = src[(size_t)(l0 - 3) * DPRJ];
        xm2 = src[(size_t)(l0 - 2) * DPRJ];
        xm1 = src[(size_t)(l0 - 1) * DPRJ];
    }
    float dbias = (c < NH) ? dtb[c] : 0.f;
    #pragma unroll 4
    for (int t = 0; t < 128; t++) {
        int l = l0 + t;
        size_t ro = (size_t)b * L_ + l;
        float xc = src[(size_t)l * DPRJ];
        float a = fmaf(k0, xm3, fmaf(k1, xm2, fmaf(k2, xm1, fmaf(k3, xc, bias))));
        xBC[ro * CDIM + c] = a * sigm(a);
        xm3 = xm2; xm2 = xm1; xm1 = xc;
        if (c < NH) {
            float v = zx[ro * DPRJ + 640 + c] + dbias;
            dto[ro * NH + c] = (v > 15.f) ? v : log1pf(__expf(v));
        }
    }
}

// ======================= chunked SSM scan (one CTA per dir,b,chunk) =======
__global__ __launch_bounds__(256, 2) void scan1_k(
    const float* __restrict__ xBC0, const float* __restrict__ dt0,
    const float* __restrict__ xBC1, const float* __restrict__ dt1,
    const float* __restrict__ Al0, const float* __restrict__ D0,
    const float* __restrict__ Al1, const float* __restrict__ D1,
    float* __restrict__ y0, float* __restrict__ y1,
    float* __restrict__ S, float* __restrict__ cum)
{
    __shared__ float sx[2][TS][CDIM];
    __shared__ float sdt[2][TS * NH];

    int bid = blockIdx.x;
    int c   = bid & (NC - 1);
    int b   = (bid >> 6) & 15;
    int dir = bid >> 10;

    const float* xBC = dir ? xBC1 : xBC0;
    const float* dtb = dir ? dt1 : dt0;
    float* yo = dir ? y1 : y0;

    int h = threadIdx.x >> 5;
    int p = threadIdx.x & 31;

    float A  = -__expf((dir ? Al1 : Al0)[h]);
    float Dv = (dir ? D1 : D0)[h];

    const float* xbase  = xBC + ((size_t)b * L_ + (size_t)c * QC) * CDIM;
    const float* dtbase = dtb + ((size_t)b * L_ + (size_t)c * QC) * NH;
    float* ybase = yo + ((size_t)b * L_ + (size_t)c * QC) * DI + h * HD + p;
    float* cumh  = cum + (((size_t)dir * 16 + b) * 8 + h) * L_ + (size_t)c * QC;

    u64 s2[32];
    #pragma unroll
    for (int j = 0; j < 32; j++) s2[j] = 0ull;
    float cd = 1.f;

    auto load_tile = [&](int buf, int tile) {
        int l = tile * TS;
        const float4* g = reinterpret_cast<const float4*>(xbase + (size_t)(l + h) * CDIM);
        float4* sdst = reinterpret_cast<float4*>(&sx[buf][h][0]);
        #pragma unroll
        for (int k = 0; k < 3; k++) sdst[p + 32 * k] = g[p + 32 * k];
        if (threadIdx.x < (TS * NH) / 4) {
            reinterpret_cast<float4*>(&sdt[buf][0])[threadIdx.x] =
                reinterpret_cast<const float4*>(dtbase + (size_t)l * NH)[threadIdx.x];
        }
    };

    load_tile(0, 0);
    __syncthreads();

    for (int tile = 0; tile < NT; tile++) {
        int cur = tile & 1;
        if (tile + 1 < NT) load_tile(cur ^ 1, tile + 1);
        #pragma unroll
        for (int t = 0; t < TS; t++) {
            float dt = sdt[cur][t * NH + h];
            float dA = __expf(dt * A);
            cd *= dA;
            float xv = sx[cur][t][h * HD + p];
            float coef = dt * xv;
            u64 dA2 = splat2(dA), coef2 = splat2(coef);
            u64 yacc[4] = {0ull, 0ull, 0ull, 0ull};
            const float4* B4 = reinterpret_cast<const float4*>(&sx[cur][t][256]);
            const float4* C4 = reinterpret_cast<const float4*>(&sx[cur][t][320]);
            #pragma unroll
            for (int j = 0; j < 16; j++) {
                union { float4 f; u64 u[2]; } Bu, Cu;
                Bu.f = B4[j]; Cu.f = C4[j];
                u64 t0 = mul2(coef2, Bu.u[0]);
                fma2acc(t0, s2[2 * j], dA2);
                s2[2 * j] = t0;
                u64 t1 = mul2(coef2, Bu.u[1]);
                fma2acc(t1, s2[2 * j + 1], dA2);
                s2[2 * j + 1] = t1;
                fma2acc(yacc[j & 3], t0, Cu.u[0]);
                fma2acc(yacc[j & 3], t1, Cu.u[1]);
            }
            float yv = sum2(add2(add2(yacc[0], yacc[1]), add2(yacc[2], yacc[3])));
            ybase[(size_t)(tile * TS + t) * DI] = yv + Dv * xv;
            if (p == 0) cumh[tile * TS + t] = cd;
        }
        __syncthreads();
    }

    float* Sp = S + ((((size_t)dir * 16 + b) * 8 + h) * NC + c) * 2048 + p * 64;
    #pragma unroll
    for (int j = 0; j < 16; j++) {
        union { float4 f; u64 u[2]; } su;
        su.u[0] = s2[2 * j]; su.u[1] = s2[2 * j + 1];
        reinterpret_cast<float4*>(Sp)[j] = su.f;
    }
}

__global__ __launch_bounds__(256) void scan2_k(float* __restrict__ S, const float* __restrict__ cum)
{
    int bid = blockIdx.x;
    int h = bid & 7, b = (bid >> 3) & 15, dir = bid >> 7;
    float* Sb = S + (((size_t)dir * 16 + b) * 8 + h) * NC * 2048 + threadIdx.x * 8;
    const float* cumh = cum + (((size_t)dir * 16 + b) * 8 + h) * L_;
    float s[8];
    #pragma unroll
    for (int j = 0; j < 8; j++) s[j] = 0.f;
    for (int c = 0; c < NC; c++) {
        float* Sp = Sb + (size_t)c * 2048;
        float4 a0 = *reinterpret_cast<const float4*>(Sp);
        float4 a1 = *reinterpret_cast<const float4*>(Sp + 4);
        float Tc = cumh[(c + 1) * QC - 1];
        *reinterpret_cast<float4*>(Sp)     = make_float4(s[0], s[1], s[2], s[3]);
        *reinterpret_cast<float4*>(Sp + 4) = make_float4(s[4], s[5], s[6], s[7]);
        s[0] = fmaf(s[0], Tc, a0.x); s[1] = fmaf(s[1], Tc, a0.y);
        s[2] = fmaf(s[2], Tc, a0.z); s[3] = fmaf(s[3], Tc, a0.w);
        s[4] = fmaf(s[4], Tc, a1.x); s[5] = fmaf(s[5], Tc, a1.y);
        s[6] = fmaf(s[6], Tc, a1.z); s[7] = fmaf(s[7], Tc, a1.w);
    }
}

__global__ __launch_bounds__(256, 2) void scan3_k(
    const float* __restrict__ xBC0, const float* __restrict__ xBC1,
    float* __restrict__ y0, float* __restrict__ y1,
    const float* __restrict__ S, const float* __restrict__ cum)
{
    __shared__ float sc[2][TS3][64];

    int bid = blockIdx.x;
    int c    = bid % (NC - 1) + 1;
    int rest = bid / (NC - 1);
    int b = rest & 15, dir = rest >> 4;

    const float* xBC = dir ? xBC1 : xBC0;
    float* yo = dir ? y1 : y0;

    int h = threadIdx.x >> 5;
    int p = threadIdx.x & 31;

    const float* Sp = S + ((((size_t)dir * 16 + b) * 8 + h) * NC + c) * 2048 + p * 64;
    u64 s02[32];
    #pragma unroll
    for (int j = 0; j < 16; j++) {
        union { float4 f; u64 u[2]; } su;
        su.f = reinterpret_cast<const float4*>(Sp)[j];
        s02[2 * j] = su.u[0]; s02[2 * j + 1] = su.u[1];
    }

    const float* cbase = xBC + ((size_t)b * L_ + (size_t)c * QC) * CDIM + 320;
    const float* cumh  = cum + (((size_t)dir * 16 + b) * 8 + h) * L_ + (size_t)c * QC;
    float* ybase = yo + ((size_t)b * L_ + (size_t)c * QC) * DI + h * HD + p;

    auto load_tile = [&](int buf, int tile) {
        int l = tile * TS3;
        int row = threadIdx.x >> 4, f4 = threadIdx.x & 15;
        reinterpret_cast<float4*>(&sc[buf][row][0])[f4] =
            *reinterpret_cast<const float4*>(cbase + (size_t)(l + row) * CDIM + f4 * 4);
    };

    load_tile(0, 0);
    __syncthreads();

    for (int tile = 0; tile < NT3; tile++) {
        int cur = tile & 1;
        if (tile + 1 < NT3) load_tile(cur ^ 1, tile + 1);
        #pragma unroll
        for (int t = 0; t < TS3; t++) {
            u64 yacc[4] = {0ull, 0ull, 0ull, 0ull};
            const float4* C4 = reinterpret_cast<const float4*>(&sc[cur][t][0]);
            #pragma unroll
            for (int j = 0; j < 16; j++) {
                union { float4 f; u64 u[2]; } Cu;
                Cu.f = C4[j];
                fma2acc(yacc[j & 3], s02[2 * j], Cu.u[0]);
                fma2acc(yacc[j & 3], s02[2 * j + 1], Cu.u[1]);
            }
            float dot = sum2(add2(add2(yacc[0], yacc[1]), add2(yacc[2], yacc[3])));
            int l = tile * TS3 + t;
            float cd = __ldg(cumh + l);
            ybase[(size_t)l * DI] += cd * dot;
        }
        __syncthreads();
    }
}

// ---------------- y <- rmsnorm(y * silu(z)) * norm_w  (in place) ----------
__global__ void rmsy_k(float* __restrict__ y, const float* __restrict__ zx,
                       const float* __restrict__ nw)
{
    int warp = threadIdx.x >> 5, lane = threadIdx.x & 31;
    size_t row = (size_t)blockIdx.x * 8 + warp;
    float* yr = y + row * DI;
    const float* zr = zx + row * DPRJ;
    float4 y0v = *reinterpret_cast<const float4*>(yr + lane * 8);
    float4 y1v = *reinterpret_cast<const float4*>(yr + lane * 8 + 4);
    float4 z0v = *reinterpret_cast<const float4*>(zr + lane * 8);
    float4 z1v = *reinterpret_cast<const float4*>(zr + lane * 8 + 4);
    float v[8];
    v[0] = y0v.x * (z0v.x * sigm(z0v.x));
    v[1] = y0v.y * (z0v.y * sigm(z0v.y));
    v[2] = y0v.z * (z0v.z * sigm(z0v.z));
    v[3] = y0v.w * (z0v.w * sigm(z0v.w));
    v[4] = y1v.x * (z1v.x * sigm(z1v.x));
    v[5] = y1v.y * (z1v.y * sigm(z1v.y));
    v[6] = y1v.z * (z1v.z * sigm(z1v.z));
    v[7] = y1v.w * (z1v.w * sigm(z1v.w));
    float ss = 0.f;
    #pragma unroll
    for (int j = 0; j < 8; j++) ss = fmaf(v[j], v[j], ss);
    #pragma unroll
    for (int o = 16; o; o >>= 1) ss += __shfl_xor_sync(0xffffffffu, ss, o);
    float r = rsqrtf(ss * (1.f / 256.f) + 1e-5f);
    float4 w0 = *reinterpret_cast<const float4*>(nw + lane * 8);
    float4 w1 = *reinterpret_cast<const float4*>(nw + lane * 8 + 4);
    float4 o0, o1;
    o0.x = v[0] * r * w0.x; o0.y = v[1] * r * w0.y; o0.z = v[2] * r * w0.z; o0.w = v[3] * r * w0.w;
    o1.x = v[4] * r * w1.x; o1.y = v[5] * r * w1.y; o1.z = v[6] * r * w1.z; o1.w = v[7] * r * w1.w;
    *reinterpret_cast<float4*>(yr + lane * 8)     = o0;
    *reinterpret_cast<float4*>(yr + lane * 8 + 4) = o1;
}

// ---------------- e = (yf + reverse(yb)) * gate ----------------------------
__global__ void combine_k(const float* __restrict__ yf, const float* __restrict__ yb,
                          const float* __restrict__ gate, float* __restrict__ e)
{
    size_t i = (size_t)blockIdx.x * blockDim.x + threadIdx.x;
    if (i >= (size_t)BL * 32) return;
    size_t row = i >> 5; int c4 = (int)(i & 31);
    size_t b = row >> 13; int l = (int)(row & (L_ - 1));
    size_t rowb = (b << 13) + (size_t)(L_ - 1 - l);
    float4 a  = reinterpret_cast<const float4*>(yf)[row * 32 + c4];
    float4 bb = reinterpret_cast<const float4*>(yb)[rowb * 32 + c4];
    float4 g  = reinterpret_cast<const float4*>(gate)[row * 32 + c4];
    float4 o;
    o.x = (a.x + bb.x) * g.x; o.y = (a.y + bb.y) * g.y;
    o.z = (a.z + bb.z) * g.z; o.w = (a.w + bb.w) * g.w;
    reinterpret_cast<float4*>(e)[row * 32 + c4] = o;
}

// ---------------- out = x + rmsnorm(o, norm_w) ------------------------------
__global__ void final_k(const float* __restrict__ x, const float* __restrict__ o,
                        const float* __restrict__ nw, float* __restrict__ outp)
{
    int warp = threadIdx.x >> 5, lane = threadIdx.x & 31;
    size_t row = (size_t)blockIdx.x * 8 + warp;
    float4 v = *reinterpret_cast<const float4*>(o + row * DM + lane * 4);
    float ss = v.x * v.x + v.y * v.y + v.z * v.z + v.w * v.w;
    #pragma unroll
    for (int s = 16; s; s >>= 1) ss += __shfl_xor_sync(0xffffffffu, ss, s);
    float r = rsqrtf(ss * (1.f / 128.f) + 1e-5f);
    float4 xv = *reinterpret_cast<const float4*>(x + row * DM + lane * 4);
    float4 w  = *reinterpret_cast<const float4*>(nw + lane * 4);
    float4 res;
    res.x = xv.x + v.x * r * w.x; res.y = xv.y + v.y * r * w.y;
    res.z = xv.z + v.z * r * w.z; res.w = xv.w + v.w * r * w.w;
    *reinterpret_cast<float4*>(outp + row * DM + lane * 4) = res;
}

// ---------------- launch ----------------------------------------------------
extern "C" void kernel_launch(void* const* d_in, const int* in_sizes, int n_in,
                              void* d_out, int out_size)
{
    const float* x       = (const float*)d_in[0];
    const float* gate_w  = (const float*)d_in[1];
    const float* gate_b  = (const float*)d_in[2];
    const float* fconv_w = (const float*)d_in[3];
    const float* fconv_b = (const float*)d_in[4];
    const float* flin_w  = (const float*)d_in[5];
    const float* flin_b  = (const float*)d_in[6];
    const float* f_in_w  = (const float*)d_in[7];
    const float* f_cw    = (const float*)d_in[8];
    const float* f_cb    = (const float*)d_in[9];
    const float* f_dtb   = (const float*)d_in[10];
    const float* f_Alog  = (const float*)d_in[11];
    const float* f_D     = (const float*)d_in[12];
    const float* f_nw    = (const float*)d_in[13];
    const float* f_ow    = (const float*)d_in[14];
    const float* bconv_w = (const float*)d_in[15];
    const float* bconv_b = (const float*)d_in[16];
    const float* blin_w  = (const float*)d_in[17];
    const float* blin_b  = (const float*)d_in[18];
    const float* b_in_w  = (const float*)d_in[19];
    const float* b_cw    = (const float*)d_in[20];
    const float* b_cb    = (const float*)d_in[21];
    const float* b_dtb   = (const float*)d_in[22];
    const float* b_Alog  = (const float*)d_in[23];
    const float* b_D     = (const float*)d_in[24];
    const float* b_nw    = (const float*)d_in[25];
    const float* b_ow    = (const float*)d_in[26];
    const float* out_w   = (const float*)d_in[27];
    const float* out_b   = (const float*)d_in[28];
    const float* norm_w  = (const float*)d_in[29];

    float *p_gate, *p_u, *p_zx, *p_xBC, *p_dt, *p_y, *p_ydir, *p_Wf, *p_bf, *p_S, *p_cum;
    cudaGetSymbolAddress((void**)&p_gate, g_gate);
    cudaGetSymbolAddress((void**)&p_u,    g_u);
    cudaGetSymbolAddress((void**)&p_zx,   g_zx);
    cudaGetSymbolAddress((void**)&p_xBC,  g_xBC);
    cudaGetSymbolAddress((void**)&p_dt,   g_dt);
    cudaGetSymbolAddress((void**)&p_y,    g_y);
    cudaGetSymbolAddress((void**)&p_ydir, g_ydir);
    cudaGetSymbolAddress((void**)&p_Wf,   g_Wf);
    cudaGetSymbolAddress((void**)&p_bf,   g_bf);
    cudaGetSymbolAddress((void**)&p_S,    g_S);
    cudaGetSymbolAddress((void**)&p_cum,  g_cum);

    float* u0   = p_u;                 float* u1   = p_u   + (size_t)BL * DM;
    float* zx0  = p_zx;                float* zx1  = p_zx  + (size_t)BL * DPRJ;
    float* xb0  = p_xBC;               float* xb1  = p_xBC + (size_t)BL * CDIM;
    float* dt0  = p_dt;                float* dt1  = p_dt  + (size_t)BL * NH;
    float* y0   = p_y;                 float* y1   = p_y   + (size_t)BL * DI;
    float* yd0  = p_ydir;              float* yd1  = p_ydir + (size_t)BL * DM;
    float* Wf0  = p_Wf;                float* Wf1  = p_Wf  + DM * 3 * DM;
    float* bf0  = p_bf;                float* bf1  = p_bf  + DM;

    const int MT = BL / 128;

    prep_w_k<<<384, 256>>>(flin_w, fconv_w, blin_w, bconv_w, Wf0, Wf1);
    prep_b_k<<<1, 256>>>(flin_b, fconv_b, blin_b, bconv_b, flin_w, blin_w, bf0, bf1);

    gemm_k<<<dim3(MT, 1), 256>>>(x, gate_w, gate_b, p_gate, 128, 128, 0, 1);

    gemm_k<<<dim3(MT, 1), 256>>>(x, Wf0, bf0, u0, 128, 384, 1, 0);
    gemm_k<<<dim3(MT, 1), 256>>>(x, Wf1, bf1, u1, 128, 384, 2, 0);

    gemm_k<<<dim3(MT, 6), 256>>>(u0, f_in_w, nullptr, zx0, 648, 128, 0, 0);
    gemm_k<<<dim3(MT, 6), 256>>>(u1, b_in_w, nullptr, zx1, 648, 128, 0, 0);

    dconv_k<<<dim3(L_ / 128, B_), 384>>>(zx0, f_cw, f_cb, f_dtb, xb0, dt0);
    dconv_k<<<dim3(L_ / 128, B_), 384>>>(zx1, b_cw, b_cb, b_dtb, xb1, dt1);

    scan1_k<<<2 * 16 * NC, 256>>>(xb0, dt0, xb1, dt1, f_Alog, f_D, b_Alog, b_D,
                                  y0, y1, p_S, p_cum);
    scan2_k<<<256, 256>>>(p_S, p_cum);
    scan3_k<<<2 * 16 * (NC - 1), 256>>>(xb0, xb1, y0, y1, p_S, p_cum);

    rmsy_k<<<BL / 8, 256>>>(y0, zx0, f_nw);
    rmsy_k<<<BL / 8, 256>>>(y1, zx1, b_nw);

    gemm_k<<<dim3(MT, 1), 256>>>(y0, f_ow, nullptr, yd0, 128, 256, 0, 0);
    gemm_k<<<dim3(MT, 1), 256>>>(y1, b_ow, nullptr, yd1, 128, 256, 0, 0);

    combine_k<<<(BL * 32) / 256, 256>>>(yd0, yd1, p_gate, u0);

    gemm_k<<<dim3(MT, 1), 256>>>(u0, out_w, out_b, u1, 128, 128, 0, 0);

    final_k<<<BL / 8, 256>>>(x, u1, norm_w, (float*)d_out);
}

// round 6
// speedup vs baseline: 3.5745x; 1.0303x over previous
#include <cuda_runtime.h>
#include <math.h>

#define B_   16
#define L_   8192
#define DM   128
#define DI   256
#define NH   8
#define HD   32
#define DST  64
#define CDIM 384
#define DPRJ 648
#define BL   (B_*L_)   /* 131072 */
#define QC   128       /* scan chunk length */
#define NC   (L_/QC)   /* 64 chunks */
#define TS   8         /* scan1 smem tile steps */
#define NT   (QC/TS)
#define TS3  16        /* scan3 smem tile steps */
#define NT3  (QC/TS3)

// ---------------- scratch (static device globals; no allocation) ----------
__device__ float g_gate[BL*DM];
__device__ float g_u[2][(size_t)BL*DM];
__device__ float g_zx[2][(size_t)BL*DPRJ];
__device__ float g_xBC[2][(size_t)BL*CDIM];
__device__ float g_dt[2][(size_t)BL*NH];
__device__ float g_y[2][(size_t)BL*DI];
__device__ float g_ydir[2][(size_t)BL*DM];
__device__ float g_Wf[2][DM*3*DM];
__device__ float g_bf[2][DM];
__device__ float g_S[(size_t)2*16*8*NC*2048];
__device__ float g_cum[(size_t)2*16*8*L_];

__device__ __forceinline__ float sigm(float v) { return 1.f / (1.f + __expf(-v)); }

__device__ __forceinline__ float tf32f(float v) {
    unsigned r;
    asm("cvt.rna.tf32.f32 %0, %1;" : "=r"(r) : "f"(v));
    return __uint_as_float(r);
}

typedef unsigned long long u64;
__device__ __forceinline__ u64 splat2(float v) {
    u64 r; asm("mov.b64 %0, {%1, %1};" : "=l"(r) : "f"(v)); return r;
}
__device__ __forceinline__ u64 mul2(u64 a, u64 b) {
    u64 d; asm("mul.rn.f32x2 %0, %1, %2;" : "=l"(d) : "l"(a), "l"(b)); return d;
}
__device__ __forceinline__ void fma2acc(u64& d, u64 a, u64 b) {
    asm("fma.rn.f32x2 %0, %1, %2, %0;" : "+l"(d) : "l"(a), "l"(b));
}
__device__ __forceinline__ u64 add2(u64 a, u64 b) {
    u64 d; asm("add.rn.f32x2 %0, %1, %2;" : "=l"(d) : "l"(a), "l"(b)); return d;
}
__device__ __forceinline__ float sum2(u64 v) {
    float lo, hi; asm("mov.b64 {%0, %1}, %2;" : "=f"(lo), "=f"(hi) : "l"(v)); return lo + hi;
}

// ---------------- weight prep: E[dir][o, s*128+i] = lin@convw (+lin at s==1)
__global__ void prep_w_k(const float* __restrict__ flw, const float* __restrict__ fcw,
                         const float* __restrict__ blw, const float* __restrict__ bcw,
                         float* __restrict__ w0, float* __restrict__ w1)
{
    int idx = blockIdx.x * blockDim.x + threadIdx.x;
    if (idx >= 2 * 128 * 384) return;
    int dir = idx / (128 * 384);
    int rem = idx % (128 * 384);
    int o = rem / 384, kk = rem % 384;
    int s = kk >> 7, i = kk & 127;
    const float* lw = dir ? blw : flw;
    const float* cw = dir ? bcw : fcw;
    float acc = (s == 1) ? lw[o * 128 + i] : 0.f;
    #pragma unroll 4
    for (int j = 0; j < 128; j++)
        acc = fmaf(lw[o * 128 + j], cw[j * 384 + i * 3 + s], acc);
    (dir ? w1 : w0)[o * 384 + kk] = acc;
}

__global__ void prep_b_k(const float* __restrict__ flb, const float* __restrict__ fcb,
                         const float* __restrict__ blb, const float* __restrict__ bcb,
                         const float* __restrict__ flw, const float* __restrict__ blw,
                         float* __restrict__ b0, float* __restrict__ b1)
{
    int t = threadIdx.x;
    int dir = t >> 7, o = t & 127;
    const float* lb = dir ? blb : flb;
    const float* cb = dir ? bcb : fcb;
    const float* lw = dir ? blw : flw;
    float acc = lb[o];
    for (int j = 0; j < 128; j++) acc = fmaf(lw[o * 128 + j], cb[j], acc);
    (dir ? b1 : b0)[o] = acc;
}

// ---------------- tf32 tensor-core GEMM, swizzled smem, double-buffered ----
// C[M,N] = act(A @ W^T + bias)
// mode 0: plain A. mode 1/2: conv3 view of x (fwd/rev). mode 3: (A + rev(A2)) * A3.
#define SPAD 136
__global__ __launch_bounds__(256, 2) void gemm_k(
    const float* __restrict__ A, const float* __restrict__ A2,
    const float* __restrict__ A3, const float* __restrict__ W,
    const float* __restrict__ bias, float* __restrict__ C,
    int N, int K, int mode, int act)
{
    __shared__ float As[2][16][SPAD];
    __shared__ float Bs[2][16][SPAD];
    int tid = threadIdx.x;
    int lane = tid & 31, warp = tid >> 5;
    int wm = warp & 1, wn = warp >> 1;
    int bm = blockIdx.x << 7, bn = blockIdx.y << 7;
    int lrow = tid >> 2;
    int lc4  = (tid & 3) << 2;
    int rl = lane >> 2, cl = lane & 3;

    float acc[4][4][4];
    #pragma unroll
    for (int a = 0; a < 4; a++)
        #pragma unroll
        for (int b = 0; b < 4; b++)
            #pragma unroll
            for (int e = 0; e < 4; e++) acc[a][b][e] = 0.f;

    float4 ar[2], br[2];

    const float* arow[2];
    const float* wrow[2];
    bool wok[2];
    #pragma unroll
    for (int rr = 0; rr < 2; rr++) {
        arow[rr] = A + (size_t)(bm + lrow + (rr << 6)) * K + lc4;
        int n = bn + lrow + (rr << 6);
        wok[rr] = (n < N);
        wrow[rr] = W + (size_t)(wok[rr] ? n : 0) * K + lc4;
    }

    auto fetch = [&](int k0) {
        #pragma unroll
        for (int rr = 0; rr < 2; rr++) {
            if (mode == 0) {
                ar[rr] = *reinterpret_cast<const float4*>(arow[rr] + k0);
            } else if (mode == 3) {
                int m = bm + lrow + (rr << 6);
                int kk = k0 + lc4;
                int b = m >> 13, l = m & (L_ - 1);
                size_t rowb = ((size_t)b << 13) + (size_t)(L_ - 1 - l);
                float4 a  = *reinterpret_cast<const float4*>(A  + (size_t)m * DM + kk);
                float4 bb = *reinterpret_cast<const float4*>(A2 + rowb * DM + kk);
                float4 g  = *reinterpret_cast<const float4*>(A3 + (size_t)m * DM + kk);
                ar[rr] = make_float4((a.x + bb.x) * g.x, (a.y + bb.y) * g.y,
                                     (a.z + bb.z) * g.z, (a.w + bb.w) * g.w);
            } else {
                int m = bm + lrow + (rr << 6);
                int kk = k0 + lc4;
                int b = m >> 13, l = m & (L_ - 1);
                int s = kk >> 7, i = kk & 127;
                int ls = l + s - 1;
                float4 v = make_float4(0.f, 0.f, 0.f, 0.f);
                if (ls >= 0 && ls < L_) {
                    int lsrc = (mode == 2) ? (L_ - 1 - ls) : ls;
                    v = *reinterpret_cast<const float4*>(A + ((size_t)b * L_ + lsrc) * DM + i);
                }
                ar[rr] = v;
            }
            br[rr] = wok[rr] ? *reinterpret_cast<const float4*>(wrow[rr] + k0)
                             : make_float4(0.f, 0.f, 0.f, 0.f);
        }
    };

    // store-column swizzle: col = m ^ (((k>>2)&3)<<3); k = lc4+i -> (k>>2)=(lc4>>2)
    int xstore = lc4 << 1;   // (lc4>>2)<<3
    auto stage = [&](int buf) {
        #pragma unroll
        for (int rr = 0; rr < 2; rr++) {
            int col = (lrow + (rr << 6)) ^ xstore;
            As[buf][lc4 + 0][col] = tf32f(ar[rr].x);
            As[buf][lc4 + 1][col] = tf32f(ar[rr].y);
            As[buf][lc4 + 2][col] = tf32f(ar[rr].z);
            As[buf][lc4 + 3][col] = tf32f(ar[rr].w);
            Bs[buf][lc4 + 0][col] = tf32f(br[rr].x);
            Bs[buf][lc4 + 1][col] = tf32f(br[rr].y);
            Bs[buf][lc4 + 2][col] = tf32f(br[rr].z);
            Bs[buf][lc4 + 3][col] = tf32f(br[rr].w);
        }
    };

    fetch(0);
    stage(0);

    int cur = 0;
    for (int k0 = 0; k0 < K; k0 += 16, cur ^= 1) {
        __syncthreads();
        bool more = (k0 + 16 < K);
        if (more) fetch(k0 + 16);

        #pragma unroll
        for (int ks = 0; ks < 2; ks++) {
            int kb = ks << 3;
            int xa = kb << 1;        // ((kb)>>2)<<3 : 0 or 16
            int xb = xa + 8;         // for k rows kb+cl+4
            unsigned bf[4][2];
            #pragma unroll
            for (int tn = 0; tn < 4; tn++) {
                int n = wn * 32 + tn * 8 + rl;
                bf[tn][0] = __float_as_uint(Bs[cur][kb + cl][n ^ xa]);
                bf[tn][1] = __float_as_uint(Bs[cur][kb + cl + 4][n ^ xb]);
            }
            unsigned af[4][4];
            #pragma unroll
            for (int tm = 0; tm < 4; tm++) {
                int m = wm * 64 + tm * 16 + rl;
                af[tm][0] = __float_as_uint(As[cur][kb + cl][m ^ xa]);
                af[tm][1] = __float_as_uint(As[cur][kb + cl][(m + 8) ^ xa]);
                af[tm][2] = __float_as_uint(As[cur][kb + cl + 4][m ^ xb]);
                af[tm][3] = __float_as_uint(As[cur][kb + cl + 4][(m + 8) ^ xb]);
            }
            #pragma unroll
            for (int tm = 0; tm < 4; tm++)
                #pragma unroll
                for (int tn = 0; tn < 4; tn++)
                    asm volatile(
                        "mma.sync.aligned.m16n8k8.row.col.f32.tf32.tf32.f32 "
                        "{%0,%1,%2,%3}, {%4,%5,%6,%7}, {%8,%9}, {%0,%1,%2,%3};"
                        : "+f"(acc[tm][tn][0]), "+f"(acc[tm][tn][1]),
                          "+f"(acc[tm][tn][2]), "+f"(acc[tm][tn][3])
                        : "r"(af[tm][0]), "r"(af[tm][1]), "r"(af[tm][2]), "r"(af[tm][3]),
                          "r"(bf[tn][0]), "r"(bf[tn][1]));
        }

        if (more) stage(cur ^ 1);
    }

    #pragma unroll
    for (int tm = 0; tm < 4; tm++) {
        int m0 = bm + wm * 64 + tm * 16 + rl;
        #pragma unroll
        for (int tn = 0; tn < 4; tn++) {
            int n0 = bn + wn * 32 + tn * 8 + cl * 2;
            #pragma unroll
            for (int e = 0; e < 4; e++) {
                int m = m0 + ((e >> 1) << 3);
                int n = n0 + (e & 1);
                if (n < N) {
                    float v = acc[tm][tn][e];
                    if (bias) v += bias[n];
                    if (act == 1) v *= sigm(v);
                    C[(size_t)m * N + n] = v;
                }
            }
        }
    }
}

// ---------------- depthwise causal conv4 + silu on xBC, and softplus dt ----
__global__ void dconv_k(const float* __restrict__ zx, const float* __restrict__ cw,
                        const float* __restrict__ cb, const float* __restrict__ dtb,
                        float* __restrict__ xBC, float* __restrict__ dto)
{
    int b = blockIdx.y;
    int l0 = blockIdx.x << 7;
    int c = threadIdx.x;
    const float* src = zx + (size_t)b * L_ * DPRJ + 256 + c;
    float k0 = cw[c * 4 + 0], k1 = cw[c * 4 + 1], k2 = cw[c * 4 + 2], k3 = cw[c * 4 + 3];
    float bias = cb[c];
    float xm3, xm2, xm1;
    if (l0 == 0) { xm3 = 0.f; xm2 = 0.f; xm1 = 0.f; }
    else {
        xm3 = src[(size_t)(l0 - 3) * DPRJ];
        xm2 = src[(size_t)(l0 - 2) * DPRJ];
        xm1 = src[(size_t)(l0 - 1) * DPRJ];
    }
    float dbias = (c < NH) ? dtb[c] : 0.f;
    #pragma unroll 4
    for (int t = 0; t < 128; t++) {
        int l = l0 + t;
        size_t ro = (size_t)b * L_ + l;
        float xc = src[(size_t)l * DPRJ];
        float a = fmaf(k0, xm3, fmaf(k1, xm2, fmaf(k2, xm1, fmaf(k3, xc, bias))));
        xBC[ro * CDIM + c] = a * sigm(a);
        xm3 = xm2; xm2 = xm1; xm1 = xc;
        if (c < NH) {
            float v = zx[ro * DPRJ + 640 + c] + dbias;
            dto[ro * NH + c] = (v > 15.f) ? v : log1pf(__expf(v));
        }
    }
}

// ======================= chunked SSM scan (one CTA per dir,b,chunk) =======
__global__ __launch_bounds__(256, 2) void scan1_k(
    const float* __restrict__ xBC0, const float* __restrict__ dt0,
    const float* __restrict__ xBC1, const float* __restrict__ dt1,
    const float* __restrict__ Al0, const float* __restrict__ D0,
    const float* __restrict__ Al1, const float* __restrict__ D1,
    float* __restrict__ y0, float* __restrict__ y1,
    float* __restrict__ S, float* __restrict__ cum)
{
    __shared__ float sx[2][TS][CDIM];
    __shared__ float sdt[2][TS * NH];

    int bid = blockIdx.x;
    int c   = bid & (NC - 1);
    int b   = (bid >> 6) & 15;
    int dir = bid >> 10;

    const float* xBC = dir ? xBC1 : xBC0;
    const float* dtb = dir ? dt1 : dt0;
    float* yo = dir ? y1 : y0;

    int h = threadIdx.x >> 5;
    int p = threadIdx.x & 31;

    float A  = -__expf((dir ? Al1 : Al0)[h]);
    float Dv = (dir ? D1 : D0)[h];

    const float* xbase  = xBC + ((size_t)b * L_ + (size_t)c * QC) * CDIM;
    const float* dtbase = dtb + ((size_t)b * L_ + (size_t)c * QC) * NH;
    float* ybase = yo + ((size_t)b * L_ + (size_t)c * QC) * DI + h * HD + p;
    float* cumh  = cum + (((size_t)dir * 16 + b) * 8 + h) * L_ + (size_t)c * QC;

    u64 s2[32];
    #pragma unroll
    for (int j = 0; j < 32; j++) s2[j] = 0ull;
    float cd = 1.f;

    auto load_tile = [&](int buf, int tile) {
        int l = tile * TS;
        const float4* g = reinterpret_cast<const float4*>(xbase + (size_t)(l + h) * CDIM);
        float4* sdst = reinterpret_cast<float4*>(&sx[buf][h][0]);
        #pragma unroll
        for (int k = 0; k < 3; k++) sdst[p + 32 * k] = g[p + 32 * k];
        if (threadIdx.x < (TS * NH) / 4) {
            reinterpret_cast<float4*>(&sdt[buf][0])[threadIdx.x] =
                reinterpret_cast<const float4*>(dtbase + (size_t)l * NH)[threadIdx.x];
        }
    };

    load_tile(0, 0);
    __syncthreads();

    for (int tile = 0; tile < NT; tile++) {
        int cur = tile & 1;
        if (tile + 1 < NT) load_tile(cur ^ 1, tile + 1);
        #pragma unroll
        for (int t = 0; t < TS; t++) {
            float dt = sdt[cur][t * NH + h];
            float dA = __expf(dt * A);
            cd *= dA;
            float xv = sx[cur][t][h * HD + p];
            float coef = dt * xv;
            u64 dA2 = splat2(dA), coef2 = splat2(coef);
            u64 yacc[4] = {0ull, 0ull, 0ull, 0ull};
            const float4* B4 = reinterpret_cast<const float4*>(&sx[cur][t][256]);
            const float4* C4 = reinterpret_cast<const float4*>(&sx[cur][t][320]);
            #pragma unroll
            for (int j = 0; j < 16; j++) {
                union { float4 f; u64 u[2]; } Bu, Cu;
                Bu.f = B4[j]; Cu.f = C4[j];
                u64 t0 = mul2(coef2, Bu.u[0]);
                fma2acc(t0, s2[2 * j], dA2);
                s2[2 * j] = t0;
                u64 t1 = mul2(coef2, Bu.u[1]);
                fma2acc(t1, s2[2 * j + 1], dA2);
                s2[2 * j + 1] = t1;
                fma2acc(yacc[j & 3], t0, Cu.u[0]);
                fma2acc(yacc[j & 3], t1, Cu.u[1]);
            }
            float yv = sum2(add2(add2(yacc[0], yacc[1]), add2(yacc[2], yacc[3])));
            ybase[(size_t)(tile * TS + t) * DI] = yv + Dv * xv;
            if (p == 0) cumh[tile * TS + t] = cd;
        }
        __syncthreads();
    }

    float* Sp = S + ((((size_t)dir * 16 + b) * 8 + h) * NC + c) * 2048 + p * 64;
    #pragma unroll
    for (int j = 0; j < 16; j++) {
        union { float4 f; u64 u[2]; } su;
        su.u[0] = s2[2 * j]; su.u[1] = s2[2 * j + 1];
        reinterpret_cast<float4*>(Sp)[j] = su.f;
    }
}

__global__ __launch_bounds__(256) void scan2_k(float* __restrict__ S, const float* __restrict__ cum)
{
    int bid = blockIdx.x;
    int h = bid & 7, b = (bid >> 3) & 15, dir = bid >> 7;
    float* Sb = S + (((size_t)dir * 16 + b) * 8 + h) * NC * 2048 + threadIdx.x * 8;
    const float* cumh = cum + (((size_t)dir * 16 + b) * 8 + h) * L_;
    float s[8];
    #pragma unroll
    for (int j = 0; j < 8; j++) s[j] = 0.f;
    for (int c = 0; c < NC; c++) {
        float* Sp = Sb + (size_t)c * 2048;
        float4 a0 = *reinterpret_cast<const float4*>(Sp);
        float4 a1 = *reinterpret_cast<const float4*>(Sp + 4);
        float Tc = cumh[(c + 1) * QC - 1];
        *reinterpret_cast<float4*>(Sp)     = make_float4(s[0], s[1], s[2], s[3]);
        *reinterpret_cast<float4*>(Sp + 4) = make_float4(s[4], s[5], s[6], s[7]);
        s[0] = fmaf(s[0], Tc, a0.x); s[1] = fmaf(s[1], Tc, a0.y);
        s[2] = fmaf(s[2], Tc, a0.z); s[3] = fmaf(s[3], Tc, a0.w);
        s[4] = fmaf(s[4], Tc, a1.x); s[5] = fmaf(s[5], Tc, a1.y);
        s[6] = fmaf(s[6], Tc, a1.z); s[7] = fmaf(s[7], Tc, a1.w);
    }
}

__global__ __launch_bounds__(256, 2) void scan3_k(
    const float* __restrict__ xBC0, const float* __restrict__ xBC1,
    float* __restrict__ y0, float* __restrict__ y1,
    const float* __restrict__ S, const float* __restrict__ cum)
{
    __shared__ float sc[2][TS3][64];

    int bid = blockIdx.x;
    int c    = bid % (NC - 1) + 1;
    int rest = bid / (NC - 1);
    int b = rest & 15, dir = rest >> 4;

    const float* xBC = dir ? xBC1 : xBC0;
    float* yo = dir ? y1 : y0;

    int h = threadIdx.x >> 5;
    int p = threadIdx.x & 31;

    const float* Sp = S + ((((size_t)dir * 16 + b) * 8 + h) * NC + c) * 2048 + p * 64;
    u64 s02[32];
    #pragma unroll
    for (int j = 0; j < 16; j++) {
        union { float4 f; u64 u[2]; } su;
        su.f = reinterpret_cast<const float4*>(Sp)[j];
        s02[2 * j] = su.u[0]; s02[2 * j + 1] = su.u[1];
    }

    const float* cbase = xBC + ((size_t)b * L_ + (size_t)c * QC) * CDIM + 320;
    const float* cumh  = cum + (((size_t)dir * 16 + b) * 8 + h) * L_ + (size_t)c * QC;
    float* ybase = yo + ((size_t)b * L_ + (size_t)c * QC) * DI + h * HD + p;

    auto load_tile = [&](int buf, int tile) {
        int l = tile * TS3;
        int row = threadIdx.x >> 4, f4 = threadIdx.x & 15;
        reinterpret_cast<float4*>(&sc[buf][row][0])[f4] =
            *reinterpret_cast<const float4*>(cbase + (size_t)(l + row) * CDIM + f4 * 4);
    };

    load_tile(0, 0);
    __syncthreads();

    for (int tile = 0; tile < NT3; tile++) {
        int cur = tile & 1;
        if (tile + 1 < NT3) load_tile(cur ^ 1, tile + 1);
        #pragma unroll
        for (int t = 0; t < TS3; t++) {
            u64 yacc[4] = {0ull, 0ull, 0ull, 0ull};
            const float4* C4 = reinterpret_cast<const float4*>(&sc[cur][t][0]);
            #pragma unroll
            for (int j = 0; j < 16; j++) {
                union { float4 f; u64 u[2]; } Cu;
                Cu.f = C4[j];
                fma2acc(yacc[j & 3], s02[2 * j], Cu.u[0]);
                fma2acc(yacc[j & 3], s02[2 * j + 1], Cu.u[1]);
            }
            float dot = sum2(add2(add2(yacc[0], yacc[1]), add2(yacc[2], yacc[3])));
            int l = tile * TS3 + t;
            float cd = __ldg(cumh + l);
            ybase[(size_t)l * DI] += cd * dot;
        }
        __syncthreads();
    }
}

// ---------------- y <- rmsnorm(y * silu(z)) * norm_w  (in place) ----------
__global__ void rmsy_k(float* __restrict__ y, const float* __restrict__ zx,
                       const float* __restrict__ nw)
{
    int warp = threadIdx.x >> 5, lane = threadIdx.x & 31;
    size_t row = (size_t)blockIdx.x * 8 + warp;
    float* yr = y + row * DI;
    const float* zr = zx + row * DPRJ;
    float4 y0v = *reinterpret_cast<const float4*>(yr + lane * 8);
    float4 y1v = *reinterpret_cast<const float4*>(yr + lane * 8 + 4);
    float4 z0v = *reinterpret_cast<const float4*>(zr + lane * 8);
    float4 z1v = *reinterpret_cast<const float4*>(zr + lane * 8 + 4);
    float v[8];
    v[0] = y0v.x * (z0v.x * sigm(z0v.x));
    v[1] = y0v.y * (z0v.y * sigm(z0v.y));
    v[2] = y0v.z * (z0v.z * sigm(z0v.z));
    v[3] = y0v.w * (z0v.w * sigm(z0v.w));
    v[4] = y1v.x * (z1v.x * sigm(z1v.x));
    v[5] = y1v.y * (z1v.y * sigm(z1v.y));
    v[6] = y1v.z * (z1v.z * sigm(z1v.z));
    v[7] = y1v.w * (z1v.w * sigm(z1v.w));
    float ss = 0.f;
    #pragma unroll
    for (int j = 0; j < 8; j++) ss = fmaf(v[j], v[j], ss);
    #pragma unroll
    for (int o = 16; o; o >>= 1) ss += __shfl_xor_sync(0xffffffffu, ss, o);
    float r = rsqrtf(ss * (1.f / 256.f) + 1e-5f);
    float4 w0 = *reinterpret_cast<const float4*>(nw + lane * 8);
    float4 w1 = *reinterpret_cast<const float4*>(nw + lane * 8 + 4);
    float4 o0, o1;
    o0.x = v[0] * r * w0.x; o0.y = v[1] * r * w0.y; o0.z = v[2] * r * w0.z; o0.w = v[3] * r * w0.w;
    o1.x = v[4] * r * w1.x; o1.y = v[5] * r * w1.y; o1.z = v[6] * r * w1.z; o1.w = v[7] * r * w1.w;
    *reinterpret_cast<float4*>(yr + lane * 8)     = o0;
    *reinterpret_cast<float4*>(yr + lane * 8 + 4) = o1;
}

// ---------------- out = x + rmsnorm(o, norm_w) ------------------------------
__global__ void final_k(const float* __restrict__ x, const float* __restrict__ o,
                        const float* __restrict__ nw, float* __restrict__ outp)
{
    int warp = threadIdx.x >> 5, lane = threadIdx.x & 31;
    size_t row = (size_t)blockIdx.x * 8 + warp;
    float4 v = *reinterpret_cast<const float4*>(o + row * DM + lane * 4);
    float ss = v.x * v.x + v.y * v.y + v.z * v.z + v.w * v.w;
    #pragma unroll
    for (int s = 16; s; s >>= 1) ss += __shfl_xor_sync(0xffffffffu, ss, s);
    float r = rsqrtf(ss * (1.f / 128.f) + 1e-5f);
    float4 xv = *reinterpret_cast<const float4*>(x + row * DM + lane * 4);
    float4 w  = *reinterpret_cast<const float4*>(nw + lane * 4);
    float4 res;
    res.x = xv.x + v.x * r * w.x; res.y = xv.y + v.y * r * w.y;
    res.z = xv.z + v.z * r * w.z; res.w = xv.w + v.w * r * w.w;
    *reinterpret_cast<float4*>(outp + row * DM + lane * 4) = res;
}

// ---------------- launch ----------------------------------------------------
extern "C" void kernel_launch(void* const* d_in, const int* in_sizes, int n_in,
                              void* d_out, int out_size)
{
    const float* x       = (const float*)d_in[0];
    const float* gate_w  = (const float*)d_in[1];
    const float* gate_b  = (const float*)d_in[2];
    const float* fconv_w = (const float*)d_in[3];
    const float* fconv_b = (const float*)d_in[4];
    const float* flin_w  = (const float*)d_in[5];
    const float* flin_b  = (const float*)d_in[6];
    const float* f_in_w  = (const float*)d_in[7];
    const float* f_cw    = (const float*)d_in[8];
    const float* f_cb    = (const float*)d_in[9];
    const float* f_dtb   = (const float*)d_in[10];
    const float* f_Alog  = (const float*)d_in[11];
    const float* f_D     = (const float*)d_in[12];
    const float* f_nw    = (const float*)d_in[13];
    const float* f_ow    = (const float*)d_in[14];
    const float* bconv_w = (const float*)d_in[15];
    const float* bconv_b = (const float*)d_in[16];
    const float* blin_w  = (const float*)d_in[17];
    const float* blin_b  = (const float*)d_in[18];
    const float* b_in_w  = (const float*)d_in[19];
    const float* b_cw    = (const float*)d_in[20];
    const float* b_cb    = (const float*)d_in[21];
    const float* b_dtb   = (const float*)d_in[22];
    const float* b_Alog  = (const float*)d_in[23];
    const float* b_D     = (const float*)d_in[24];
    const float* b_nw    = (const float*)d_in[25];
    const float* b_ow    = (const float*)d_in[26];
    const float* out_w   = (const float*)d_in[27];
    const float* out_b   = (const float*)d_in[28];
    const float* norm_w  = (const float*)d_in[29];

    float *p_gate, *p_u, *p_zx, *p_xBC, *p_dt, *p_y, *p_ydir, *p_Wf, *p_bf, *p_S, *p_cum;
    cudaGetSymbolAddress((void**)&p_gate, g_gate);
    cudaGetSymbolAddress((void**)&p_u,    g_u);
    cudaGetSymbolAddress((void**)&p_zx,   g_zx);
    cudaGetSymbolAddress((void**)&p_xBC,  g_xBC);
    cudaGetSymbolAddress((void**)&p_dt,   g_dt);
    cudaGetSymbolAddress((void**)&p_y,    g_y);
    cudaGetSymbolAddress((void**)&p_ydir, g_ydir);
    cudaGetSymbolAddress((void**)&p_Wf,   g_Wf);
    cudaGetSymbolAddress((void**)&p_bf,   g_bf);
    cudaGetSymbolAddress((void**)&p_S,    g_S);
    cudaGetSymbolAddress((void**)&p_cum,  g_cum);

    float* u0   = p_u;                 float* u1   = p_u   + (size_t)BL * DM;
    float* zx0  = p_zx;                float* zx1  = p_zx  + (size_t)BL * DPRJ;
    float* xb0  = p_xBC;               float* xb1  = p_xBC + (size_t)BL * CDIM;
    float* dt0  = p_dt;                float* dt1  = p_dt  + (size_t)BL * NH;
    float* y0   = p_y;                 float* y1   = p_y   + (size_t)BL * DI;
    float* yd0  = p_ydir;              float* yd1  = p_ydir + (size_t)BL * DM;
    float* Wf0  = p_Wf;                float* Wf1  = p_Wf  + DM * 3 * DM;
    float* bf0  = p_bf;                float* bf1  = p_bf  + DM;

    const int MT = BL / 128;

    prep_w_k<<<384, 256>>>(flin_w, fconv_w, blin_w, bconv_w, Wf0, Wf1);
    prep_b_k<<<1, 256>>>(flin_b, fconv_b, blin_b, bconv_b, flin_w, blin_w, bf0, bf1);

    gemm_k<<<dim3(MT, 1), 256>>>(x, nullptr, nullptr, gate_w, gate_b, p_gate, 128, 128, 0, 1);

    gemm_k<<<dim3(MT, 1), 256>>>(x, nullptr, nullptr, Wf0, bf0, u0, 128, 384, 1, 0);
    gemm_k<<<dim3(MT, 1), 256>>>(x, nullptr, nullptr, Wf1, bf1, u1, 128, 384, 2, 0);

    gemm_k<<<dim3(MT, 6), 256>>>(u0, nullptr, nullptr, f_in_w, nullptr, zx0, 648, 128, 0, 0);
    gemm_k<<<dim3(MT, 6), 256>>>(u1, nullptr, nullptr, b_in_w, nullptr, zx1, 648, 128, 0, 0);

    dconv_k<<<dim3(L_ / 128, B_), 384>>>(zx0, f_cw, f_cb, f_dtb, xb0, dt0);
    dconv_k<<<dim3(L_ / 128, B_), 384>>>(zx1, b_cw, b_cb, b_dtb, xb1, dt1);

    scan1_k<<<2 * 16 * NC, 256>>>(xb0, dt0, xb1, dt1, f_Alog, f_D, b_Alog, b_D,
                                  y0, y1, p_S, p_cum);
    scan2_k<<<256, 256>>>(p_S, p_cum);
    scan3_k<<<2 * 16 * (NC - 1), 256>>>(xb0, xb1, y0, y1, p_S, p_cum);

    rmsy_k<<<BL / 8, 256>>>(y0, zx0, f_nw);
    rmsy_k<<<BL / 8, 256>>>(y1, zx1, b_nw);

    gemm_k<<<dim3(MT, 1), 256>>>(y0, nullptr, nullptr, f_ow, nullptr, yd0, 128, 256, 0, 0);
    gemm_k<<<dim3(MT, 1), 256>>>(y1, nullptr, nullptr, b_ow, nullptr, yd1, 128, 256, 0, 0);

    // fused: A-view = (yd0 + reverse(yd1)) * gate  ->  out = view @ out_w.T + out_b
    gemm_k<<<dim3(MT, 1), 256>>>(yd0, yd1, p_gate, out_w, out_b, u1, 128, 128, 3, 0);

    final_k<<<BL / 8, 256>>>(x, u1, norm_w, (float*)d_out);
}

// round 7
// speedup vs baseline: 3.8307x; 1.0717x over previous
#include <cuda_runtime.h>
#include <math.h>

#define B_   16
#define L_   8192
#define DM   128
#define DI   256
#define NH   8
#define HD   32
#define DST  64
#define CDIM 384
#define DPRJ 648
#define BL   (B_*L_)   /* 131072 */
#define QC   128       /* scan chunk length */
#define NC   (L_/QC)   /* 64 chunks */
#define TS   8         /* scan1 smem tile steps */
#define NT   (QC/TS)
#define TS3  16        /* scan3 smem tile steps */
#define NT3  (QC/TS3)

// gemm pipeline config
#define STG   3
#define SROW  36                       /* floats per smem row (32 + pad) */
#define SMAT  (128*SROW)               /* floats per matrix per stage */
#define SMEM_GEMM (STG*2*SMAT*4)       /* 110592 bytes */

// ---------------- scratch (static device globals; no allocation) ----------
__device__ float g_gate[BL*DM];
__device__ float g_u[2][(size_t)BL*DM];
__device__ float g_zx[2][(size_t)BL*DPRJ];
__device__ float g_xBC[2][(size_t)BL*CDIM];
__device__ float g_dt[2][(size_t)BL*NH];
__device__ float g_y[2][(size_t)BL*DI];
__device__ float g_ydir[2][(size_t)BL*DM];
__device__ float g_Wf[2][DM*3*DM];
__device__ float g_bf[2][DM];
__device__ float g_S[(size_t)2*16*8*NC*2048];
__device__ float g_cum[(size_t)2*16*8*L_];
__device__ float g_xt[(size_t)BL*DM];          // tf32-rounded x
__device__ float g_Wt[300000];                 // tf32-rounded weight copies

__device__ __forceinline__ float sigm(float v) { return 1.f / (1.f + __expf(-v)); }

__device__ __forceinline__ float tf32f(float v) {
    unsigned r;
    asm("cvt.rna.tf32.f32 %0, %1;" : "=r"(r) : "f"(v));
    return __uint_as_float(r);
}

typedef unsigned long long u64;
__device__ __forceinline__ u64 splat2(float v) {
    u64 r; asm("mov.b64 %0, {%1, %1};" : "=l"(r) : "f"(v)); return r;
}
__device__ __forceinline__ u64 mul2(u64 a, u64 b) {
    u64 d; asm("mul.rn.f32x2 %0, %1, %2;" : "=l"(d) : "l"(a), "l"(b)); return d;
}
__device__ __forceinline__ void fma2acc(u64& d, u64 a, u64 b) {
    asm("fma.rn.f32x2 %0, %1, %2, %0;" : "+l"(d) : "l"(a), "l"(b));
}
__device__ __forceinline__ u64 add2(u64 a, u64 b) {
    u64 d; asm("add.rn.f32x2 %0, %1, %2;" : "=l"(d) : "l"(a), "l"(b)); return d;
}
__device__ __forceinline__ float sum2(u64 v) {
    float lo, hi; asm("mov.b64 {%0, %1}, %2;" : "=f"(lo), "=f"(hi) : "l"(v)); return lo + hi;
}

__device__ __forceinline__ void cpa16(unsigned dst, const void* src, int srcsize) {
    asm volatile("cp.async.cg.shared.global [%0], [%1], 16, %2;\n"
                 :: "r"(dst), "l"(src), "r"(srcsize));
}
__device__ __forceinline__ void cpa_commit() {
    asm volatile("cp.async.commit_group;\n" ::: "memory");
}
template<int NN> __device__ __forceinline__ void cpa_wait() {
    asm volatile("cp.async.wait_group %0;\n" :: "n"(NN) : "memory");
}

// ---------------- round a buffer to tf32 -----------------------------------
__global__ void round_k(const float* __restrict__ in, float* __restrict__ out, size_t n)
{
    size_t i = ((size_t)blockIdx.x * blockDim.x + threadIdx.x) * 4;
    if (i >= n) return;
    float4 v = *reinterpret_cast<const float4*>(in + i);
    v.x = tf32f(v.x); v.y = tf32f(v.y); v.z = tf32f(v.z); v.w = tf32f(v.w);
    *reinterpret_cast<float4*>(out + i) = v;
}

// ---------------- weight prep: E[dir][o, s*128+i] = lin@convw (+lin at s==1)
__global__ void prep_w_k(const float* __restrict__ flw, const float* __restrict__ fcw,
                         const float* __restrict__ blw, const float* __restrict__ bcw,
                         float* __restrict__ w0, float* __restrict__ w1)
{
    int idx = blockIdx.x * blockDim.x + threadIdx.x;
    if (idx >= 2 * 128 * 384) return;
    int dir = idx / (128 * 384);
    int rem = idx % (128 * 384);
    int o = rem / 384, kk = rem % 384;
    int s = kk >> 7, i = kk & 127;
    const float* lw = dir ? blw : flw;
    const float* cw = dir ? bcw : fcw;
    float acc = (s == 1) ? lw[o * 128 + i] : 0.f;
    #pragma unroll 4
    for (int j = 0; j < 128; j++)
        acc = fmaf(lw[o * 128 + j], cw[j * 384 + i * 3 + s], acc);
    (dir ? w1 : w0)[o * 384 + kk] = tf32f(acc);
}

__global__ void prep_b_k(const float* __restrict__ flb, const float* __restrict__ fcb,
                         const float* __restrict__ blb, const float* __restrict__ bcb,
                         const float* __restrict__ flw, const float* __restrict__ blw,
                         float* __restrict__ b0, float* __restrict__ b1)
{
    int t = threadIdx.x;
    int dir = t >> 7, o = t & 127;
    const float* lb = dir ? blb : flb;
    const float* cb = dir ? bcb : fcb;
    const float* lw = dir ? blw : flw;
    float acc = lb[o];
    for (int j = 0; j < 128; j++) acc = fmaf(lw[o * 128 + j], cb[j], acc);
    (dir ? b1 : b0)[o] = acc;
}

// ---------------- tf32 GEMM, cp.async 3-stage pipeline, BK=32 --------------
// C[M,N] = act(A @ W^T + bias). A and W MUST be tf32-rounded fp32.
// mode 0: plain A. mode 1/2: conv3 view of x (fwd/rev).
__global__ __launch_bounds__(256, 2) void gemm_k(
    const float* __restrict__ A, const float* __restrict__ W,
    const float* __restrict__ bias, float* __restrict__ C,
    int N, int K, int mode, int act, int rnd)
{
    extern __shared__ float sm[];
    int tid = threadIdx.x;
    int lane = tid & 31, warp = tid >> 5;
    int wm = warp & 1, wn = warp >> 1;
    int bm = blockIdx.x << 7, bn = blockIdx.y << 7;
    int rl = lane >> 2, cl = lane & 3;

    unsigned smbase = (unsigned)__cvta_generic_to_shared(sm);

    float acc[4][4][4];
    #pragma unroll
    for (int a = 0; a < 4; a++)
        #pragma unroll
        for (int b = 0; b < 4; b++)
            #pragma unroll
            for (int e = 0; e < 4; e++) acc[a][b][e] = 0.f;

    const int NIT = K >> 5;

    auto issue = [&](int it) {
        int stg = it % STG;
        unsigned abase = smbase + (unsigned)(stg * 2 * SMAT) * 4u;
        unsigned bbase = abase + (unsigned)SMAT * 4u;
        int k0 = it << 5;
        #pragma unroll
        for (int j = 0; j < 4; j++) {
            int chunk = tid + (j << 8);
            int row = chunk >> 3, cid = chunk & 7;
            int kk = k0 + (cid << 2);
            unsigned dA = abase + (unsigned)(row * SROW + (cid << 2)) * 4u;
            if (mode == 0) {
                cpa16(dA, A + (size_t)(bm + row) * K + kk, 16);
            } else {
                int m = bm + row;
                int b = m >> 13, l = m & (L_ - 1);
                int s = kk >> 7, i = kk & 127;
                int ls = l + s - 1;
                int ok = (ls >= 0 && ls < L_);
                int lsrc = (mode == 2) ? (L_ - 1 - ls) : ls;
                if (!ok) lsrc = 0;
                cpa16(dA, A + ((size_t)b * L_ + lsrc) * DM + i, ok ? 16 : 0);
            }
            int n = bn + row;
            unsigned dB = bbase + (unsigned)(row * SROW + (cid << 2)) * 4u;
            cpa16(dB, W + (size_t)(n < N ? n : 0) * K + kk, (n < N) ? 16 : 0);
        }
        cpa_commit();
    };

    issue(0);
    issue(1);

    for (int it = 0; it < NIT; it++) {
        if (it < NIT - 1) cpa_wait<1>(); else cpa_wait<0>();
        __syncthreads();
        if (it + 2 < NIT) issue(it + 2);

        int stg = it % STG;
        const float* As = sm + stg * 2 * SMAT;
        const float* Bs = As + SMAT;
        #pragma unroll
        for (int ks = 0; ks < 4; ks++) {
            int kb = ks << 3;
            unsigned bf[4][2];
            #pragma unroll
            for (int tn = 0; tn < 4; tn++) {
                int n = wn * 32 + tn * 8 + rl;
                bf[tn][0] = __float_as_uint(Bs[n * SROW + kb + cl]);
                bf[tn][1] = __float_as_uint(Bs[n * SROW + kb + cl + 4]);
            }
            unsigned af[4][4];
            #pragma unroll
            for (int tm = 0; tm < 4; tm++) {
                int m = wm * 64 + tm * 16 + rl;
                af[tm][0] = __float_as_uint(As[m * SROW + kb + cl]);
                af[tm][1] = __float_as_uint(As[(m + 8) * SROW + kb + cl]);
                af[tm][2] = __float_as_uint(As[m * SROW + kb + cl + 4]);
                af[tm][3] = __float_as_uint(As[(m + 8) * SROW + kb + cl + 4]);
            }
            #pragma unroll
            for (int tm = 0; tm < 4; tm++)
                #pragma unroll
                for (int tn = 0; tn < 4; tn++)
                    asm volatile(
                        "mma.sync.aligned.m16n8k8.row.col.f32.tf32.tf32.f32 "
                        "{%0,%1,%2,%3}, {%4,%5,%6,%7}, {%8,%9}, {%0,%1,%2,%3};"
                        : "+f"(acc[tm][tn][0]), "+f"(acc[tm][tn][1]),
                          "+f"(acc[tm][tn][2]), "+f"(acc[tm][tn][3])
                        : "r"(af[tm][0]), "r"(af[tm][1]), "r"(af[tm][2]), "r"(af[tm][3]),
                          "r"(bf[tn][0]), "r"(bf[tn][1]));
        }
    }

    #pragma unroll
    for (int tm = 0; tm < 4; tm++) {
        int m0 = bm + wm * 64 + tm * 16 + rl;
        #pragma unroll
        for (int tn = 0; tn < 4; tn++) {
            int n0 = bn + wn * 32 + tn * 8 + cl * 2;
            #pragma unroll
            for (int e = 0; e < 4; e++) {
                int m = m0 + ((e >> 1) << 3);
                int n = n0 + (e & 1);
                if (n < N) {
                    float v = acc[tm][tn][e];
                    if (bias) v += bias[n];
                    if (act == 1) v *= sigm(v);
                    if (rnd) v = tf32f(v);
                    C[(size_t)m * N + n] = v;
                }
            }
        }
    }
}

// ---------------- depthwise causal conv4 + silu on xBC, and softplus dt ----
__global__ void dconv_k(const float* __restrict__ zx, const float* __restrict__ cw,
                        const float* __restrict__ cb, const float* __restrict__ dtb,
                        float* __restrict__ xBC, float* __restrict__ dto)
{
    int b = blockIdx.y;
    int l0 = blockIdx.x << 7;
    int c = threadIdx.x;
    const float* src = zx + (size_t)b * L_ * DPRJ + 256 + c;
    float k0 = cw[c * 4 + 0], k1 = cw[c * 4 + 1], k2 = cw[c * 4 + 2], k3 = cw[c * 4 + 3];
    float bias = cb[c];
    float xm3, xm2, xm1;
    if (l0 == 0) { xm3 = 0.f; xm2 = 0.f; xm1 = 0.f; }
    else {
        xm3 = src[(size_t)(l0 - 3) * DPRJ];
        xm2 = src[(size_t)(l0 - 2) * DPRJ];
        xm1 = src[(size_t)(l0 - 1) * DPRJ];
    }
    float dbias = (c < NH) ? dtb[c] : 0.f;
    #pragma unroll 4
    for (int t = 0; t < 128; t++) {
        int l = l0 + t;
        size_t ro = (size_t)b * L_ + l;
        float xc = src[(size_t)l * DPRJ];
        float a = fmaf(k0, xm3, fmaf(k1, xm2, fmaf(k2, xm1, fmaf(k3, xc, bias))));
        xBC[ro * CDIM + c] = a * sigm(a);
        xm3 = xm2; xm2 = xm1; xm1 = xc;
        if (c < NH) {
            float v = zx[ro * DPRJ + 640 + c] + dbias;
            dto[ro * NH + c] = (v > 15.f) ? v : log1pf(__expf(v));
        }
    }
}

// ======================= chunked SSM scan (one CTA per dir,b,chunk) =======
__global__ __launch_bounds__(256, 2) void scan1_k(
    const float* __restrict__ xBC0, const float* __restrict__ dt0,
    const float* __restrict__ xBC1, const float* __restrict__ dt1,
    const float* __restrict__ Al0, const float* __restrict__ D0,
    const float* __restrict__ Al1, const float* __restrict__ D1,
    float* __restrict__ y0, float* __restrict__ y1,
    float* __restrict__ S, float* __restrict__ cum)
{
    __shared__ float sx[2][TS][CDIM];
    __shared__ float sdt[2][TS * NH];

    int bid = blockIdx.x;
    int c   = bid & (NC - 1);
    int b   = (bid >> 6) & 15;
    int dir = bid >> 10;

    const float* xBC = dir ? xBC1 : xBC0;
    const float* dtb = dir ? dt1 : dt0;
    float* yo = dir ? y1 : y0;

    int h = threadIdx.x >> 5;
    int p = threadIdx.x & 31;

    float A  = -__expf((dir ? Al1 : Al0)[h]);
    float Dv = (dir ? D1 : D0)[h];

    const float* xbase  = xBC + ((size_t)b * L_ + (size_t)c * QC) * CDIM;
    const float* dtbase = dtb + ((size_t)b * L_ + (size_t)c * QC) * NH;
    float* ybase = yo + ((size_t)b * L_ + (size_t)c * QC) * DI + h * HD + p;
    float* cumh  = cum + (((size_t)dir * 16 + b) * 8 + h) * L_ + (size_t)c * QC;

    u64 s2[32];
    #pragma unroll
    for (int j = 0; j < 32; j++) s2[j] = 0ull;
    float cd = 1.f;

    auto load_tile = [&](int buf, int tile) {
        int l = tile * TS;
        const float4* g = reinterpret_cast<const float4*>(xbase + (size_t)(l + h) * CDIM);
        float4* sdst = reinterpret_cast<float4*>(&sx[buf][h][0]);
        #pragma unroll
        for (int k = 0; k < 3; k++) sdst[p + 32 * k] = g[p + 32 * k];
        if (threadIdx.x < (TS * NH) / 4) {
            reinterpret_cast<float4*>(&sdt[buf][0])[threadIdx.x] =
                reinterpret_cast<const float4*>(dtbase + (size_t)l * NH)[threadIdx.x];
        }
    };

    load_tile(0, 0);
    __syncthreads();

    for (int tile = 0; tile < NT; tile++) {
        int cur = tile & 1;
        if (tile + 1 < NT) load_tile(cur ^ 1, tile + 1);
        #pragma unroll
        for (int t = 0; t < TS; t++) {
            float dt = sdt[cur][t * NH + h];
            float dA = __expf(dt * A);
            cd *= dA;
            float xv = sx[cur][t][h * HD + p];
            float coef = dt * xv;
            u64 dA2 = splat2(dA), coef2 = splat2(coef);
            u64 yacc[4] = {0ull, 0ull, 0ull, 0ull};
            const float4* B4 = reinterpret_cast<const float4*>(&sx[cur][t][256]);
            const float4* C4 = reinterpret_cast<const float4*>(&sx[cur][t][320]);
            #pragma unroll
            for (int j = 0; j < 16; j++) {
                union { float4 f; u64 u[2]; } Bu, Cu;
                Bu.f = B4[j]; Cu.f = C4[j];
                u64 t0 = mul2(coef2, Bu.u[0]);
                fma2acc(t0, s2[2 * j], dA2);
                s2[2 * j] = t0;
                u64 t1 = mul2(coef2, Bu.u[1]);
                fma2acc(t1, s2[2 * j + 1], dA2);
                s2[2 * j + 1] = t1;
                fma2acc(yacc[j & 3], t0, Cu.u[0]);
                fma2acc(yacc[j & 3], t1, Cu.u[1]);
            }
            float yv = sum2(add2(add2(yacc[0], yacc[1]), add2(yacc[2], yacc[3])));
            ybase[(size_t)(tile * TS + t) * DI] = yv + Dv * xv;
            if (p == 0) cumh[tile * TS + t] = cd;
        }
        __syncthreads();
    }

    float* Sp = S + ((((size_t)dir * 16 + b) * 8 + h) * NC + c) * 2048 + p * 64;
    #pragma unroll
    for (int j = 0; j < 16; j++) {
        union { float4 f; u64 u[2]; } su;
        su.u[0] = s2[2 * j]; su.u[1] = s2[2 * j + 1];
        reinterpret_cast<float4*>(Sp)[j] = su.f;
    }
}

__global__ __launch_bounds__(256) void scan2_k(float* __restrict__ S, const float* __restrict__ cum)
{
    int bid = blockIdx.x;
    int h = bid & 7, b = (bid >> 3) & 15, dir = bid >> 7;
    float* Sb = S + (((size_t)dir * 16 + b) * 8 + h) * NC * 2048 + threadIdx.x * 8;
    const float* cumh = cum + (((size_t)dir * 16 + b) * 8 + h) * L_;
    float s[8];
    #pragma unroll
    for (int j = 0; j < 8; j++) s[j] = 0.f;
    for (int c = 0; c < NC; c++) {
        float* Sp = Sb + (size_t)c * 2048;
        float4 a0 = *reinterpret_cast<const float4*>(Sp);
        float4 a1 = *reinterpret_cast<const float4*>(Sp + 4);
        float Tc = cumh[(c + 1) * QC - 1];
        *reinterpret_cast<float4*>(Sp)     = make_float4(s[0], s[1], s[2], s[3]);
        *reinterpret_cast<float4*>(Sp + 4) = make_float4(s[4], s[5], s[6], s[7]);
        s[0] = fmaf(s[0], Tc, a0.x); s[1] = fmaf(s[1], Tc, a0.y);
        s[2] = fmaf(s[2], Tc, a0.z); s[3] = fmaf(s[3], Tc, a0.w);
        s[4] = fmaf(s[4], Tc, a1.x); s[5] = fmaf(s[5], Tc, a1.y);
        s[6] = fmaf(s[6], Tc, a1.z); s[7] = fmaf(s[7], Tc, a1.w);
    }
}

__global__ __launch_bounds__(256, 2) void scan3_k(
    const float* __restrict__ xBC0, const float* __restrict__ xBC1,
    float* __restrict__ y0, float* __restrict__ y1,
    const float* __restrict__ S, const float* __restrict__ cum)
{
    __shared__ float sc[2][TS3][64];

    int bid = blockIdx.x;
    int c    = bid % (NC - 1) + 1;
    int rest = bid / (NC - 1);
    int b = rest & 15, dir = rest >> 4;

    const float* xBC = dir ? xBC1 : xBC0;
    float* yo = dir ? y1 : y0;

    int h = threadIdx.x >> 5;
    int p = threadIdx.x & 31;

    const float* Sp = S + ((((size_t)dir * 16 + b) * 8 + h) * NC + c) * 2048 + p * 64;
    u64 s02[32];
    #pragma unroll
    for (int j = 0; j < 16; j++) {
        union { float4 f; u64 u[2]; } su;
        su.f = reinterpret_cast<const float4*>(Sp)[j];
        s02[2 * j] = su.u[0]; s02[2 * j + 1] = su.u[1];
    }

    const float* cbase = xBC + ((size_t)b * L_ + (size_t)c * QC) * CDIM + 320;
    const float* cumh  = cum + (((size_t)dir * 16 + b) * 8 + h) * L_ + (size_t)c * QC;
    float* ybase = yo + ((size_t)b * L_ + (size_t)c * QC) * DI + h * HD + p;

    auto load_tile = [&](int buf, int tile) {
        int l = tile * TS3;
        int row = threadIdx.x >> 4, f4 = threadIdx.x & 15;
        reinterpret_cast<float4*>(&sc[buf][row][0])[f4] =
            *reinterpret_cast<const float4*>(cbase + (size_t)(l + row) * CDIM + f4 * 4);
    };

    load_tile(0, 0);
    __syncthreads();

    for (int tile = 0; tile < NT3; tile++) {
        int cur = tile & 1;
        if (tile + 1 < NT3) load_tile(cur ^ 1, tile + 1);
        #pragma unroll
        for (int t = 0; t < TS3; t++) {
            u64 yacc[4] = {0ull, 0ull, 0ull, 0ull};
            const float4* C4 = reinterpret_cast<const float4*>(&sc[cur][t][0]);
            #pragma unroll
            for (int j = 0; j < 16; j++) {
                union { float4 f; u64 u[2]; } Cu;
                Cu.f = C4[j];
                fma2acc(yacc[j & 3], s02[2 * j], Cu.u[0]);
                fma2acc(yacc[j & 3], s02[2 * j + 1], Cu.u[1]);
            }
            float dot = sum2(add2(add2(yacc[0], yacc[1]), add2(yacc[2], yacc[3])));
            int l = tile * TS3 + t;
            float cd = __ldg(cumh + l);
            ybase[(size_t)l * DI] += cd * dot;
        }
        __syncthreads();
    }
}

// ---------------- y <- rmsnorm(y * silu(z)) * norm_w (rounded, in place) ---
__global__ void rmsy_k(float* __restrict__ y, const float* __restrict__ zx,
                       const float* __restrict__ nw)
{
    int warp = threadIdx.x >> 5, lane = threadIdx.x & 31;
    size_t row = (size_t)blockIdx.x * 8 + warp;
    float* yr = y + row * DI;
    const float* zr = zx + row * DPRJ;
    float4 y0v = *reinterpret_cast<const float4*>(yr + lane * 8);
    float4 y1v = *reinterpret_cast<const float4*>(yr + lane * 8 + 4);
    float4 z0v = *reinterpret_cast<const float4*>(zr + lane * 8);
    float4 z1v = *reinterpret_cast<const float4*>(zr + lane * 8 + 4);
    float v[8];
    v[0] = y0v.x * (z0v.x * sigm(z0v.x));
    v[1] = y0v.y * (z0v.y * sigm(z0v.y));
    v[2] = y0v.z * (z0v.z * sigm(z0v.z));
    v[3] = y0v.w * (z0v.w * sigm(z0v.w));
    v[4] = y1v.x * (z1v.x * sigm(z1v.x));
    v[5] = y1v.y * (z1v.y * sigm(z1v.y));
    v[6] = y1v.z * (z1v.z * sigm(z1v.z));
    v[7] = y1v.w * (z1v.w * sigm(z1v.w));
    float ss = 0.f;
    #pragma unroll
    for (int j = 0; j < 8; j++) ss = fmaf(v[j], v[j], ss);
    #pragma unroll
    for (int o = 16; o; o >>= 1) ss += __shfl_xor_sync(0xffffffffu, ss, o);
    float r = rsqrtf(ss * (1.f / 256.f) + 1e-5f);
    float4 w0 = *reinterpret_cast<const float4*>(nw + lane * 8);
    float4 w1 = *reinterpret_cast<const float4*>(nw + lane * 8 + 4);
    float4 o0, o1;
    o0.x = tf32f(v[0] * r * w0.x); o0.y = tf32f(v[1] * r * w0.y);
    o0.z = tf32f(v[2] * r * w0.z); o0.w = tf32f(v[3] * r * w0.w);
    o1.x = tf32f(v[4] * r * w1.x); o1.y = tf32f(v[5] * r * w1.y);
    o1.z = tf32f(v[6] * r * w1.z); o1.w = tf32f(v[7] * r * w1.w);
    *reinterpret_cast<float4*>(yr + lane * 8)     = o0;
    *reinterpret_cast<float4*>(yr + lane * 8 + 4) = o1;
}

// ---------------- e = tf32round((yf + reverse(yb)) * gate) -----------------
__global__ void combine_k(const float* __restrict__ yf, const float* __restrict__ yb,
                          const float* __restrict__ gate, float* __restrict__ e)
{
    size_t i = (size_t)blockIdx.x * blockDim.x + threadIdx.x;
    if (i >= (size_t)BL * 32) return;
    size_t row = i >> 5; int c4 = (int)(i & 31);
    size_t b = row >> 13; int l = (int)(row & (L_ - 1));
    size_t rowb = (b << 13) + (size_t)(L_ - 1 - l);
    float4 a  = reinterpret_cast<const float4*>(yf)[row * 32 + c4];
    float4 bb = reinterpret_cast<const float4*>(yb)[rowb * 32 + c4];
    float4 g  = reinterpret_cast<const float4*>(gate)[row * 32 + c4];
    float4 o;
    o.x = tf32f((a.x + bb.x) * g.x); o.y = tf32f((a.y + bb.y) * g.y);
    o.z = tf32f((a.z + bb.z) * g.z); o.w = tf32f((a.w + bb.w) * g.w);
    reinterpret_cast<float4*>(e)[row * 32 + c4] = o;
}

// ---------------- out = x + rmsnorm(o, norm_w) ------------------------------
__global__ void final_k(const float* __restrict__ x, const float* __restrict__ o,
                        const float* __restrict__ nw, float* __restrict__ outp)
{
    int warp = threadIdx.x >> 5, lane = threadIdx.x & 31;
    size_t row = (size_t)blockIdx.x * 8 + warp;
    float4 v = *reinterpret_cast<const float4*>(o + row * DM + lane * 4);
    float ss = v.x * v.x + v.y * v.y + v.z * v.z + v.w * v.w;
    #pragma unroll
    for (int s = 16; s; s >>= 1) ss += __shfl_xor_sync(0xffffffffu, ss, s);
    float r = rsqrtf(ss * (1.f / 128.f) + 1e-5f);
    float4 xv = *reinterpret_cast<const float4*>(x + row * DM + lane * 4);
    float4 w  = *reinterpret_cast<const float4*>(nw + lane * 4);
    float4 res;
    res.x = xv.x + v.x * r * w.x; res.y = xv.y + v.y * r * w.y;
    res.z = xv.z + v.z * r * w.z; res.w = xv.w + v.w * r * w.w;
    *reinterpret_cast<float4*>(outp + row * DM + lane * 4) = res;
}

// ---------------- launch ----------------------------------------------------
extern "C" void kernel_launch(void* const* d_in, const int* in_sizes, int n_in,
                              void* d_out, int out_size)
{
    const float* x       = (const float*)d_in[0];
    const float* gate_w  = (const float*)d_in[1];
    const float* gate_b  = (const float*)d_in[2];
    const float* fconv_w = (const float*)d_in[3];
    const float* fconv_b = (const float*)d_in[4];
    const float* flin_w  = (const float*)d_in[5];
    const float* flin_b  = (const float*)d_in[6];
    const float* f_in_w  = (const float*)d_in[7];
    const float* f_cw    = (const float*)d_in[8];
    const float* f_cb    = (const float*)d_in[9];
    const float* f_dtb   = (const float*)d_in[10];
    const float* f_Alog  = (const float*)d_in[11];
    const float* f_D     = (const float*)d_in[12];
    const float* f_nw    = (const float*)d_in[13];
    const float* f_ow    = (const float*)d_in[14];
    const float* bconv_w = (const float*)d_in[15];
    const float* bconv_b = (const float*)d_in[16];
    const float* blin_w  = (const float*)d_in[17];
    const float* blin_b  = (const float*)d_in[18];
    const float* b_in_w  = (const float*)d_in[19];
    const float* b_cw    = (const float*)d_in[20];
    const float* b_cb    = (const float*)d_in[21];
    const float* b_dtb   = (const float*)d_in[22];
    const float* b_Alog  = (const float*)d_in[23];
    const float* b_D     = (const float*)d_in[24];
    const float* b_nw    = (const float*)d_in[25];
    const float* b_ow    = (const float*)d_in[26];
    const float* out_w   = (const float*)d_in[27];
    const float* out_b   = (const float*)d_in[28];
    const float* norm_w  = (const float*)d_in[29];

    float *p_gate, *p_u, *p_zx, *p_xBC, *p_dt, *p_y, *p_ydir, *p_Wf, *p_bf, *p_S, *p_cum, *p_xt, *p_Wt;
    cudaGetSymbolAddress((void**)&p_gate, g_gate);
    cudaGetSymbolAddress((void**)&p_u,    g_u);
    cudaGetSymbolAddress((void**)&p_zx,   g_zx);
    cudaGetSymbolAddress((void**)&p_xBC,  g_xBC);
    cudaGetSymbolAddress((void**)&p_dt,   g_dt);
    cudaGetSymbolAddress((void**)&p_y,    g_y);
    cudaGetSymbolAddress((void**)&p_ydir, g_ydir);
    cudaGetSymbolAddress((void**)&p_Wf,   g_Wf);
    cudaGetSymbolAddress((void**)&p_bf,   g_bf);
    cudaGetSymbolAddress((void**)&p_S,    g_S);
    cudaGetSymbolAddress((void**)&p_cum,  g_cum);
    cudaGetSymbolAddress((void**)&p_xt,   g_xt);
    cudaGetSymbolAddress((void**)&p_Wt,   g_Wt);

    float* u0   = p_u;                 float* u1   = p_u   + (size_t)BL * DM;
    float* zx0  = p_zx;                float* zx1  = p_zx  + (size_t)BL * DPRJ;
    float* xb0  = p_xBC;               float* xb1  = p_xBC + (size_t)BL * CDIM;
    float* dt0  = p_dt;                float* dt1  = p_dt  + (size_t)BL * NH;
    float* y0   = p_y;                 float* y1   = p_y   + (size_t)BL * DI;
    float* yd0  = p_ydir;              float* yd1  = p_ydir + (size_t)BL * DM;
    float* Wf0  = p_Wf;                float* Wf1  = p_Wf  + DM * 3 * DM;
    float* bf0  = p_bf;                float* bf1  = p_bf  + DM;

    // tf32 weight copies
    float* Wt_gate = p_Wt;                       // 128*128
    float* Wt_fin  = Wt_gate + 128 * 128;        // 648*128
    float* Wt_bin  = Wt_fin  + 648 * 128;        // 648*128
    float* Wt_fow  = Wt_bin  + 648 * 128;        // 128*256
    float* Wt_bow  = Wt_fow  + 128 * 256;        // 128*256
    float* Wt_out  = Wt_bow  + 128 * 256;        // 128*128

    const int MT = BL / 128;

    cudaFuncSetAttribute(gemm_k, cudaFuncAttributeMaxDynamicSharedMemorySize, SMEM_GEMM);

    // one-time rounding of GEMM inputs
    round_k<<<(BL * DM / 4 + 255) / 256, 256>>>(x, p_xt, (size_t)BL * DM);
    round_k<<<(128 * 128 / 4 + 255) / 256, 256>>>(gate_w, Wt_gate, 128 * 128);
    round_k<<<(648 * 128 / 4 + 255) / 256, 256>>>(f_in_w, Wt_fin, 648 * 128);
    round_k<<<(648 * 128 / 4 + 255) / 256, 256>>>(b_in_w, Wt_bin, 648 * 128);
    round_k<<<(128 * 256 / 4 + 255) / 256, 256>>>(f_ow, Wt_fow, 128 * 256);
    round_k<<<(128 * 256 / 4 + 255) / 256, 256>>>(b_ow, Wt_bow, 128 * 256);
    round_k<<<(128 * 128 / 4 + 255) / 256, 256>>>(out_w, Wt_out, 128 * 128);

    prep_w_k<<<384, 256>>>(flin_w, fconv_w, blin_w, bconv_w, Wf0, Wf1);
    prep_b_k<<<1, 256>>>(flin_b, fconv_b, blin_b, bconv_b, flin_w, blin_w, bf0, bf1);

    // gate = silu(x @ gate_w.T + gate_b)
    gemm_k<<<dim3(MT, 1), 256, SMEM_GEMM>>>(p_xt, Wt_gate, gate_b, p_gate, 128, 128, 0, 1, 0);

    // front: u = (x + conv3(x)) @ lin.T + bias (conv view), output rounded
    gemm_k<<<dim3(MT, 1), 256, SMEM_GEMM>>>(p_xt, Wf0, bf0, u0, 128, 384, 1, 0, 1);
    gemm_k<<<dim3(MT, 1), 256, SMEM_GEMM>>>(p_xt, Wf1, bf1, u1, 128, 384, 2, 0, 1);

    // in_proj
    gemm_k<<<dim3(MT, 6), 256, SMEM_GEMM>>>(u0, Wt_fin, nullptr, zx0, 648, 128, 0, 0, 0);
    gemm_k<<<dim3(MT, 6), 256, SMEM_GEMM>>>(u1, Wt_bin, nullptr, zx1, 648, 128, 0, 0, 0);

    dconv_k<<<dim3(L_ / 128, B_), 384>>>(zx0, f_cw, f_cb, f_dtb, xb0, dt0);
    dconv_k<<<dim3(L_ / 128, B_), 384>>>(zx1, b_cw, b_cb, b_dtb, xb1, dt1);

    scan1_k<<<2 * 16 * NC, 256>>>(xb0, dt0, xb1, dt1, f_Alog, f_D, b_Alog, b_D,
                                  y0, y1, p_S, p_cum);
    scan2_k<<<256, 256>>>(p_S, p_cum);
    scan3_k<<<2 * 16 * (NC - 1), 256>>>(xb0, xb1, y0, y1, p_S, p_cum);

    rmsy_k<<<BL / 8, 256>>>(y0, zx0, f_nw);
    rmsy_k<<<BL / 8, 256>>>(y1, zx1, b_nw);

    gemm_k<<<dim3(MT, 1), 256, SMEM_GEMM>>>(y0, Wt_fow, nullptr, yd0, 128, 256, 0, 0, 0);
    gemm_k<<<dim3(MT, 1), 256, SMEM_GEMM>>>(y1, Wt_bow, nullptr, yd1, 128, 256, 0, 0, 0);

    // e = round((yf + reverse(yb)) * gate) into u0
    combine_k<<<(BL * 32) / 256, 256>>>(yd0, yd1, p_gate, u0);

    gemm_k<<<dim3(MT, 1), 256, SMEM_GEMM>>>(u0, Wt_out, out_b, u1, 128, 128, 0, 0, 0);

    final_k<<<BL / 8, 256>>>(x, u1, norm_w, (float*)d_out);
}

// round 8
// speedup vs baseline: 4.2108x; 1.0992x over previous
#include <cuda_runtime.h>
#include <math.h>

#define B_   16
#define L_   8192
#define DM   128
#define DI   256
#define NH   8
#define HD   32
#define DST  64
#define CDIM 384
#define DPRJ 648
#define BL   (B_*L_)   /* 131072 */
#define QC   128       /* scan chunk length */
#define NC   (L_/QC)   /* 64 chunks */
#define TS   8         /* scan1 smem tile steps */
#define NT   (QC/TS)
#define TS3  16        /* scan3 smem tile steps */
#define NT3  (QC/TS3)
#define RW   (TS+3)    /* raw rows per scan1 tile (3 halo) */
#define RCOL 392       /* zx cols 256..647 */

// gemm pipeline config
#define STG   3
#define SROW  36
#define SMAT  (128*SROW)
#define SMEM_GEMM (STG*2*SMAT*4)       /* 110592 bytes */

// scan1 dynamic smem (floats)
#define S1_RAW  (2*RW*RCOL)            /* 8624 */
#define S1_SX   (2*TS*384)             /* 6144 */
#define S1_SDT  (2*TS*NH)              /* 128 */
#define S1_WT   (384*4)                /* 1536 */
#define S1_SB   384
#define S1_DTB  8
#define SMEM_SCAN1 ((S1_RAW+S1_SX+S1_SDT+S1_WT+S1_SB+S1_DTB)*4)

// ---------------- scratch (static device globals; no allocation) ----------
__device__ float g_gate[BL*DM];
__device__ float g_u[2][(size_t)BL*DM];
__device__ float g_zx[2][(size_t)BL*DPRJ];
__device__ float g_y[2][(size_t)BL*DI];
__device__ float g_ydir[2][(size_t)BL*DM];
__device__ float g_Wf[2][DM*3*DM];
__device__ float g_bf[2][DM];
__device__ float g_S[(size_t)2*16*8*NC*2048];
__device__ float g_cum[(size_t)2*16*8*L_];
__device__ float g_C[(size_t)2*BL*64];         // compact conv'd C columns
__device__ float g_xt[(size_t)BL*DM];          // tf32-rounded x
__device__ float g_Wt[300000];                 // tf32-rounded weight copies

__device__ __forceinline__ float sigm(float v) { return 1.f / (1.f + __expf(-v)); }

__device__ __forceinline__ float tf32f(float v) {
    unsigned r;
    asm("cvt.rna.tf32.f32 %0, %1;" : "=r"(r) : "f"(v));
    return __uint_as_float(r);
}

typedef unsigned long long u64;
__device__ __forceinline__ u64 splat2(float v) {
    u64 r; asm("mov.b64 %0, {%1, %1};" : "=l"(r) : "f"(v)); return r;
}
__device__ __forceinline__ u64 mul2(u64 a, u64 b) {
    u64 d; asm("mul.rn.f32x2 %0, %1, %2;" : "=l"(d) : "l"(a), "l"(b)); return d;
}
__device__ __forceinline__ void fma2acc(u64& d, u64 a, u64 b) {
    asm("fma.rn.f32x2 %0, %1, %2, %0;" : "+l"(d) : "l"(a), "l"(b));
}
__device__ __forceinline__ u64 add2(u64 a, u64 b) {
    u64 d; asm("add.rn.f32x2 %0, %1, %2;" : "=l"(d) : "l"(a), "l"(b)); return d;
}
__device__ __forceinline__ float sum2(u64 v) {
    float lo, hi; asm("mov.b64 {%0, %1}, %2;" : "=f"(lo), "=f"(hi) : "l"(v)); return lo + hi;
}

__device__ __forceinline__ void cpa16(unsigned dst, const void* src, int srcsize) {
    asm volatile("cp.async.cg.shared.global [%0], [%1], 16, %2;\n"
                 :: "r"(dst), "l"(src), "r"(srcsize));
}
__device__ __forceinline__ void cpa_commit() {
    asm volatile("cp.async.commit_group;\n" ::: "memory");
}
template<int NN> __device__ __forceinline__ void cpa_wait() {
    asm volatile("cp.async.wait_group %0;\n" :: "n"(NN) : "memory");
}

// ---------------- round a buffer to tf32 -----------------------------------
__global__ void round_k(const float* __restrict__ in, float* __restrict__ out, size_t n)
{
    size_t i = ((size_t)blockIdx.x * blockDim.x + threadIdx.x) * 4;
    if (i >= n) return;
    float4 v = *reinterpret_cast<const float4*>(in + i);
    v.x = tf32f(v.x); v.y = tf32f(v.y); v.z = tf32f(v.z); v.w = tf32f(v.w);
    *reinterpret_cast<float4*>(out + i) = v;
}

// ---------------- weight prep: E[dir][o, s*128+i] = lin@convw (+lin at s==1)
__global__ void prep_w_k(const float* __restrict__ flw, const float* __restrict__ fcw,
                         const float* __restrict__ blw, const float* __restrict__ bcw,
                         float* __restrict__ w0, float* __restrict__ w1)
{
    int idx = blockIdx.x * blockDim.x + threadIdx.x;
    if (idx >= 2 * 128 * 384) return;
    int dir = idx / (128 * 384);
    int rem = idx % (128 * 384);
    int o = rem / 384, kk = rem % 384;
    int s = kk >> 7, i = kk & 127;
    const float* lw = dir ? blw : flw;
    const float* cw = dir ? bcw : fcw;
    float acc = (s == 1) ? lw[o * 128 + i] : 0.f;
    #pragma unroll 4
    for (int j = 0; j < 128; j++)
        acc = fmaf(lw[o * 128 + j], cw[j * 384 + i * 3 + s], acc);
    (dir ? w1 : w0)[o * 384 + kk] = tf32f(acc);
}

__global__ void prep_b_k(const float* __restrict__ flb, const float* __restrict__ fcb,
                         const float* __restrict__ blb, const float* __restrict__ bcb,
                         const float* __restrict__ flw, const float* __restrict__ blw,
                         float* __restrict__ b0, float* __restrict__ b1)
{
    int t = threadIdx.x;
    int dir = t >> 7, o = t & 127;
    const float* lb = dir ? blb : flb;
    const float* cb = dir ? bcb : fcb;
    const float* lw = dir ? blw : flw;
    float acc = lb[o];
    for (int j = 0; j < 128; j++) acc = fmaf(lw[o * 128 + j], cb[j], acc);
    (dir ? b1 : b0)[o] = acc;
}

// ---------------- tf32 GEMM, cp.async 3-stage pipeline, BK=32 --------------
// C[M,N] = act(A @ W^T + bias). A and W MUST be tf32-rounded fp32.
// mode 0: plain A. mode 1/2: conv3 view of x (fwd/rev).
// xres != null: fused final epilogue out = xres + rmsnorm(C_row)*nw (needs N==128).
__global__ __launch_bounds__(256, 2) void gemm_k(
    const float* __restrict__ A, const float* __restrict__ W,
    const float* __restrict__ bias, float* __restrict__ C,
    int N, int K, int mode, int act, int rnd,
    const float* __restrict__ xres, const float* __restrict__ nwp)
{
    extern __shared__ float sm[];
    int tid = threadIdx.x;
    int lane = tid & 31, warp = tid >> 5;
    int wm = warp & 1, wn = warp >> 1;
    int bm = blockIdx.x << 7, bn = blockIdx.y << 7;
    int rl = lane >> 2, cl = lane & 3;

    unsigned smbase = (unsigned)__cvta_generic_to_shared(sm);

    float acc[4][4][4];
    #pragma unroll
    for (int a = 0; a < 4; a++)
        #pragma unroll
        for (int b = 0; b < 4; b++)
            #pragma unroll
            for (int e = 0; e < 4; e++) acc[a][b][e] = 0.f;

    const int NIT = K >> 5;

    auto issue = [&](int it) {
        int stg = it % STG;
        unsigned abase = smbase + (unsigned)(stg * 2 * SMAT) * 4u;
        unsigned bbase = abase + (unsigned)SMAT * 4u;
        int k0 = it << 5;
        #pragma unroll
        for (int j = 0; j < 4; j++) {
            int chunk = tid + (j << 8);
            int row = chunk >> 3, cid = chunk & 7;
            int kk = k0 + (cid << 2);
            unsigned dA = abase + (unsigned)(row * SROW + (cid << 2)) * 4u;
            if (mode == 0) {
                cpa16(dA, A + (size_t)(bm + row) * K + kk, 16);
            } else {
                int m = bm + row;
                int b = m >> 13, l = m & (L_ - 1);
                int s = kk >> 7, i = kk & 127;
                int ls = l + s - 1;
                int ok = (ls >= 0 && ls < L_);
                int lsrc = (mode == 2) ? (L_ - 1 - ls) : ls;
                if (!ok) lsrc = 0;
                cpa16(dA, A + ((size_t)b * L_ + lsrc) * DM + i, ok ? 16 : 0);
            }
            int n = bn + row;
            unsigned dB = bbase + (unsigned)(row * SROW + (cid << 2)) * 4u;
            cpa16(dB, W + (size_t)(n < N ? n : 0) * K + kk, (n < N) ? 16 : 0);
        }
        cpa_commit();
    };

    issue(0);
    issue(1);

    for (int it = 0; it < NIT; it++) {
        if (it < NIT - 1) cpa_wait<1>(); else cpa_wait<0>();
        __syncthreads();
        if (it + 2 < NIT) issue(it + 2);

        int stg = it % STG;
        const float* As = sm + stg * 2 * SMAT;
        const float* Bs = As + SMAT;
        #pragma unroll
        for (int ks = 0; ks < 4; ks++) {
            int kb = ks << 3;
            unsigned bf[4][2];
            #pragma unroll
            for (int tn = 0; tn < 4; tn++) {
                int n = wn * 32 + tn * 8 + rl;
                bf[tn][0] = __float_as_uint(Bs[n * SROW + kb + cl]);
                bf[tn][1] = __float_as_uint(Bs[n * SROW + kb + cl + 4]);
            }
            unsigned af[4][4];
            #pragma unroll
            for (int tm = 0; tm < 4; tm++) {
                int m = wm * 64 + tm * 16 + rl;
                af[tm][0] = __float_as_uint(As[m * SROW + kb + cl]);
                af[tm][1] = __float_as_uint(As[(m + 8) * SROW + kb + cl]);
                af[tm][2] = __float_as_uint(As[m * SROW + kb + cl + 4]);
                af[tm][3] = __float_as_uint(As[(m + 8) * SROW + kb + cl + 4]);
            }
            #pragma unroll
            for (int tm = 0; tm < 4; tm++)
                #pragma unroll
                for (int tn = 0; tn < 4; tn++)
                    asm volatile(
                        "mma.sync.aligned.m16n8k8.row.col.f32.tf32.tf32.f32 "
                        "{%0,%1,%2,%3}, {%4,%5,%6,%7}, {%8,%9}, {%0,%1,%2,%3};"
                        : "+f"(acc[tm][tn][0]), "+f"(acc[tm][tn][1]),
                          "+f"(acc[tm][tn][2]), "+f"(acc[tm][tn][3])
                        : "r"(af[tm][0]), "r"(af[tm][1]), "r"(af[tm][2]), "r"(af[tm][3]),
                          "r"(bf[tn][0]), "r"(bf[tn][1]));
        }
    }

    if (xres == nullptr) {
        #pragma unroll
        for (int tm = 0; tm < 4; tm++) {
            int m0 = bm + wm * 64 + tm * 16 + rl;
            #pragma unroll
            for (int tn = 0; tn < 4; tn++) {
                int n0 = bn + wn * 32 + tn * 8 + cl * 2;
                #pragma unroll
                for (int e = 0; e < 4; e++) {
                    int m = m0 + ((e >> 1) << 3);
                    int n = n0 + (e & 1);
                    if (n < N) {
                        float v = acc[tm][tn][e];
                        if (bias) v += bias[n];
                        if (act == 1) v *= sigm(v);
                        if (rnd) v = tf32f(v);
                        C[(size_t)m * N + n] = v;
                    }
                }
            }
        }
    } else {
        // fused: out = xres + rmsnorm(acc + bias) * nwp  (N == 128)
        __syncthreads();
        float* smC = sm;  // 128 x 132
        #pragma unroll
        for (int tm = 0; tm < 4; tm++) {
            int ml0 = wm * 64 + tm * 16 + rl;
            #pragma unroll
            for (int tn = 0; tn < 4; tn++) {
                int n0 = wn * 32 + tn * 8 + cl * 2;
                #pragma unroll
                for (int e = 0; e < 4; e++) {
                    int ml = ml0 + ((e >> 1) << 3);
                    int n = n0 + (e & 1);
                    smC[ml * 132 + n] = acc[tm][tn][e] + bias[n];
                }
            }
        }
        __syncthreads();
        #pragma unroll
        for (int r = 0; r < 16; r++) {
            int row = warp * 16 + r;
            const float* cr = smC + row * 132 + lane * 4;
            float4 v = make_float4(cr[0], cr[1], cr[2], cr[3]);
            float ss = v.x * v.x + v.y * v.y + v.z * v.z + v.w * v.w;
            #pragma unroll
            for (int o = 16; o; o >>= 1) ss += __shfl_xor_sync(0xffffffffu, ss, o);
            float rs = rsqrtf(ss * (1.f / 128.f) + 1e-5f);
            size_t gm = (size_t)(bm + row);
            float4 xv = *reinterpret_cast<const float4*>(xres + gm * DM + lane * 4);
            float4 w  = *reinterpret_cast<const float4*>(nwp + lane * 4);
            float4 res;
            res.x = xv.x + v.x * rs * w.x; res.y = xv.y + v.y * rs * w.y;
            res.z = xv.z + v.z * rs * w.z; res.w = xv.w + v.w * rs * w.w;
            *reinterpret_cast<float4*>(C + gm * DM + lane * 4) = res;
        }
    }
}

// ============ scan1: fused conv4+silu+softplus + local SSM scan ============
// one CTA per (dir, b, chunk); warp = head, lane = headdim p.
__global__ __launch_bounds__(256, 2) void scan1_k(
    const float* __restrict__ zx0, const float* __restrict__ zx1,
    const float* __restrict__ fcw, const float* __restrict__ fcb, const float* __restrict__ fdtb,
    const float* __restrict__ bcw, const float* __restrict__ bcb, const float* __restrict__ bdtb,
    const float* __restrict__ Al0, const float* __restrict__ D0,
    const float* __restrict__ Al1, const float* __restrict__ D1,
    float* __restrict__ y0, float* __restrict__ y1,
    float* __restrict__ S, float* __restrict__ cum, float* __restrict__ Cc)
{
    extern __shared__ float sm1[];
    float* raw  = sm1;                   // [2][RW][RCOL]
    float* sx   = raw + S1_RAW;          // [2][TS][384]
    float* sdt  = sx + S1_SX;            // [2][TS*NH]
    float* swt  = sdt + S1_SDT;          // [1536]
    float* sb   = swt + S1_WT;           // [384]
    float* sdtb = sb + S1_SB;            // [8]
    unsigned rawbase = (unsigned)__cvta_generic_to_shared(raw);

    int bid = blockIdx.x;
    int c   = bid & (NC - 1);
    int b   = (bid >> 6) & 15;
    int dir = bid >> 10;
    int tid = threadIdx.x;

    const float* zx  = dir ? zx1 : zx0;
    const float* cw  = dir ? bcw : fcw;
    const float* cb  = dir ? bcb : fcb;
    const float* dtb = dir ? bdtb : fdtb;
    float* yo = dir ? y1 : y0;

    int h = tid >> 5;
    int p = tid & 31;

    float A  = -__expf((dir ? Al1 : Al0)[h]);
    float Dv = (dir ? D1 : D0)[h];

    // preload conv weights
    for (int i = tid; i < 1536; i += 256) swt[i] = cw[i];
    for (int i = tid; i < 384; i += 256) sb[i] = cb[i];
    if (tid < 8) sdtb[tid] = dtb[tid];

    int l0 = c * QC;
    const float* zbase = zx + (size_t)b * L_ * DPRJ;
    float* ybase = yo + ((size_t)b * L_ + (size_t)l0) * DI + h * HD + p;
    float* cumh  = cum + (((size_t)dir * 16 + b) * 8 + h) * L_ + (size_t)l0;
    float* Ccb   = Cc + ((size_t)dir * BL + (size_t)b * L_ + l0) * 64;

    u64 s2[32];
    #pragma unroll
    for (int j = 0; j < 32; j++) s2[j] = 0ull;
    float cd = 1.f;

    auto issue_raw = [&](int tile, int buf) {
        int lstart = l0 + tile * TS - 3;
        #pragma unroll
        for (int k = 0; k < 5; k++) {
            int chunk = tid + (k << 8);
            if (chunk < RW * 98) {
                int r = chunk / 98, j = chunk % 98;
                int l = lstart + r;
                int ok = (l >= 0);
                unsigned d = rawbase + (unsigned)((buf * RW * RCOL + r * RCOL + j * 4) * 4);
                cpa16(d, zbase + (size_t)(ok ? l : 0) * DPRJ + 256 + j * 4, ok ? 16 : 0);
            }
        }
        cpa_commit();
    };

    issue_raw(0, 0);

    for (int tile = 0; tile < NT; tile++) {
        int cur = tile & 1;
        cpa_wait<0>();
        __syncthreads();
        if (tile + 1 < NT) issue_raw(tile + 1, cur ^ 1);

        // convert: conv4 + silu for 8 steps x 384 channels; dt softplus
        {
            const float* rb = raw + cur * RW * RCOL;
            float* sxb = sx + cur * TS * 384;
            int lt = l0 + tile * TS;
            #pragma unroll
            for (int k = 0; k < 12; k++) {
                int idx = tid + (k << 8);   // < 3072
                int t = idx / 384, cch = idx % 384;
                float xm3 = rb[t * RCOL + cch];
                float xm2 = rb[(t + 1) * RCOL + cch];
                float xm1 = rb[(t + 2) * RCOL + cch];
                float xc  = rb[(t + 3) * RCOL + cch];
                float a = fmaf(swt[cch * 4 + 0], xm3,
                          fmaf(swt[cch * 4 + 1], xm2,
                          fmaf(swt[cch * 4 + 2], xm1,
                          fmaf(swt[cch * 4 + 3], xc, sb[cch]))));
                float v = a * sigm(a);
                sxb[t * 384 + cch] = v;
                if (cch >= 320)
                    Ccb[(size_t)(tile * TS + t) * 64 + (cch - 320)] = v;
            }
            if (tid < TS * NH) {
                int t = tid >> 3, hh = tid & 7;
                float v = rb[(t + 3) * RCOL + 384 + hh] + sdtb[hh];
                sdt[cur * TS * NH + tid] = (v > 15.f) ? v : log1pf(__expf(v));
            }
        }
        __syncthreads();

        const float* sxt0 = sx + cur * TS * 384;
        #pragma unroll
        for (int t = 0; t < TS; t++) {
            float dt = sdt[cur * TS * NH + t * NH + h];
            float dA = __expf(dt * A);
            cd *= dA;
            const float* row = sxt0 + t * 384;
            float xv = row[h * HD + p];
            float coef = dt * xv;
            u64 dA2 = splat2(dA), coef2 = splat2(coef);
            u64 yacc[4] = {0ull, 0ull, 0ull, 0ull};
            const float4* B4 = reinterpret_cast<const float4*>(row + 256);
            const float4* C4 = reinterpret_cast<const float4*>(row + 320);
            #pragma unroll
            for (int j = 0; j < 16; j++) {
                union { float4 f; u64 u[2]; } Bu, Cu;
                Bu.f = B4[j]; Cu.f = C4[j];
                u64 t0 = mul2(coef2, Bu.u[0]);
                fma2acc(t0, s2[2 * j], dA2);
                s2[2 * j] = t0;
                u64 t1 = mul2(coef2, Bu.u[1]);
                fma2acc(t1, s2[2 * j + 1], dA2);
                s2[2 * j + 1] = t1;
                fma2acc(yacc[j & 3], t0, Cu.u[0]);
                fma2acc(yacc[j & 3], t1, Cu.u[1]);
            }
            float yv = sum2(add2(add2(yacc[0], yacc[1]), add2(yacc[2], yacc[3])));
            ybase[(size_t)(tile * TS + t) * DI] = yv + Dv * xv;
            if (tid == h * 32) cumh[tile * TS + t] = cd;
        }
        __syncthreads();
    }

    float* Sp = S + ((((size_t)dir * 16 + b) * 8 + h) * NC + c) * 2048 + p * 64;
    #pragma unroll
    for (int j = 0; j < 16; j++) {
        union { float4 f; u64 u[2]; } su;
        su.u[0] = s2[2 * j]; su.u[1] = s2[2 * j + 1];
        reinterpret_cast<float4*>(Sp)[j] = su.f;
    }
}

__global__ __launch_bounds__(256) void scan2_k(float* __restrict__ S, const float* __restrict__ cum)
{
    int bid = blockIdx.x;
    int h = bid & 7, b = (bid >> 3) & 15, dir = bid >> 7;
    float* Sb = S + (((size_t)dir * 16 + b) * 8 + h) * NC * 2048 + threadIdx.x * 8;
    const float* cumh = cum + (((size_t)dir * 16 + b) * 8 + h) * L_;
    float s[8];
    #pragma unroll
    for (int j = 0; j < 8; j++) s[j] = 0.f;
    for (int c = 0; c < NC; c++) {
        float* Sp = Sb + (size_t)c * 2048;
        float4 a0 = *reinterpret_cast<const float4*>(Sp);
        float4 a1 = *reinterpret_cast<const float4*>(Sp + 4);
        float Tc = cumh[(c + 1) * QC - 1];
        *reinterpret_cast<float4*>(Sp)     = make_float4(s[0], s[1], s[2], s[3]);
        *reinterpret_cast<float4*>(Sp + 4) = make_float4(s[4], s[5], s[6], s[7]);
        s[0] = fmaf(s[0], Tc, a0.x); s[1] = fmaf(s[1], Tc, a0.y);
        s[2] = fmaf(s[2], Tc, a0.z); s[3] = fmaf(s[3], Tc, a0.w);
        s[4] = fmaf(s[4], Tc, a1.x); s[5] = fmaf(s[5], Tc, a1.y);
        s[6] = fmaf(s[6], Tc, a1.z); s[7] = fmaf(s[7], Tc, a1.w);
    }
}

// scan3: y_t += cum_t * (C_t . s0_chunk) using the compact C buffer.
__global__ __launch_bounds__(256, 2) void scan3_k(
    float* __restrict__ y0, float* __restrict__ y1,
    const float* __restrict__ S, const float* __restrict__ cum,
    const float* __restrict__ Cc)
{
    __shared__ float sc[2][TS3][64];

    int bid = blockIdx.x;
    int c    = bid % (NC - 1) + 1;
    int rest = bid / (NC - 1);
    int b = rest & 15, dir = rest >> 4;

    float* yo = dir ? y1 : y0;

    int h = threadIdx.x >> 5;
    int p = threadIdx.x & 31;

    const float* Sp = S + ((((size_t)dir * 16 + b) * 8 + h) * NC + c) * 2048 + p * 64;
    u64 s02[32];
    #pragma unroll
    for (int j = 0; j < 16; j++) {
        union { float4 f; u64 u[2]; } su;
        su.f = reinterpret_cast<const float4*>(Sp)[j];
        s02[2 * j] = su.u[0]; s02[2 * j + 1] = su.u[1];
    }

    const float* cbase = Cc + ((size_t)dir * BL + (size_t)b * L_ + (size_t)c * QC) * 64;
    const float* cumh  = cum + (((size_t)dir * 16 + b) * 8 + h) * L_ + (size_t)c * QC;
    float* ybase = yo + ((size_t)b * L_ + (size_t)c * QC) * DI + h * HD + p;

    auto load_tile = [&](int buf, int tile) {
        int row = threadIdx.x >> 4, f4 = threadIdx.x & 15;
        reinterpret_cast<float4*>(&sc[buf][row][0])[f4] =
            *reinterpret_cast<const float4*>(cbase + (size_t)(tile * TS3 + row) * 64 + f4 * 4);
    };

    load_tile(0, 0);
    __syncthreads();

    for (int tile = 0; tile < NT3; tile++) {
        int cur = tile & 1;
        if (tile + 1 < NT3) load_tile(cur ^ 1, tile + 1);
        #pragma unroll
        for (int t = 0; t < TS3; t++) {
            u64 yacc[4] = {0ull, 0ull, 0ull, 0ull};
            const float4* C4 = reinterpret_cast<const float4*>(&sc[cur][t][0]);
            #pragma unroll
            for (int j = 0; j < 16; j++) {
                union { float4 f; u64 u[2]; } Cu;
                Cu.f = C4[j];
                fma2acc(yacc[j & 3], s02[2 * j], Cu.u[0]);
                fma2acc(yacc[j & 3], s02[2 * j + 1], Cu.u[1]);
            }
            float dot = sum2(add2(add2(yacc[0], yacc[1]), add2(yacc[2], yacc[3])));
            int l = tile * TS3 + t;
            float cd = __ldg(cumh + l);
            ybase[(size_t)l * DI] += cd * dot;
        }
        __syncthreads();
    }
}

// ---------------- y <- rmsnorm(y * silu(z)) * norm_w (rounded, in place) ---
__global__ void rmsy_k(float* __restrict__ y, const float* __restrict__ zx,
                       const float* __restrict__ nw)
{
    int warp = threadIdx.x >> 5, lane = threadIdx.x & 31;
    size_t row = (size_t)blockIdx.x * 8 + warp;
    float* yr = y + row * DI;
    const float* zr = zx + row * DPRJ;
    float4 y0v = *reinterpret_cast<const float4*>(yr + lane * 8);
    float4 y1v = *reinterpret_cast<const float4*>(yr + lane * 8 + 4);
    float4 z0v = *reinterpret_cast<const float4*>(zr + lane * 8);
    float4 z1v = *reinterpret_cast<const float4*>(zr + lane * 8 + 4);
    float v[8];
    v[0] = y0v.x * (z0v.x * sigm(z0v.x));
    v[1] = y0v.y * (z0v.y * sigm(z0v.y));
    v[2] = y0v.z * (z0v.z * sigm(z0v.z));
    v[3] = y0v.w * (z0v.w * sigm(z0v.w));
    v[4] = y1v.x * (z1v.x * sigm(z1v.x));
    v[5] = y1v.y * (z1v.y * sigm(z1v.y));
    v[6] = y1v.z * (z1v.z * sigm(z1v.z));
    v[7] = y1v.w * (z1v.w * sigm(z1v.w));
    float ss = 0.f;
    #pragma unroll
    for (int j = 0; j < 8; j++) ss = fmaf(v[j], v[j], ss);
    #pragma unroll
    for (int o = 16; o; o >>= 1) ss += __shfl_xor_sync(0xffffffffu, ss, o);
    float r = rsqrtf(ss * (1.f / 256.f) + 1e-5f);
    float4 w0 = *reinterpret_cast<const float4*>(nw + lane * 8);
    float4 w1 = *reinterpret_cast<const float4*>(nw + lane * 8 + 4);
    float4 o0, o1;
    o0.x = tf32f(v[0] * r * w0.x); o0.y = tf32f(v[1] * r * w0.y);
    o0.z = tf32f(v[2] * r * w0.z); o0.w = tf32f(v[3] * r * w0.w);
    o1.x = tf32f(v[4] * r * w1.x); o1.y = tf32f(v[5] * r * w1.y);
    o1.z = tf32f(v[6] * r * w1.z); o1.w = tf32f(v[7] * r * w1.w);
    *reinterpret_cast<float4*>(yr + lane * 8)     = o0;
    *reinterpret_cast<float4*>(yr + lane * 8 + 4) = o1;
}

// ---------------- e = tf32round((yf + reverse(yb)) * gate) -----------------
__global__ void combine_k(const float* __restrict__ yf, const float* __restrict__ yb,
                          const float* __restrict__ gate, float* __restrict__ e)
{
    size_t i = (size_t)blockIdx.x * blockDim.x + threadIdx.x;
    if (i >= (size_t)BL * 32) return;
    size_t row = i >> 5; int c4 = (int)(i & 31);
    size_t b = row >> 13; int l = (int)(row & (L_ - 1));
    size_t rowb = (b << 13) + (size_t)(L_ - 1 - l);
    float4 a  = reinterpret_cast<const float4*>(yf)[row * 32 + c4];
    float4 bb = reinterpret_cast<const float4*>(yb)[rowb * 32 + c4];
    float4 g  = reinterpret_cast<const float4*>(gate)[row * 32 + c4];
    float4 o;
    o.x = tf32f((a.x + bb.x) * g.x); o.y = tf32f((a.y + bb.y) * g.y);
    o.z = tf32f((a.z + bb.z) * g.z); o.w = tf32f((a.w + bb.w) * g.w);
    reinterpret_cast<float4*>(e)[row * 32 + c4] = o;
}

// ---------------- launch ----------------------------------------------------
extern "C" void kernel_launch(void* const* d_in, const int* in_sizes, int n_in,
                              void* d_out, int out_size)
{
    const float* x       = (const float*)d_in[0];
    const float* gate_w  = (const float*)d_in[1];
    const float* gate_b  = (const float*)d_in[2];
    const float* fconv_w = (const float*)d_in[3];
    const float* fconv_b = (const float*)d_in[4];
    const float* flin_w  = (const float*)d_in[5];
    const float* flin_b  = (const float*)d_in[6];
    const float* f_in_w  = (const float*)d_in[7];
    const float* f_cw    = (const float*)d_in[8];
    const float* f_cb    = (const float*)d_in[9];
    const float* f_dtb   = (const float*)d_in[10];
    const float* f_Alog  = (const float*)d_in[11];
    const float* f_D     = (const float*)d_in[12];
    const float* f_nw    = (const float*)d_in[13];
    const float* f_ow    = (const float*)d_in[14];
    const float* bconv_w = (const float*)d_in[15];
    const float* bconv_b = (const float*)d_in[16];
    const float* blin_w  = (const float*)d_in[17];
    const float* blin_b  = (const float*)d_in[18];
    const float* b_in_w  = (const float*)d_in[19];
    const float* b_cw    = (const float*)d_in[20];
    const float* b_cb    = (const float*)d_in[21];
    const float* b_dtb   = (const float*)d_in[22];
    const float* b_Alog  = (const float*)d_in[23];
    const float* b_D     = (const float*)d_in[24];
    const float* b_nw    = (const float*)d_in[25];
    const float* b_ow    = (const float*)d_in[26];
    const float* out_w   = (const float*)d_in[27];
    const float* out_b   = (const float*)d_in[28];
    const float* norm_w  = (const float*)d_in[29];

    float *p_gate, *p_u, *p_zx, *p_y, *p_ydir, *p_Wf, *p_bf, *p_S, *p_cum, *p_C, *p_xt, *p_Wt;
    cudaGetSymbolAddress((void**)&p_gate, g_gate);
    cudaGetSymbolAddress((void**)&p_u,    g_u);
    cudaGetSymbolAddress((void**)&p_zx,   g_zx);
    cudaGetSymbolAddress((void**)&p_y,    g_y);
    cudaGetSymbolAddress((void**)&p_ydir, g_ydir);
    cudaGetSymbolAddress((void**)&p_Wf,   g_Wf);
    cudaGetSymbolAddress((void**)&p_bf,   g_bf);
    cudaGetSymbolAddress((void**)&p_S,    g_S);
    cudaGetSymbolAddress((void**)&p_cum,  g_cum);
    cudaGetSymbolAddress((void**)&p_C,    g_C);
    cudaGetSymbolAddress((void**)&p_xt,   g_xt);
    cudaGetSymbolAddress((void**)&p_Wt,   g_Wt);

    float* u0   = p_u;                 float* u1   = p_u   + (size_t)BL * DM;
    float* zx0  = p_zx;                float* zx1  = p_zx  + (size_t)BL * DPRJ;
    float* y0   = p_y;                 float* y1   = p_y   + (size_t)BL * DI;
    float* yd0  = p_ydir;              float* yd1  = p_ydir + (size_t)BL * DM;
    float* Wf0  = p_Wf;                float* Wf1  = p_Wf  + DM * 3 * DM;
    float* bf0  = p_bf;                float* bf1  = p_bf  + DM;

    float* Wt_gate = p_Wt;
    float* Wt_fin  = Wt_gate + 128 * 128;
    float* Wt_bin  = Wt_fin  + 648 * 128;
    float* Wt_fow  = Wt_bin  + 648 * 128;
    float* Wt_bow  = Wt_fow  + 128 * 256;
    float* Wt_out  = Wt_bow  + 128 * 256;

    const int MT = BL / 128;

    cudaFuncSetAttribute(gemm_k, cudaFuncAttributeMaxDynamicSharedMemorySize, SMEM_GEMM);
    cudaFuncSetAttribute(scan1_k, cudaFuncAttributeMaxDynamicSharedMemorySize, SMEM_SCAN1);

    round_k<<<(BL * DM / 4 + 255) / 256, 256>>>(x, p_xt, (size_t)BL * DM);
    round_k<<<(128 * 128 / 4 + 255) / 256, 256>>>(gate_w, Wt_gate, 128 * 128);
    round_k<<<(648 * 128 / 4 + 255) / 256, 256>>>(f_in_w, Wt_fin, 648 * 128);
    round_k<<<(648 * 128 / 4 + 255) / 256, 256>>>(b_in_w, Wt_bin, 648 * 128);
    round_k<<<(128 * 256 / 4 + 255) / 256, 256>>>(f_ow, Wt_fow, 128 * 256);
    round_k<<<(128 * 256 / 4 + 255) / 256, 256>>>(b_ow, Wt_bow, 128 * 256);
    round_k<<<(128 * 128 / 4 + 255) / 256, 256>>>(out_w, Wt_out, 128 * 128);

    prep_w_k<<<384, 256>>>(flin_w, fconv_w, blin_w, bconv_w, Wf0, Wf1);
    prep_b_k<<<1, 256>>>(flin_b, fconv_b, blin_b, bconv_b, flin_w, blin_w, bf0, bf1);

    gemm_k<<<dim3(MT, 1), 256, SMEM_GEMM>>>(p_xt, Wt_gate, gate_b, p_gate, 128, 128, 0, 1, 0, nullptr, nullptr);

    gemm_k<<<dim3(MT, 1), 256, SMEM_GEMM>>>(p_xt, Wf0, bf0, u0, 128, 384, 1, 0, 1, nullptr, nullptr);
    gemm_k<<<dim3(MT, 1), 256, SMEM_GEMM>>>(p_xt, Wf1, bf1, u1, 128, 384, 2, 0, 1, nullptr, nullptr);

    gemm_k<<<dim3(MT, 6), 256, SMEM_GEMM>>>(u0, Wt_fin, nullptr, zx0, 648, 128, 0, 0, 0, nullptr, nullptr);
    gemm_k<<<dim3(MT, 6), 256, SMEM_GEMM>>>(u1, Wt_bin, nullptr, zx1, 648, 128, 0, 0, 0, nullptr, nullptr);

    // fused conv + local scan
    scan1_k<<<2 * 16 * NC, 256, SMEM_SCAN1>>>(
        zx0, zx1, f_cw, f_cb, f_dtb, b_cw, b_cb, b_dtb,
        f_Alog, f_D, b_Alog, b_D, y0, y1, p_S, p_cum, p_C);
    scan2_k<<<256, 256>>>(p_S, p_cum);
    scan3_k<<<2 * 16 * (NC - 1), 256>>>(y0, y1, p_S, p_cum, p_C);

    rmsy_k<<<BL / 8, 256>>>(y0, zx0, f_nw);
    rmsy_k<<<BL / 8, 256>>>(y1, zx1, b_nw);

    gemm_k<<<dim3(MT, 1), 256, SMEM_GEMM>>>(y0, Wt_fow, nullptr, yd0, 128, 256, 0, 0, 0, nullptr, nullptr);
    gemm_k<<<dim3(MT, 1), 256, SMEM_GEMM>>>(y1, Wt_bow, nullptr, yd1, 128, 256, 0, 0, 0, nullptr, nullptr);

    combine_k<<<(BL * 32) / 256, 256>>>(yd0, yd1, p_gate, u0);

    // fused final: out = x + rmsnorm(u0 @ out_w.T + out_b) * norm_w
    gemm_k<<<dim3(MT, 1), 256, SMEM_GEMM>>>(u0, Wt_out, out_b, (float*)d_out, 128, 128, 0, 0, 0, x, norm_w);
}